// round 2
// baseline (speedup 1.0000x reference)
#include <cuda_runtime.h>
#include <math.h>

#define BB 2
#define LL 1024
#define HH 8
#define DD 64
#define DMM 768
#define HD (HH*DD)   // 512

// ---------------- scratch (static device globals; no allocs) ----------------
__device__ float g_q [BB*LL*HD];
__device__ float g_k [BB*LL*HD];
__device__ float g_v [BB*LL*HD];
__device__ float g_Su[BB*HH*LL*33];
__device__ float g_Ss[BB*HH*LL*33];
__device__ float g_uk[BB*HH*LL];
__device__ float g_vr[HH*(2*LL-1)];
__device__ int   g_tmin[LL];
__device__ float g_ao[BB*LL*HD];

// ---------------- prep: tmin LUT + vr table -------------------------------
__global__ void prep_kernel(const float* __restrict__ v_bias,
                            const float* __restrict__ w_pos) {
    __shared__ double cw[32];
    __shared__ float  vws[512];
    __shared__ float  Vu[8][33];
    __shared__ float  Vsg[8][33];
    int tid = threadIdx.x;
    if (tid < 32)
        cw[tid] = exp((double)(tid + 1) * log((double)(LL + 1) / 2.0) / 32.0);
    __syncthreads();
    // tmin[a] = smallest t with a <= cw[t], else 32
    for (int a = tid; a < LL; a += 256) {
        int t = 32;
        for (int j = 31; j >= 0; j--) if ((double)a <= cw[j]) t = j;
        g_tmin[a] = t;
    }
    // vw[h,n] = sum_d v_bias[h,d] * w_pos[h,d,n]
    for (int o = tid; o < 512; o += 256) {
        int h = o >> 6, n = o & 63;
        float s = 0.f;
        for (int d = 0; d < 64; d++)
            s += v_bias[h*64 + d] * w_pos[h*4096 + d*64 + n];
        vws[o] = s;
    }
    __syncthreads();
    // suffix sums over the 32 thresholds
    if (tid < 16) {
        int h = tid >> 1, sg = tid & 1;
        float run = 0.f;
        float* dst = sg ? Vsg[h] : Vu[h];
        dst[32] = 0.f;
        for (int t = 31; t >= 0; t--) { run += vws[h*64 + sg*32 + t]; dst[t] = run; }
    }
    __syncthreads();
    // vr table over (h, d) with d = j - i in [-(L-1), L-1]
    for (int idx = tid; idx < HH*(2*LL-1); idx += 256) {
        int h  = idx / (2*LL-1);
        int dd = idx % (2*LL-1);
        int d  = dd - (LL-1);
        int a  = d < 0 ? -d : d;
        int t  = g_tmin[a];
        float sg = d > 0 ? 1.f : (d < 0 ? -1.f : 0.f);
        g_vr[idx] = Vu[h][t] + sg * Vsg[h][t];
    }
}

// ---------------- SGEMM: C[M,N] = A[M,K] @ W[N,K]^T (+bias[N]) -------------
template<bool HAS_BIAS>
__global__ __launch_bounds__(256)
void sgemm_kernel(const float* __restrict__ A, const float* __restrict__ W,
                  const float* __restrict__ bias, float* __restrict__ C,
                  int M, int N, int K) {
    __shared__ float As[16][68];
    __shared__ float Bs[16][68];
    int tid = threadIdx.x;
    int tx = tid & 15, ty = tid >> 4;
    int m0 = blockIdx.x * 64, n0 = blockIdx.y * 64;
    float acc[4][4] = {};
    int lm = tid >> 2, lq = (tid & 3) << 2;
    const float* Ap = A + (size_t)(m0 + lm) * K + lq;
    const float* Wp = W + (size_t)(n0 + lm) * K + lq;
    for (int k0 = 0; k0 < K; k0 += 16) {
        float4 av = *(const float4*)(Ap + k0);
        float4 wv = *(const float4*)(Wp + k0);
        As[lq+0][lm] = av.x; As[lq+1][lm] = av.y; As[lq+2][lm] = av.z; As[lq+3][lm] = av.w;
        Bs[lq+0][lm] = wv.x; Bs[lq+1][lm] = wv.y; Bs[lq+2][lm] = wv.z; Bs[lq+3][lm] = wv.w;
        __syncthreads();
        #pragma unroll
        for (int kk = 0; kk < 16; kk++) {
            float4 a = *(const float4*)&As[kk][ty << 2];
            float4 b = *(const float4*)&Bs[kk][tx << 2];
            float ar[4] = {a.x, a.y, a.z, a.w};
            float br[4] = {b.x, b.y, b.z, b.w};
            #pragma unroll
            for (int i = 0; i < 4; i++)
                #pragma unroll
                for (int j = 0; j < 4; j++)
                    acc[i][j] += ar[i] * br[j];
        }
        __syncthreads();
    }
    float bv[4] = {0.f, 0.f, 0.f, 0.f};
    if (HAS_BIAS) {
        #pragma unroll
        for (int j = 0; j < 4; j++) bv[j] = bias[n0 + (tx << 2) + j];
    }
    #pragma unroll
    for (int i = 0; i < 4; i++) {
        int m = m0 + (ty << 2) + i;
        float4 o = make_float4(acc[i][0] + bv[0], acc[i][1] + bv[1],
                               acc[i][2] + bv[2], acc[i][3] + bv[3]);
        *(float4*)(C + (size_t)m * N + n0 + (tx << 2)) = o;
    }
}

// -------- bias prep: qw suffix sums (Su/Ss) + uk, one block per (b,i) ------
__global__ __launch_bounds__(256)
void bias_prep_kernel(const float* __restrict__ w_pos,
                      const float* __restrict__ u_bias) {
    int row = blockIdx.x;            // b*L + i
    int tid = threadIdx.x;
    __shared__ float qs[512], ks[512], qws[512];
    qs[tid]       = g_q[(size_t)row * HD + tid];
    qs[tid + 256] = g_q[(size_t)row * HD + tid + 256];
    ks[tid]       = g_k[(size_t)row * HD + tid];
    ks[tid + 256] = g_k[(size_t)row * HD + tid + 256];
    __syncthreads();
    // qw[h,n] = sum_d q[h,d] * w_pos[h,d,n]
    for (int o = tid; o < 512; o += 256) {
        int h = o >> 6, n = o & 63;
        const float* wp = w_pos + h*4096 + n;
        float s = 0.f;
        #pragma unroll 8
        for (int d = 0; d < 64; d++) s += qs[h*64 + d] * wp[d << 6];
        qws[o] = s;
    }
    // uk[b,h,i] = u_bias[h,:] . k[b,i,h,:]   (one warp per head)
    {
        int wid = tid >> 5, lane = tid & 31;
        float us = ks[wid*64 + lane]      * u_bias[wid*64 + lane]
                 + ks[wid*64 + 32 + lane] * u_bias[wid*64 + 32 + lane];
        #pragma unroll
        for (int off = 16; off; off >>= 1) us += __shfl_xor_sync(0xffffffffu, us, off);
        if (lane == 0) {
            int b = row >> 10, i = row & 1023;
            g_uk[(b*HH + wid) * LL + i] = us;
        }
    }
    __syncthreads();
    if (tid < 16) {
        int h = tid >> 1, sg = tid & 1;
        int b = row >> 10, i = row & 1023;
        float* dst = (sg ? g_Ss : g_Su) + (size_t)((b*HH + h) * LL + i) * 33;
        float run = 0.f;
        dst[32] = 0.f;
        for (int t = 31; t >= 0; t--) { run += qws[h*64 + sg*32 + t]; dst[t] = run; }
    }
}

// ---------------- flash attention with O(1) relative bias ------------------
// grid (32 i-tiles, 8 heads, 2 batches); 256 threads; 32 rows/block; octet=8 thr/row
__global__ __launch_bounds__(256)
void attn_kernel() {
    extern __shared__ float sm[];
    float* Qs  = sm;                  // [32][65]
    float* Kst = Qs  + 32*65;         // [64][64], XOR block swizzle
    float* Vsm = Kst + 64*64;         // [64][64]
    float* Ps  = Vsm + 64*64;         // [32][68]
    float* Sus = Ps  + 32*68;         // [32][33]
    float* Sss = Sus + 32*33;         // [32][33]
    float* uks = Sss + 32*33;         // [64]

    int b = blockIdx.z, h = blockIdx.y;
    int i0 = blockIdx.x * 32;
    int tid = threadIdx.x;
    int r = tid >> 3, oc = tid & 7;

    for (int x = tid; x < 32*64; x += 256) {
        int rr = x >> 6, d = x & 63;
        Qs[rr*65 + d] = g_q[(size_t)(b*LL + i0 + rr) * HD + h*64 + d];
    }
    for (int x = tid; x < 32*33; x += 256) {
        int rr = x / 33, t = x % 33;
        size_t base = (size_t)((b*HH + h) * LL + i0 + rr) * 33 + t;
        Sus[x] = g_Su[base];
        Sss[x] = g_Ss[base];
    }

    float m = -INFINITY, ell = 0.f;
    float o[8];
    #pragma unroll
    for (int u = 0; u < 8; u++) o[u] = 0.f;

    int i = i0 + r;
    const float* vr_h = g_vr + h * (2*LL - 1) + (LL - 1);

    for (int j0 = 0; j0 < LL; j0 += 64) {
        // load K (transposed + swizzled) and V
        for (int x = tid; x < 64*16; x += 256) {
            int jj = x >> 4, c4 = x & 15;
            size_t gidx = (size_t)(b*LL + j0 + jj) * HD + h*64 + (c4 << 2);
            float4 kv = *(const float4*)(g_k + gidx);
            int col = ((((jj >> 3) ^ (c4 & 7)) << 3) | (jj & 7));   // f(kk)=(kk>>2)&7 = c4&7
            Kst[(c4*4 + 0)*64 + col] = kv.x;
            Kst[(c4*4 + 1)*64 + col] = kv.y;
            Kst[(c4*4 + 2)*64 + col] = kv.z;
            Kst[(c4*4 + 3)*64 + col] = kv.w;
            *(float4*)&Vsm[jj*64 + (c4 << 2)] = *(const float4*)(g_v + gidx);
        }
        if (tid < 64) uks[tid] = g_uk[(b*HH + h) * LL + j0 + tid];
        __syncthreads();

        // scores: each thread does 8 consecutive j
        float s[8];
        #pragma unroll
        for (int u = 0; u < 8; u++) s[u] = 0.f;
        #pragma unroll 4
        for (int kk = 0; kk < 64; kk++) {
            float qv = Qs[r*65 + kk];
            int fk = (kk >> 2) & 7;
            const float* kp = &Kst[kk*64 + ((oc ^ fk) << 3)];
            float4 ka = *(const float4*)kp;
            float4 kb = *(const float4*)(kp + 4);
            s[0] += qv*ka.x; s[1] += qv*ka.y; s[2] += qv*ka.z; s[3] += qv*ka.w;
            s[4] += qv*kb.x; s[5] += qv*kb.y; s[6] += qv*kb.z; s[7] += qv*kb.w;
        }
        // add relative-position bias (O(1) per element)
        int jb = j0 + oc*8;
        #pragma unroll
        for (int u = 0; u < 8; u++) {
            int j = jb + u;
            int d = j - i;
            int a = d < 0 ? -d : d;
            int t = g_tmin[a];
            float sg = d > 0 ? 1.f : (d < 0 ? -1.f : 0.f);
            s[u] = (s[u] + Sus[r*33 + t] + sg * Sss[r*33 + t] + uks[oc*8 + u] + vr_h[d]) * 0.125f;
        }
        // online softmax across the octet
        float mt = s[0];
        #pragma unroll
        for (int u = 1; u < 8; u++) mt = fmaxf(mt, s[u]);
        #pragma unroll
        for (int off = 4; off; off >>= 1) mt = fmaxf(mt, __shfl_xor_sync(0xffffffffu, mt, off));
        float mn = fmaxf(m, mt);
        float alpha = __expf(m - mn);
        float ps = 0.f;
        #pragma unroll
        for (int u = 0; u < 8; u++) { s[u] = __expf(s[u] - mn); ps += s[u]; }
        #pragma unroll
        for (int off = 4; off; off >>= 1) ps += __shfl_xor_sync(0xffffffffu, ps, off);
        ell = ell * alpha + ps;
        m = mn;
        #pragma unroll
        for (int u = 0; u < 8; u++) o[u] *= alpha;

        *(float4*)&Ps[r*68 + oc*8]     = make_float4(s[0], s[1], s[2], s[3]);
        *(float4*)&Ps[r*68 + oc*8 + 4] = make_float4(s[4], s[5], s[6], s[7]);
        __syncthreads();

        // PV: thread owns dv slice [oc*8, oc*8+8)
        #pragma unroll 4
        for (int j = 0; j < 64; j++) {
            float p = Ps[r*68 + j];
            const float* vp = &Vsm[j*64 + oc*8];
            float4 va = *(const float4*)vp;
            float4 vb = *(const float4*)(vp + 4);
            o[0] += p*va.x; o[1] += p*va.y; o[2] += p*va.z; o[3] += p*va.w;
            o[4] += p*vb.x; o[5] += p*vb.y; o[6] += p*vb.z; o[7] += p*vb.w;
        }
        __syncthreads();
    }

    float inv = 1.f / ell;
    float* dst = g_ao + (size_t)(b*LL + i) * HD + h*64 + oc*8;
    *(float4*)dst       = make_float4(o[0]*inv, o[1]*inv, o[2]*inv, o[3]*inv);
    *(float4*)(dst + 4) = make_float4(o[4]*inv, o[5]*inv, o[6]*inv, o[7]*inv);
}

// ---------------------------------------------------------------------------
extern "C" void kernel_launch(void* const* d_in, const int* in_sizes, int n_in,
                              void* d_out, int out_size) {
    const float* x  = (const float*)d_in[0];
    const float* Wq = (const float*)d_in[1];
    const float* Wk = (const float*)d_in[2];
    const float* Wv = (const float*)d_in[3];
    const float* Wo = (const float*)d_in[4];
    const float* bo = (const float*)d_in[5];
    const float* ub = (const float*)d_in[6];
    const float* vb = (const float*)d_in[7];
    const float* wp = (const float*)d_in[8];
    float* out = (float*)d_out;

    float *pq, *pk, *pv, *pao;
    cudaGetSymbolAddress((void**)&pq,  g_q);
    cudaGetSymbolAddress((void**)&pk,  g_k);
    cudaGetSymbolAddress((void**)&pv,  g_v);
    cudaGetSymbolAddress((void**)&pao, g_ao);

    prep_kernel<<<1, 256>>>(vb, wp);

    dim3 gqkv(BB*LL/64, HD/64);
    sgemm_kernel<false><<<gqkv, 256>>>(x, Wq, nullptr, pq, BB*LL, HD, DMM);
    sgemm_kernel<false><<<gqkv, 256>>>(x, Wk, nullptr, pk, BB*LL, HD, DMM);
    sgemm_kernel<false><<<gqkv, 256>>>(x, Wv, nullptr, pv, BB*LL, HD, DMM);

    bias_prep_kernel<<<BB*LL, 256>>>(wp, ub);

    const int ATTN_SMEM = (32*65 + 64*64 + 64*64 + 32*68 + 32*33*2 + 64) * 4;
    cudaFuncSetAttribute(attn_kernel, cudaFuncAttributeMaxDynamicSharedMemorySize, ATTN_SMEM);
    attn_kernel<<<dim3(LL/32, HH, BB), 256, ATTN_SMEM>>>();

    dim3 go(BB*LL/64, DMM/64);
    sgemm_kernel<true><<<go, 256>>>(pao, Wo, bo, out, BB*LL, DMM, HD);
}

// round 4
// speedup vs baseline: 2.2891x; 2.2891x over previous
#include <cuda_runtime.h>
#include <math.h>

#define BB 2
#define LL 1024
#define HH 8
#define DD 64
#define DMM 768
#define HD 512

// ---------------- scratch (static device globals; no allocs) ----------------
__device__ float g_q [BB*LL*HD];
__device__ float g_k [BB*LL*HD];
__device__ float g_v [BB*LL*HD];
__device__ float g_Su[BB*HH*LL*33];
__device__ float g_Ss[BB*HH*LL*33];
__device__ float g_uk[BB*HH*LL];
__device__ float g_Vu[HH*33];
__device__ float g_Vsg[HH*33];
__device__ int   g_tmin[LL];
__device__ float g_ao[BB*LL*HD];

// 8-float-granular XOR swizzle for k-major [64][128] tiles
#define SWC(kk,c) (((((c) >> 3) ^ ((kk) & 15)) << 3) | ((c) & 7))
// 4-float-granular XOR swizzle for k-major [16][64] tiles
#define SWB(kk,c) (((((c) >> 2) ^ ((kk) & 15)) << 2) | ((c) & 3))

// ---------------- prep: tmin LUT + per-head Vu/Vsg suffix tables -----------
__global__ void prep_kernel(const float* __restrict__ v_bias,
                            const float* __restrict__ w_pos) {
    __shared__ double cw[32];
    __shared__ float  vws[512];
    int tid = threadIdx.x;
    if (tid < 32)
        cw[tid] = exp((double)(tid + 1) * log((double)(LL + 1) / 2.0) / 32.0);
    __syncthreads();
    for (int a = tid; a < LL; a += 256) {
        int t = 32;
        for (int j = 31; j >= 0; j--) if ((double)a <= cw[j]) t = j;
        g_tmin[a] = t;
    }
    // vw[h,n] = sum_d v_bias[h,d] * w_pos[h,d,n]
    for (int o = tid; o < 512; o += 256) {
        int h = o >> 6, n = o & 63;
        float s = 0.f;
        for (int d = 0; d < 64; d++)
            s += v_bias[h*64 + d] * w_pos[h*4096 + d*64 + n];
        vws[o] = s;
    }
    __syncthreads();
    // suffix sums over the 32 thresholds -> per-head tables
    if (tid < 16) {
        int h = tid >> 1, sg = tid & 1;
        float run = 0.f;
        float* dst = (sg ? g_Vsg : g_Vu) + h*33;
        dst[32] = 0.f;
        for (int t = 31; t >= 0; t--) { run += vws[h*64 + sg*32 + t]; dst[t] = run; }
    }
}

// ---------------- GEMM body: C[128,64] tile = A[M,K] @ W[N,K]^T ------------
__device__ __forceinline__ void gemm_body(
    const float* __restrict__ A, const float* __restrict__ W,
    const float* __restrict__ bias, float* __restrict__ C,
    int K, int N, int m0, int n0, float* As, float* Bs)
{
    const int tid = threadIdx.x;
    const int ty = tid >> 4, tx = tid & 15;
    const int lr = tid >> 2, lc = (tid & 3) << 2;

    float acc[8][4];
    #pragma unroll
    for (int u = 0; u < 8; u++) {
        acc[u][0] = 0.f; acc[u][1] = 0.f; acc[u][2] = 0.f; acc[u][3] = 0.f;
    }

    const float* Ap0 = A + (size_t)(m0 + lr) * K + lc;
    const float* Ap1 = A + (size_t)(m0 + lr + 64) * K + lc;
    const float* Wp  = W + (size_t)(n0 + lr) * K + lc;

    float4 a0 = *(const float4*)Ap0;
    float4 a1 = *(const float4*)Ap1;
    float4 b0 = *(const float4*)Wp;

    for (int k0 = 0; k0 < K; k0 += 16) {
        {
            int kk = lc;
            As[(kk+0)*128 + SWC(kk+0, lr)]      = a0.x;
            As[(kk+1)*128 + SWC(kk+1, lr)]      = a0.y;
            As[(kk+2)*128 + SWC(kk+2, lr)]      = a0.z;
            As[(kk+3)*128 + SWC(kk+3, lr)]      = a0.w;
            As[(kk+0)*128 + SWC(kk+0, lr + 64)] = a1.x;
            As[(kk+1)*128 + SWC(kk+1, lr + 64)] = a1.y;
            As[(kk+2)*128 + SWC(kk+2, lr + 64)] = a1.z;
            As[(kk+3)*128 + SWC(kk+3, lr + 64)] = a1.w;
            Bs[(kk+0)*64 + SWB(kk+0, lr)] = b0.x;
            Bs[(kk+1)*64 + SWB(kk+1, lr)] = b0.y;
            Bs[(kk+2)*64 + SWB(kk+2, lr)] = b0.z;
            Bs[(kk+3)*64 + SWB(kk+3, lr)] = b0.w;
        }
        __syncthreads();
        if (k0 + 16 < K) {
            a0 = *(const float4*)(Ap0 + k0 + 16);
            a1 = *(const float4*)(Ap1 + k0 + 16);
            b0 = *(const float4*)(Wp  + k0 + 16);
        }
        #pragma unroll
        for (int kk = 0; kk < 16; kk++) {
            const float4* ap = (const float4*)(As + kk*128 + ((ty ^ kk) << 3));
            float4 xa = ap[0], xb = ap[1];
            float4 bb = *(const float4*)(Bs + kk*64 + ((tx ^ kk) << 2));
            float xr[8] = {xa.x, xa.y, xa.z, xa.w, xb.x, xb.y, xb.z, xb.w};
            #pragma unroll
            for (int u = 0; u < 8; u++) {
                acc[u][0] += xr[u] * bb.x;
                acc[u][1] += xr[u] * bb.y;
                acc[u][2] += xr[u] * bb.z;
                acc[u][3] += xr[u] * bb.w;
            }
        }
        __syncthreads();
    }

    float4 bv = make_float4(0.f, 0.f, 0.f, 0.f);
    if (bias) bv = *(const float4*)(bias + n0 + (tx << 2));
    #pragma unroll
    for (int u = 0; u < 8; u++) {
        float4 r = make_float4(acc[u][0] + bv.x, acc[u][1] + bv.y,
                               acc[u][2] + bv.z, acc[u][3] + bv.w);
        *(float4*)(C + (size_t)(m0 + ty*8 + u) * N + n0 + (tx << 2)) = r;
    }
}

// Fused QKV: grid (16, 24); by: 0-7 -> Q, 8-15 -> K, 16-23 -> V
__global__ __launch_bounds__(256)
void qkv_kernel(const float* __restrict__ x, const float* __restrict__ Wq,
                const float* __restrict__ Wk, const float* __restrict__ Wv) {
    __shared__ float As[16*128];
    __shared__ float Bs[16*64];
    int sel = blockIdx.y >> 3, nb = blockIdx.y & 7;
    const float* W = sel == 0 ? Wq : (sel == 1 ? Wk : Wv);
    float* C = sel == 0 ? g_q : (sel == 1 ? g_k : g_v);
    gemm_body(x, W, nullptr, C, DMM, HD, blockIdx.x * 128, nb * 64, As, Bs);
}

__global__ __launch_bounds__(256)
void out_kernel(const float* __restrict__ Wo, const float* __restrict__ bo,
                float* __restrict__ out) {
    __shared__ float As[16*128];
    __shared__ float Bs[16*64];
    gemm_body(g_ao, Wo, bo, out, HD, DMM, blockIdx.x * 128, blockIdx.y * 64, As, Bs);
}

// -------- bias prep: qw suffix sums (Su/Ss) + uk, one block per (b,i) ------
__global__ __launch_bounds__(256)
void bias_prep_kernel(const float* __restrict__ w_pos,
                      const float* __restrict__ u_bias) {
    int row = blockIdx.x;            // b*L + i
    int tid = threadIdx.x;
    __shared__ float qs[512], ks[512], qws[512];
    qs[tid]       = g_q[(size_t)row * HD + tid];
    qs[tid + 256] = g_q[(size_t)row * HD + tid + 256];
    ks[tid]       = g_k[(size_t)row * HD + tid];
    ks[tid + 256] = g_k[(size_t)row * HD + tid + 256];
    __syncthreads();
    for (int o = tid; o < 512; o += 256) {
        int h = o >> 6, n = o & 63;
        const float* wp = w_pos + h*4096 + n;
        float s = 0.f;
        #pragma unroll 8
        for (int d = 0; d < 64; d++) s += qs[h*64 + d] * wp[d << 6];
        qws[o] = s;
    }
    {
        int wid = tid >> 5, lane = tid & 31;
        float us = ks[wid*64 + lane]      * u_bias[wid*64 + lane]
                 + ks[wid*64 + 32 + lane] * u_bias[wid*64 + 32 + lane];
        #pragma unroll
        for (int off = 16; off; off >>= 1) us += __shfl_xor_sync(0xffffffffu, us, off);
        if (lane == 0) {
            int b = row >> 10, i = row & 1023;
            g_uk[(b*HH + wid) * LL + i] = us;
        }
    }
    __syncthreads();
    if (tid < 16) {
        int h = tid >> 1, sg = tid & 1;
        int b = row >> 10, i = row & 1023;
        float* dst = (sg ? g_Ss : g_Su) + (size_t)((b*HH + h) * LL + i) * 33;
        float run = 0.f;
        dst[32] = 0.f;
        for (int t = 31; t >= 0; t--) { run += qws[h*64 + sg*32 + t]; dst[t] = run; }
    }
}

// ---------------- flash attention, 128x128 tile, 8x8 micro-tile ------------
__global__ __launch_bounds__(256, 1)
void attn_kernel() {
    extern __shared__ float sm[];
    float* Qst = sm;                    // [64][128] k-major, swizzled, pre-scaled
    float* Kst = Qst + 64*128;          // [64][128] k-major, swizzled
    float* Vs  = Kst + 64*128;          // [128][64] row-major
    float* Ps  = Vs  + 128*64;          // [128][128]
    float* Sus = Ps  + 128*128;         // [128][33] (Su + Vu[h]) * scale
    float* Sss = Sus + 128*33;          // [128][33]
    float* uks = Sss + 128*33;          // [128]
    int*   tms = (int*)(uks + 128);     // [1024]

    const int b = blockIdx.z, h = blockIdx.y;
    const int i0 = blockIdx.x * 128;
    const int tid = threadIdx.x;
    const int ty = tid >> 4, tx = tid & 15;

    {
        const float* qg = g_q + (size_t)(b*LL + i0) * HD + h*64;
        for (int x = tid; x < 128*16; x += 256) {
            int jj = x >> 4, c4 = x & 15;
            float4 qv = *(const float4*)(qg + (size_t)jj*HD + (c4 << 2));
            int k0 = c4 << 2;
            Qst[(k0+0)*128 + SWC(k0+0, jj)] = qv.x * 0.125f;
            Qst[(k0+1)*128 + SWC(k0+1, jj)] = qv.y * 0.125f;
            Qst[(k0+2)*128 + SWC(k0+2, jj)] = qv.z * 0.125f;
            Qst[(k0+3)*128 + SWC(k0+3, jj)] = qv.w * 0.125f;
        }
        const float* sub = g_Su + (size_t)((b*HH + h)*LL + i0) * 33;
        const float* ssb = g_Ss + (size_t)((b*HH + h)*LL + i0) * 33;
        const float* vu  = g_Vu  + h*33;
        const float* vsg = g_Vsg + h*33;
        for (int x = tid; x < 128*33; x += 256) {
            int t = x % 33;
            Sus[x] = (sub[x] + vu[t])  * 0.125f;
            Sss[x] = (ssb[x] + vsg[t]) * 0.125f;
        }
        for (int x = tid; x < LL; x += 256) tms[x] = g_tmin[x];
    }

    float m8[8], l8[8];
    float4 O4[8];
    #pragma unroll
    for (int u = 0; u < 8; u++) {
        m8[u] = -INFINITY; l8[u] = 0.f; O4[u] = make_float4(0.f, 0.f, 0.f, 0.f);
    }

    const int ibase = i0 + ty*8;

    for (int j0 = 0; j0 < LL; j0 += 128) {
        __syncthreads();   // previous PV done before overwriting Kst/Vs/uks
        const float* kg = g_k + (size_t)(b*LL + j0) * HD + h*64;
        const float* vg = g_v + (size_t)(b*LL + j0) * HD + h*64;
        for (int x = tid; x < 128*16; x += 256) {
            int jj = x >> 4, c4 = x & 15;
            float4 kv = *(const float4*)(kg + (size_t)jj*HD + (c4 << 2));
            int k0 = c4 << 2;
            Kst[(k0+0)*128 + SWC(k0+0, jj)] = kv.x;
            Kst[(k0+1)*128 + SWC(k0+1, jj)] = kv.y;
            Kst[(k0+2)*128 + SWC(k0+2, jj)] = kv.z;
            Kst[(k0+3)*128 + SWC(k0+3, jj)] = kv.w;
            *(float4*)(Vs + jj*64 + (c4 << 2)) =
                *(const float4*)(vg + (size_t)jj*HD + (c4 << 2));
        }
        if (tid < 128) uks[tid] = g_uk[(size_t)(b*HH + h)*LL + j0 + tid] * 0.125f;
        __syncthreads();

        // ---- scores: S[8][8] ----
        float S[8][8];
        #pragma unroll
        for (int u = 0; u < 8; u++)
            #pragma unroll
            for (int w = 0; w < 8; w++) S[u][w] = 0.f;

        #pragma unroll 4
        for (int kk = 0; kk < 64; kk++) {
            int f = kk & 15;
            const float4* qp = (const float4*)(Qst + kk*128 + ((ty ^ f) << 3));
            const float4* kp = (const float4*)(Kst + kk*128 + ((tx ^ f) << 3));
            float4 qa = qp[0], qb = qp[1];
            float4 ka = kp[0], kb = kp[1];
            float qr[8] = {qa.x, qa.y, qa.z, qa.w, qb.x, qb.y, qb.z, qb.w};
            float kr[8] = {ka.x, ka.y, ka.z, ka.w, kb.x, kb.y, kb.z, kb.w};
            #pragma unroll
            for (int u = 0; u < 8; u++)
                #pragma unroll
                for (int w = 0; w < 8; w++)
                    S[u][w] += qr[u] * kr[w];
        }

        // ---- bias + online softmax (per i-row u) ----
        float4 uka = *(const float4*)(uks + tx*8);
        float4 ukb = *(const float4*)(uks + tx*8 + 4);
        float ukr[8] = {uka.x, uka.y, uka.z, uka.w, ukb.x, ukb.y, ukb.z, ukb.w};
        const int jbase = j0 + tx*8;
        #pragma unroll
        for (int u = 0; u < 8; u++) {
            const int i = ibase + u;
            const float* suR = Sus + (ty*8 + u)*33;
            const float* ssR = Sss + (ty*8 + u)*33;
            #pragma unroll
            for (int w = 0; w < 8; w++) {
                int d = jbase + w - i;
                int a = d < 0 ? -d : d;
                int t = tms[a];
                float sg = (float)((d > 0) - (d < 0));
                S[u][w] += suR[t] + sg * ssR[t] + ukr[w];
            }
            float mt = S[u][0];
            #pragma unroll
            for (int w = 1; w < 8; w++) mt = fmaxf(mt, S[u][w]);
            #pragma unroll
            for (int off = 1; off <= 8; off <<= 1)
                mt = fmaxf(mt, __shfl_xor_sync(0xffffffffu, mt, off));
            float mn = fmaxf(m8[u], mt);
            float alpha = __expf(m8[u] - mn);
            float ps = 0.f;
            #pragma unroll
            for (int w = 0; w < 8; w++) { S[u][w] = __expf(S[u][w] - mn); ps += S[u][w]; }
            #pragma unroll
            for (int off = 1; off <= 8; off <<= 1)
                ps += __shfl_xor_sync(0xffffffffu, ps, off);
            l8[u] = l8[u] * alpha + ps;
            m8[u] = mn;
            O4[u].x *= alpha; O4[u].y *= alpha; O4[u].z *= alpha; O4[u].w *= alpha;
            *(float4*)(Ps + (ty*8 + u)*128 + tx*8) =
                make_float4(S[u][0], S[u][1], S[u][2], S[u][3]);
            *(float4*)(Ps + (ty*8 + u)*128 + tx*8 + 4) =
                make_float4(S[u][4], S[u][5], S[u][6], S[u][7]);
        }
        __syncthreads();

        // ---- PV: O[8 i][4 dv], dv slice = tx*4 ----
        #pragma unroll 2
        for (int jg = 0; jg < 32; jg++) {
            float4 v0 = *(const float4*)(Vs + (jg*4 + 0)*64 + (tx << 2));
            float4 v1 = *(const float4*)(Vs + (jg*4 + 1)*64 + (tx << 2));
            float4 v2 = *(const float4*)(Vs + (jg*4 + 2)*64 + (tx << 2));
            float4 v3 = *(const float4*)(Vs + (jg*4 + 3)*64 + (tx << 2));
            #pragma unroll
            for (int u = 0; u < 8; u++) {
                float4 p = *(const float4*)(Ps + (ty*8 + u)*128 + (jg << 2));
                O4[u].x += p.x*v0.x + p.y*v1.x + p.z*v2.x + p.w*v3.x;
                O4[u].y += p.x*v0.y + p.y*v1.y + p.z*v2.y + p.w*v3.y;
                O4[u].z += p.x*v0.z + p.y*v1.z + p.z*v2.z + p.w*v3.z;
                O4[u].w += p.x*v0.w + p.y*v1.w + p.z*v2.w + p.w*v3.w;
            }
        }
    }

    #pragma unroll
    for (int u = 0; u < 8; u++) {
        float inv = 1.f / l8[u];
        float4 o = make_float4(O4[u].x*inv, O4[u].y*inv, O4[u].z*inv, O4[u].w*inv);
        *(float4*)(g_ao + (size_t)(b*LL + ibase + u) * HD + h*64 + (tx << 2)) = o;
    }
}

// ---------------------------------------------------------------------------
extern "C" void kernel_launch(void* const* d_in, const int* in_sizes, int n_in,
                              void* d_out, int out_size) {
    const float* x  = (const float*)d_in[0];
    const float* Wq = (const float*)d_in[1];
    const float* Wk = (const float*)d_in[2];
    const float* Wv = (const float*)d_in[3];
    const float* Wo = (const float*)d_in[4];
    const float* bo = (const float*)d_in[5];
    const float* ub = (const float*)d_in[6];
    const float* vb = (const float*)d_in[7];
    const float* wp = (const float*)d_in[8];
    float* out = (float*)d_out;

    prep_kernel<<<1, 256>>>(vb, wp);

    qkv_kernel<<<dim3(16, 24), 256>>>(x, Wq, Wk, Wv);

    bias_prep_kernel<<<BB*LL, 256>>>(wp, ub);

    const int ATTN_SMEM = (64*128*2 + 128*64 + 128*128 + 128*33*2 + 128 + 1024) * 4;
    cudaFuncSetAttribute(attn_kernel, cudaFuncAttributeMaxDynamicSharedMemorySize, ATTN_SMEM);
    attn_kernel<<<dim3(LL/128, HH, BB), 256, ATTN_SMEM>>>();

    out_kernel<<<dim3(16, 12), 256>>>(Wo, bo, out);
}

// round 5
// speedup vs baseline: 2.4576x; 1.0736x over previous
#include <cuda_runtime.h>
#include <math.h>

#define BB 2
#define LL 1024
#define HH 8
#define DD 64
#define DMM 768
#define HD 512

typedef unsigned long long u64;

// ---------------- packed f32x2 helpers (sm_103a FFMA2 path) ----------------
__device__ __forceinline__ void fma2(u64& d, u64 a, u64 b) {
    asm("fma.rn.f32x2 %0, %1, %2, %0;" : "+l"(d) : "l"(a), "l"(b));
}
__device__ __forceinline__ u64 mul2(u64 a, u64 b) {
    u64 r; asm("mul.rn.f32x2 %0, %1, %2;" : "=l"(r) : "l"(a), "l"(b)); return r;
}
__device__ __forceinline__ u64 dup2(float x) {
    u64 r; unsigned u = __float_as_uint(x);
    asm("mov.b64 %0, {%1, %1};" : "=l"(r) : "r"(u)); return r;
}
__device__ __forceinline__ float2 unp2(u64 p) {
    unsigned lo, hi;
    asm("mov.b64 {%0, %1}, %2;" : "=r"(lo), "=r"(hi) : "l"(p));
    return make_float2(__uint_as_float(lo), __uint_as_float(hi));
}

// ---------------- scratch (static device globals; no allocs) ----------------
__device__ float g_q [BB*LL*HD];
__device__ float g_k [BB*LL*HD];
__device__ float g_v [BB*LL*HD];
__device__ float g_Su[BB*HH*LL*33];
__device__ float g_Ss[BB*HH*LL*33];
__device__ float g_uk[BB*HH*LL];
__device__ float g_Vu[HH*33];
__device__ float g_Vsg[HH*33];
__device__ int   g_tmin[LL];
__device__ float g_ao[BB*LL*HD];

// 8-float-granular XOR swizzle for k-major [64][128] tiles
#define SWC(kk,c) (((((c) >> 3) ^ ((kk) & 15)) << 3) | ((c) & 7))
// 4-float-granular XOR swizzle for k-major [16][64] tiles
#define SWB(kk,c) (((((c) >> 2) ^ ((kk) & 15)) << 2) | ((c) & 3))

// ---------------- prep: tmin LUT + per-head Vu/Vsg suffix tables -----------
__global__ void prep_kernel(const float* __restrict__ v_bias,
                            const float* __restrict__ w_pos) {
    __shared__ double cw[32];
    __shared__ float  vws[512];
    int tid = threadIdx.x;
    if (tid < 32)
        cw[tid] = exp((double)(tid + 1) * log((double)(LL + 1) / 2.0) / 32.0);
    __syncthreads();
    for (int a = tid; a < LL; a += 256) {
        int t = 32;
        for (int j = 31; j >= 0; j--) if ((double)a <= cw[j]) t = j;
        g_tmin[a] = t;
    }
    for (int o = tid; o < 512; o += 256) {
        int h = o >> 6, n = o & 63;
        float s = 0.f;
        for (int d = 0; d < 64; d++)
            s += v_bias[h*64 + d] * w_pos[h*4096 + d*64 + n];
        vws[o] = s;
    }
    __syncthreads();
    if (tid < 16) {
        int h = tid >> 1, sg = tid & 1;
        float run = 0.f;
        float* dst = (sg ? g_Vsg : g_Vu) + h*33;
        dst[32] = 0.f;
        for (int t = 31; t >= 0; t--) { run += vws[h*64 + sg*32 + t]; dst[t] = run; }
    }
}

// ---------------- GEMM body: C[128,64] tile = A[M,K] @ W[N,K]^T ------------
__device__ __forceinline__ void gemm_body(
    const float* __restrict__ A, const float* __restrict__ W,
    const float* __restrict__ bias, float* __restrict__ C,
    int K, int N, int m0, int n0, float* As, float* Bs)
{
    const int tid = threadIdx.x;
    const int ty = tid >> 4, tx = tid & 15;
    const int lr = tid >> 2, lc = (tid & 3) << 2;

    u64 acc2[4][4];   // row-pairs (2p,2p+1) x 4 cols
    #pragma unroll
    for (int p = 0; p < 4; p++)
        #pragma unroll
        for (int c = 0; c < 4; c++) acc2[p][c] = 0ull;

    const float* Ap0 = A + (size_t)(m0 + lr) * K + lc;
    const float* Ap1 = A + (size_t)(m0 + lr + 64) * K + lc;
    const float* Wp  = W + (size_t)(n0 + lr) * K + lc;

    float4 a0 = *(const float4*)Ap0;
    float4 a1 = *(const float4*)Ap1;
    float4 b0 = *(const float4*)Wp;

    for (int k0 = 0; k0 < K; k0 += 16) {
        {
            int kk = lc;
            As[(kk+0)*128 + SWC(kk+0, lr)]      = a0.x;
            As[(kk+1)*128 + SWC(kk+1, lr)]      = a0.y;
            As[(kk+2)*128 + SWC(kk+2, lr)]      = a0.z;
            As[(kk+3)*128 + SWC(kk+3, lr)]      = a0.w;
            As[(kk+0)*128 + SWC(kk+0, lr + 64)] = a1.x;
            As[(kk+1)*128 + SWC(kk+1, lr + 64)] = a1.y;
            As[(kk+2)*128 + SWC(kk+2, lr + 64)] = a1.z;
            As[(kk+3)*128 + SWC(kk+3, lr + 64)] = a1.w;
            Bs[(kk+0)*64 + SWB(kk+0, lr)] = b0.x;
            Bs[(kk+1)*64 + SWB(kk+1, lr)] = b0.y;
            Bs[(kk+2)*64 + SWB(kk+2, lr)] = b0.z;
            Bs[(kk+3)*64 + SWB(kk+3, lr)] = b0.w;
        }
        __syncthreads();
        if (k0 + 16 < K) {
            a0 = *(const float4*)(Ap0 + k0 + 16);
            a1 = *(const float4*)(Ap1 + k0 + 16);
            b0 = *(const float4*)(Wp  + k0 + 16);
        }
        #pragma unroll
        for (int kk = 0; kk < 16; kk++) {
            const ulonglong2* ap = (const ulonglong2*)(As + kk*128 + ((ty ^ kk) << 3));
            ulonglong2 xA = ap[0], xB = ap[1];
            u64 xu[4] = {xA.x, xA.y, xB.x, xB.y};
            float4 bb = *(const float4*)(Bs + kk*64 + ((tx ^ kk) << 2));
            u64 b2[4] = {dup2(bb.x), dup2(bb.y), dup2(bb.z), dup2(bb.w)};
            #pragma unroll
            for (int p = 0; p < 4; p++)
                #pragma unroll
                for (int c = 0; c < 4; c++)
                    fma2(acc2[p][c], xu[p], b2[c]);
        }
        __syncthreads();
    }

    float4 bv = make_float4(0.f, 0.f, 0.f, 0.f);
    if (bias) bv = *(const float4*)(bias + n0 + (tx << 2));
    #pragma unroll
    for (int p = 0; p < 4; p++) {
        float2 c0 = unp2(acc2[p][0]), c1 = unp2(acc2[p][1]);
        float2 c2 = unp2(acc2[p][2]), c3 = unp2(acc2[p][3]);
        float4 r0 = make_float4(c0.x + bv.x, c1.x + bv.y, c2.x + bv.z, c3.x + bv.w);
        float4 r1 = make_float4(c0.y + bv.x, c1.y + bv.y, c2.y + bv.z, c3.y + bv.w);
        *(float4*)(C + (size_t)(m0 + ty*8 + 2*p)     * N + n0 + (tx << 2)) = r0;
        *(float4*)(C + (size_t)(m0 + ty*8 + 2*p + 1) * N + n0 + (tx << 2)) = r1;
    }
}

// Fused QKV: grid (16, 24); by: 0-7 -> Q, 8-15 -> K, 16-23 -> V
__global__ __launch_bounds__(256)
void qkv_kernel(const float* __restrict__ x, const float* __restrict__ Wq,
                const float* __restrict__ Wk, const float* __restrict__ Wv) {
    __shared__ float As[16*128];
    __shared__ float Bs[16*64];
    int sel = blockIdx.y >> 3, nb = blockIdx.y & 7;
    const float* W = sel == 0 ? Wq : (sel == 1 ? Wk : Wv);
    float* C = sel == 0 ? g_q : (sel == 1 ? g_k : g_v);
    gemm_body(x, W, nullptr, C, DMM, HD, blockIdx.x * 128, nb * 64, As, Bs);
}

__global__ __launch_bounds__(256)
void out_kernel(const float* __restrict__ Wo, const float* __restrict__ bo,
                float* __restrict__ out) {
    __shared__ float As[16*128];
    __shared__ float Bs[16*64];
    gemm_body(g_ao, Wo, bo, out, HD, DMM, blockIdx.x * 128, blockIdx.y * 64, As, Bs);
}

// -------- bias prep: qw suffix sums (Su/Ss) + uk, one block per (b,i) ------
__global__ __launch_bounds__(256)
void bias_prep_kernel(const float* __restrict__ w_pos,
                      const float* __restrict__ u_bias) {
    int row = blockIdx.x;            // b*L + i
    int tid = threadIdx.x;
    __shared__ float qs[512], ks[512], qws[512];
    qs[tid]       = g_q[(size_t)row * HD + tid];
    qs[tid + 256] = g_q[(size_t)row * HD + tid + 256];
    ks[tid]       = g_k[(size_t)row * HD + tid];
    ks[tid + 256] = g_k[(size_t)row * HD + tid + 256];
    __syncthreads();
    for (int o = tid; o < 512; o += 256) {
        int h = o >> 6, n = o & 63;
        const float* wp = w_pos + h*4096 + n;
        float s = 0.f;
        #pragma unroll 8
        for (int d = 0; d < 64; d++) s += qs[h*64 + d] * wp[d << 6];
        qws[o] = s;
    }
    {
        int wid = tid >> 5, lane = tid & 31;
        float us = ks[wid*64 + lane]      * u_bias[wid*64 + lane]
                 + ks[wid*64 + 32 + lane] * u_bias[wid*64 + 32 + lane];
        #pragma unroll
        for (int off = 16; off; off >>= 1) us += __shfl_xor_sync(0xffffffffu, us, off);
        if (lane == 0) {
            int b = row >> 10, i = row & 1023;
            g_uk[(b*HH + wid) * LL + i] = us;
        }
    }
    __syncthreads();
    if (tid < 16) {
        int h = tid >> 1, sg = tid & 1;
        int b = row >> 10, i = row & 1023;
        float* dst = (sg ? g_Ss : g_Su) + (size_t)((b*HH + h) * LL + i) * 33;
        float run = 0.f;
        dst[32] = 0.f;
        for (int t = 31; t >= 0; t--) { run += qws[h*64 + sg*32 + t]; dst[t] = run; }
    }
}

// ---------------- flash attention, 128x128 tile, 8x8 micro-tile, f32x2 -----
__global__ __launch_bounds__(256, 1)
void attn_kernel() {
    extern __shared__ float sm[];
    float* Qst = sm;                    // [64][128] k-major, swizzled, pre-scaled
    float* Kst = Qst + 64*128;          // [64][128] k-major, swizzled
    float* Vs  = Kst + 64*128;          // [128][64] row-major
    float* Ps  = Vs  + 128*64;          // [128][128]
    float* Sus = Ps  + 128*128;         // [128][33]
    float* Sss = Sus + 128*33;          // [128][33]
    float* uks = Sss + 128*33;          // [128]
    int*   tms = (int*)(uks + 128);     // [1024]

    const int b = blockIdx.z, h = blockIdx.y;
    const int i0 = blockIdx.x * 128;
    const int tid = threadIdx.x;
    const int ty = tid >> 4, tx = tid & 15;

    {
        const float* qg = g_q + (size_t)(b*LL + i0) * HD + h*64;
        for (int x = tid; x < 128*16; x += 256) {
            int jj = x >> 4, c4 = x & 15;
            float4 qv = *(const float4*)(qg + (size_t)jj*HD + (c4 << 2));
            int k0 = c4 << 2;
            Qst[(k0+0)*128 + SWC(k0+0, jj)] = qv.x * 0.125f;
            Qst[(k0+1)*128 + SWC(k0+1, jj)] = qv.y * 0.125f;
            Qst[(k0+2)*128 + SWC(k0+2, jj)] = qv.z * 0.125f;
            Qst[(k0+3)*128 + SWC(k0+3, jj)] = qv.w * 0.125f;
        }
        const float* sub = g_Su + (size_t)((b*HH + h)*LL + i0) * 33;
        const float* ssb = g_Ss + (size_t)((b*HH + h)*LL + i0) * 33;
        const float* vu  = g_Vu  + h*33;
        const float* vsg = g_Vsg + h*33;
        for (int x = tid; x < 128*33; x += 256) {
            int t = x % 33;
            Sus[x] = (sub[x] + vu[t])  * 0.125f;
            Sss[x] = (ssb[x] + vsg[t]) * 0.125f;
        }
        for (int x = tid; x < LL; x += 256) tms[x] = g_tmin[x];
    }

    float m8[8], l8[8];
    u64 O2[8][2];
    #pragma unroll
    for (int u = 0; u < 8; u++) {
        m8[u] = -INFINITY; l8[u] = 0.f; O2[u][0] = 0ull; O2[u][1] = 0ull;
    }

    const int ibase = i0 + ty*8;

    for (int j0 = 0; j0 < LL; j0 += 128) {
        __syncthreads();
        const float* kg = g_k + (size_t)(b*LL + j0) * HD + h*64;
        const float* vg = g_v + (size_t)(b*LL + j0) * HD + h*64;
        for (int x = tid; x < 128*16; x += 256) {
            int jj = x >> 4, c4 = x & 15;
            float4 kv = *(const float4*)(kg + (size_t)jj*HD + (c4 << 2));
            int k0 = c4 << 2;
            Kst[(k0+0)*128 + SWC(k0+0, jj)] = kv.x;
            Kst[(k0+1)*128 + SWC(k0+1, jj)] = kv.y;
            Kst[(k0+2)*128 + SWC(k0+2, jj)] = kv.z;
            Kst[(k0+3)*128 + SWC(k0+3, jj)] = kv.w;
            *(float4*)(Vs + jj*64 + (c4 << 2)) =
                *(const float4*)(vg + (size_t)jj*HD + (c4 << 2));
        }
        if (tid < 128) uks[tid] = g_uk[(size_t)(b*HH + h)*LL + j0 + tid] * 0.125f;
        __syncthreads();

        // ---- scores: S2[u][w-pair], packed along j ----
        u64 S2[8][4];
        #pragma unroll
        for (int u = 0; u < 8; u++)
            #pragma unroll
            for (int w = 0; w < 4; w++) S2[u][w] = 0ull;

        #pragma unroll 4
        for (int kk = 0; kk < 64; kk++) {
            int f = kk & 15;
            const ulonglong2* kp = (const ulonglong2*)(Kst + kk*128 + ((tx ^ f) << 3));
            ulonglong2 kA = kp[0], kB = kp[1];
            u64 kw[4] = {kA.x, kA.y, kB.x, kB.y};
            const float4* qp = (const float4*)(Qst + kk*128 + ((ty ^ f) << 3));
            float4 qa = qp[0], qb = qp[1];
            float qr[8] = {qa.x, qa.y, qa.z, qa.w, qb.x, qb.y, qb.z, qb.w};
            #pragma unroll
            for (int u = 0; u < 8; u++) {
                u64 qd = dup2(qr[u]);
                #pragma unroll
                for (int w = 0; w < 4; w++) fma2(S2[u][w], qd, kw[w]);
            }
        }

        // ---- bias + online softmax (per i-row u) ----
        float4 uka = *(const float4*)(uks + tx*8);
        float4 ukb = *(const float4*)(uks + tx*8 + 4);
        float ukr[8] = {uka.x, uka.y, uka.z, uka.w, ukb.x, ukb.y, ukb.z, ukb.w};
        const int jbase = j0 + tx*8;
        #pragma unroll
        for (int u = 0; u < 8; u++) {
            float s[8];
            #pragma unroll
            for (int w = 0; w < 4; w++) {
                float2 t = unp2(S2[u][w]);
                s[2*w] = t.x; s[2*w+1] = t.y;
            }
            const int i = ibase + u;
            const float* suR = Sus + (ty*8 + u)*33;
            const float* ssR = Sss + (ty*8 + u)*33;
            #pragma unroll
            for (int w = 0; w < 8; w++) {
                int d = jbase + w - i;
                int a = d < 0 ? -d : d;
                int t = tms[a];
                float sg = (float)((d > 0) - (d < 0));
                s[w] += suR[t] + sg * ssR[t] + ukr[w];
            }
            float mt = s[0];
            #pragma unroll
            for (int w = 1; w < 8; w++) mt = fmaxf(mt, s[w]);
            #pragma unroll
            for (int off = 1; off <= 8; off <<= 1)
                mt = fmaxf(mt, __shfl_xor_sync(0xffffffffu, mt, off));
            float mn = fmaxf(m8[u], mt);
            float alpha = __expf(m8[u] - mn);
            float ps = 0.f;
            #pragma unroll
            for (int w = 0; w < 8; w++) { s[w] = __expf(s[w] - mn); ps += s[w]; }
            #pragma unroll
            for (int off = 1; off <= 8; off <<= 1)
                ps += __shfl_xor_sync(0xffffffffu, ps, off);
            l8[u] = l8[u] * alpha + ps;
            m8[u] = mn;
            u64 a2 = dup2(alpha);
            O2[u][0] = mul2(O2[u][0], a2);
            O2[u][1] = mul2(O2[u][1], a2);
            *(float4*)(Ps + (ty*8 + u)*128 + tx*8) =
                make_float4(s[0], s[1], s[2], s[3]);
            *(float4*)(Ps + (ty*8 + u)*128 + tx*8 + 4) =
                make_float4(s[4], s[5], s[6], s[7]);
        }
        __syncthreads();

        // ---- PV: O2[8 i][2 dv-pairs], dv slice = tx*4 ----
        #pragma unroll 2
        for (int jg = 0; jg < 32; jg++) {
            ulonglong2 v0 = *(const ulonglong2*)(Vs + (jg*4 + 0)*64 + (tx << 2));
            ulonglong2 v1 = *(const ulonglong2*)(Vs + (jg*4 + 1)*64 + (tx << 2));
            ulonglong2 v2 = *(const ulonglong2*)(Vs + (jg*4 + 2)*64 + (tx << 2));
            ulonglong2 v3 = *(const ulonglong2*)(Vs + (jg*4 + 3)*64 + (tx << 2));
            #pragma unroll
            for (int u = 0; u < 8; u++) {
                float4 p = *(const float4*)(Ps + (ty*8 + u)*128 + (jg << 2));
                u64 p0 = dup2(p.x), p1 = dup2(p.y), p2 = dup2(p.z), p3 = dup2(p.w);
                fma2(O2[u][0], p0, v0.x); fma2(O2[u][1], p0, v0.y);
                fma2(O2[u][0], p1, v1.x); fma2(O2[u][1], p1, v1.y);
                fma2(O2[u][0], p2, v2.x); fma2(O2[u][1], p2, v2.y);
                fma2(O2[u][0], p3, v3.x); fma2(O2[u][1], p3, v3.y);
            }
        }
    }

    #pragma unroll
    for (int u = 0; u < 8; u++) {
        u64 iv = dup2(1.f / l8[u]);
        float2 a = unp2(mul2(O2[u][0], iv));
        float2 c = unp2(mul2(O2[u][1], iv));
        *(float4*)(g_ao + (size_t)(b*LL + ibase + u) * HD + h*64 + (tx << 2)) =
            make_float4(a.x, a.y, c.x, c.y);
    }
}

// ---------------------------------------------------------------------------
extern "C" void kernel_launch(void* const* d_in, const int* in_sizes, int n_in,
                              void* d_out, int out_size) {
    const float* x  = (const float*)d_in[0];
    const float* Wq = (const float*)d_in[1];
    const float* Wk = (const float*)d_in[2];
    const float* Wv = (const float*)d_in[3];
    const float* Wo = (const float*)d_in[4];
    const float* bo = (const float*)d_in[5];
    const float* ub = (const float*)d_in[6];
    const float* vb = (const float*)d_in[7];
    const float* wp = (const float*)d_in[8];
    float* out = (float*)d_out;

    prep_kernel<<<1, 256>>>(vb, wp);

    qkv_kernel<<<dim3(16, 24), 256>>>(x, Wq, Wk, Wv);

    bias_prep_kernel<<<BB*LL, 256>>>(wp, ub);

    const int ATTN_SMEM = (64*128*2 + 128*64 + 128*128 + 128*33*2 + 128 + 1024) * 4;
    cudaFuncSetAttribute(attn_kernel, cudaFuncAttributeMaxDynamicSharedMemorySize, ATTN_SMEM);
    attn_kernel<<<dim3(LL/128, HH, BB), 256, ATTN_SMEM>>>();

    out_kernel<<<dim3(16, 12), 256>>>(Wo, bo, out);
}

// round 8
// speedup vs baseline: 3.0294x; 1.2327x over previous
#include <cuda_runtime.h>
#include <cuda_bf16.h>
#include <math.h>
#include <stdint.h>

#define BB 2
#define LL 1024
#define HH 8
#define DD 64
#define DMM 768
#define HD 512

typedef unsigned long long u64;

// ---------------- packed f32x2 helpers (attn) ------------------------------
__device__ __forceinline__ void fma2(u64& d, u64 a, u64 b) {
    asm("fma.rn.f32x2 %0, %1, %2, %0;" : "+l"(d) : "l"(a), "l"(b));
}
__device__ __forceinline__ u64 mul2(u64 a, u64 b) {
    u64 r; asm("mul.rn.f32x2 %0, %1, %2;" : "=l"(r) : "l"(a), "l"(b)); return r;
}
__device__ __forceinline__ u64 dup2(float x) {
    u64 r; unsigned u = __float_as_uint(x);
    asm("mov.b64 %0, {%1, %1};" : "=l"(r) : "r"(u)); return r;
}
__device__ __forceinline__ float2 unp2(u64 p) {
    unsigned lo, hi;
    asm("mov.b64 {%0, %1}, %2;" : "=r"(lo), "=r"(hi) : "l"(p));
    return make_float2(__uint_as_float(lo), __uint_as_float(hi));
}

// ---------------- mma.sync helpers (baseline ISA, works on sm_103) ---------
__device__ __forceinline__ uint32_t smem_u32(const void* p) {
    uint32_t a;
    asm("{ .reg .u64 t; cvta.to.shared.u64 t, %1; cvt.u32.u64 %0, t; }"
        : "=r"(a) : "l"(p));
    return a;
}
__device__ __forceinline__ void ldsm_x4(uint32_t& r0, uint32_t& r1,
                                        uint32_t& r2, uint32_t& r3, uint32_t addr) {
    asm volatile("ldmatrix.sync.aligned.m8n8.x4.shared.b16 {%0,%1,%2,%3}, [%4];"
                 : "=r"(r0), "=r"(r1), "=r"(r2), "=r"(r3) : "r"(addr));
}
__device__ __forceinline__ void mma_bf16(float* c, const uint32_t* a,
                                         uint32_t b0, uint32_t b1) {
    asm volatile(
        "mma.sync.aligned.m16n8k16.row.col.f32.bf16.bf16.f32 "
        "{%0,%1,%2,%3}, {%4,%5,%6,%7}, {%8,%9}, {%0,%1,%2,%3};"
        : "+f"(c[0]), "+f"(c[1]), "+f"(c[2]), "+f"(c[3])
        : "r"(a[0]), "r"(a[1]), "r"(a[2]), "r"(a[3]), "r"(b0), "r"(b1));
}

// ---------------- scratch (static device globals; no allocs) ----------------
__device__ float g_q [BB*LL*HD];
__device__ float g_k [BB*LL*HD];
__device__ float g_v [BB*LL*HD];
__device__ float g_Su[BB*HH*LL*33];
__device__ float g_Ss[BB*HH*LL*33];
__device__ float g_uk[BB*HH*LL];
__device__ float g_Vu[HH*33];
__device__ float g_Vsg[HH*33];
__device__ int   g_tmin[LL];
__device__ float g_ao[BB*LL*HD];

// bf16-split operand buffers
__device__ __align__(16) __nv_bfloat16 g_xhi [BB*LL*DMM];
__device__ __align__(16) __nv_bfloat16 g_xlo [BB*LL*DMM];
__device__ __align__(16) __nv_bfloat16 g_whi [3*HD*DMM];
__device__ __align__(16) __nv_bfloat16 g_wlo [3*HD*DMM];
__device__ __align__(16) __nv_bfloat16 g_wohi[DMM*HD];
__device__ __align__(16) __nv_bfloat16 g_wolo[DMM*HD];
__device__ __align__(16) __nv_bfloat16 g_aohi[BB*LL*HD];
__device__ __align__(16) __nv_bfloat16 g_aolo[BB*LL*HD];

// 8-float-granular XOR swizzle for k-major [64][128] f32 tiles (attn)
#define SWC(kk,c) (((((c) >> 3) ^ ((kk) & 15)) << 3) | ((c) & 7))

// ---------------- f32 -> bf16 hi/lo split ----------------------------------
__global__ __launch_bounds__(256)
void conv_kernel(const float* __restrict__ src, __nv_bfloat16* __restrict__ hi,
                 __nv_bfloat16* __restrict__ lo, int n4) {
    int i = blockIdx.x * 256 + threadIdx.x;
    if (i >= n4) return;
    float4 x = ((const float4*)src)[i];
    __nv_bfloat16 h0 = __float2bfloat16(x.x);
    __nv_bfloat16 h1 = __float2bfloat16(x.y);
    __nv_bfloat16 h2 = __float2bfloat16(x.z);
    __nv_bfloat16 h3 = __float2bfloat16(x.w);
    __nv_bfloat16 l0 = __float2bfloat16(x.x - __bfloat162float(h0));
    __nv_bfloat16 l1 = __float2bfloat16(x.y - __bfloat162float(h1));
    __nv_bfloat16 l2 = __float2bfloat16(x.z - __bfloat162float(h2));
    __nv_bfloat16 l3 = __float2bfloat16(x.w - __bfloat162float(h3));
    ((__nv_bfloat162*)hi)[2*i]     = __halves2bfloat162(h0, h1);
    ((__nv_bfloat162*)hi)[2*i + 1] = __halves2bfloat162(h2, h3);
    ((__nv_bfloat162*)lo)[2*i]     = __halves2bfloat162(l0, l1);
    ((__nv_bfloat162*)lo)[2*i + 1] = __halves2bfloat162(l2, l3);
}

// ---------------- mma.sync bf16-split GEMM body ----------------------------
// C[128,128] tile = A[128,Kt] @ B[128,Kt]^T  (3-term bf16 split, fp32 acc)
// 256 thr = 8 warps (2 M x 4 N), warp tile 64x32, K chunk 64 in smem.
__device__ __forceinline__ void gemm_mma_body(
    const __nv_bfloat16* __restrict__ Ahi, const __nv_bfloat16* __restrict__ Alo,
    const __nv_bfloat16* __restrict__ Bhi, const __nv_bfloat16* __restrict__ Blo,
    int Kt, float* __restrict__ Cout, int Cstride, const float* __restrict__ bias)
{
    extern __shared__ char gsm[];
    const uint32_t sb = smem_u32(gsm);
    const int tid = threadIdx.x;
    const int wid = tid >> 5, lane = tid & 31;
    const int wm = wid >> 2, wn = wid & 3;       // warp grid 2 x 4

    float acc[4][4][4];
    #pragma unroll
    for (int mt = 0; mt < 4; mt++)
        #pragma unroll
        for (int nt = 0; nt < 4; nt++)
            #pragma unroll
            for (int r = 0; r < 4; r++) acc[mt][nt][r] = 0.f;

    // ldmatrix lane geometry
    const int lr  = lane & 15;        // row within 16-row tile
    const int lk8 = lane >> 4;        // 0/1 -> k halves (8 bf16 = 1 seg)

    const __nv_bfloat16* srcs[4] = {Ahi, Alo, Bhi, Blo};
    const int NCH = Kt >> 6;

    for (int ch = 0; ch < NCH; ch++) {
        const int k0 = ch << 6;
        // fill 4 operand tiles [128 rows][64 bf16], 128B rows, XOR-16B swizzle
        #pragma unroll
        for (int t = 0; t < 4; t++) {
            const __nv_bfloat16* s = srcs[t] + k0;
            char* dp = gsm + t * 16384;
            #pragma unroll
            for (int u = 0; u < 4; u++) {
                int e = tid + u * 256;           // 0..1023
                int row = e >> 3, seg = e & 7;
                uint4 v = *(const uint4*)(s + (size_t)row * Kt + seg * 8);
                *(uint4*)(dp + row * 128 + ((seg ^ (row & 7)) << 4)) = v;
            }
        }
        __syncthreads();

        #pragma unroll
        for (int ks = 0; ks < 4; ks++) {
            const int kseg = (ks << 1) + lk8;
            // A frags: 4 m16 tiles, hi+lo
            uint32_t ah[4][4], al[4][4];
            #pragma unroll
            for (int mt = 0; mt < 4; mt++) {
                int row = wm * 64 + mt * 16 + lr;
                uint32_t off = row * 128 + (((kseg ^ (row & 7))) << 4);
                ldsm_x4(ah[mt][0], ah[mt][1], ah[mt][2], ah[mt][3], sb + off);
                ldsm_x4(al[mt][0], al[mt][1], al[mt][2], al[mt][3], sb + 16384 + off);
            }
            // B frags: 2 n16 tiles, hi+lo -> per n8: {r0,r2} / {r1,r3}
            uint32_t bh[2][4], bl[2][4];
            #pragma unroll
            for (int bt = 0; bt < 2; bt++) {
                int row = wn * 32 + bt * 16 + lr;
                uint32_t off = row * 128 + (((kseg ^ (row & 7))) << 4);
                ldsm_x4(bh[bt][0], bh[bt][1], bh[bt][2], bh[bt][3], sb + 32768 + off);
                ldsm_x4(bl[bt][0], bl[bt][1], bl[bt][2], bl[bt][3], sb + 49152 + off);
            }
            #pragma unroll
            for (int mt = 0; mt < 4; mt++) {
                #pragma unroll
                for (int nt = 0; nt < 4; nt++) {
                    int bt = nt >> 1, hi = nt & 1;
                    uint32_t b0h = bh[bt][hi],     b1h = bh[bt][hi + 2];
                    uint32_t b0l = bl[bt][hi],     b1l = bl[bt][hi + 2];
                    mma_bf16(acc[mt][nt], ah[mt], b0h, b1h);
                    mma_bf16(acc[mt][nt], ah[mt], b0l, b1l);
                    mma_bf16(acc[mt][nt], al[mt], b0h, b1h);
                }
            }
        }
        __syncthreads();
    }

    // epilogue: c0=(r,c), c1=(r,c+1), c2=(r+8,c), c3=(r+8,c+1)
    const int er = lane >> 2, ec = (lane & 3) << 1;
    #pragma unroll
    for (int mt = 0; mt < 4; mt++) {
        #pragma unroll
        for (int nt = 0; nt < 4; nt++) {
            int m = wm * 64 + mt * 16 + er;
            int n = wn * 32 + nt * 8 + ec;
            float b0 = 0.f, b1 = 0.f;
            if (bias) { b0 = bias[n]; b1 = bias[n + 1]; }
            *(float2*)(Cout + (size_t)m * Cstride + n) =
                make_float2(acc[mt][nt][0] + b0, acc[mt][nt][1] + b1);
            *(float2*)(Cout + (size_t)(m + 8) * Cstride + n) =
                make_float2(acc[mt][nt][2] + b0, acc[mt][nt][3] + b1);
        }
    }
}

// QKV: grid (16 M-tiles, 12 N-tiles over concatenated 1536)
__global__ __launch_bounds__(256)
void qkv_mma_kernel() {
    int m0 = blockIdx.x * 128;
    int nglob = blockIdx.y * 128;
    int sel = nglob >> 9, ncol = nglob & 511;
    float* base = sel == 0 ? g_q : (sel == 1 ? g_k : g_v);
    gemm_mma_body(g_xhi + (size_t)m0 * DMM, g_xlo + (size_t)m0 * DMM,
                  g_whi + (size_t)nglob * DMM, g_wlo + (size_t)nglob * DMM,
                  DMM, base + (size_t)m0 * HD + ncol, HD, nullptr);
}

// out: grid (16 M-tiles, 6 N-tiles over 768)
__global__ __launch_bounds__(256)
void out_mma_kernel(const float* __restrict__ bo, float* __restrict__ out) {
    int m0 = blockIdx.x * 128;
    int n0 = blockIdx.y * 128;
    gemm_mma_body(g_aohi + (size_t)m0 * HD, g_aolo + (size_t)m0 * HD,
                  g_wohi + (size_t)n0 * HD, g_wolo + (size_t)n0 * HD,
                  HD, out + (size_t)m0 * DMM + n0, DMM, bo + n0);
}

// ---------------- prep: tmin LUT + per-head Vu/Vsg suffix tables -----------
__global__ void prep_kernel(const float* __restrict__ v_bias,
                            const float* __restrict__ w_pos) {
    __shared__ double cw[32];
    __shared__ float  vws[512];
    int tid = threadIdx.x;
    if (tid < 32)
        cw[tid] = exp((double)(tid + 1) * log((double)(LL + 1) / 2.0) / 32.0);
    __syncthreads();
    for (int a = tid; a < LL; a += 256) {
        int t = 32;
        for (int j = 31; j >= 0; j--) if ((double)a <= cw[j]) t = j;
        g_tmin[a] = t;
    }
    for (int o = tid; o < 512; o += 256) {
        int h = o >> 6, n = o & 63;
        float s = 0.f;
        for (int d = 0; d < 64; d++)
            s += v_bias[h*64 + d] * w_pos[h*4096 + d*64 + n];
        vws[o] = s;
    }
    __syncthreads();
    if (tid < 16) {
        int h = tid >> 1, sg = tid & 1;
        float run = 0.f;
        float* dst = (sg ? g_Vsg : g_Vu) + h*33;
        dst[32] = 0.f;
        for (int t = 31; t >= 0; t--) { run += vws[h*64 + sg*32 + t]; dst[t] = run; }
    }
}

// -------- bias prep: qw suffix sums (Su/Ss) + uk, one block per (b,i) ------
__global__ __launch_bounds__(256)
void bias_prep_kernel(const float* __restrict__ w_pos,
                      const float* __restrict__ u_bias) {
    int row = blockIdx.x;            // b*L + i
    int tid = threadIdx.x;
    __shared__ float qs[512], ks[512], qws[512];
    qs[tid]       = g_q[(size_t)row * HD + tid];
    qs[tid + 256] = g_q[(size_t)row * HD + tid + 256];
    ks[tid]       = g_k[(size_t)row * HD + tid];
    ks[tid + 256] = g_k[(size_t)row * HD + tid + 256];
    __syncthreads();
    for (int o = tid; o < 512; o += 256) {
        int h = o >> 6, n = o & 63;
        const float* wp = w_pos + h*4096 + n;
        float s = 0.f;
        #pragma unroll 8
        for (int d = 0; d < 64; d++) s += qs[h*64 + d] * wp[d << 6];
        qws[o] = s;
    }
    {
        int wid = tid >> 5, lane = tid & 31;
        float us = ks[wid*64 + lane]      * u_bias[wid*64 + lane]
                 + ks[wid*64 + 32 + lane] * u_bias[wid*64 + 32 + lane];
        #pragma unroll
        for (int off = 16; off; off >>= 1) us += __shfl_xor_sync(0xffffffffu, us, off);
        if (lane == 0) {
            int b = row >> 10, i = row & 1023;
            g_uk[(b*HH + wid) * LL + i] = us;
        }
    }
    __syncthreads();
    if (tid < 16) {
        int h = tid >> 1, sg = tid & 1;
        int b = row >> 10, i = row & 1023;
        float* dst = (sg ? g_Ss : g_Su) + (size_t)((b*HH + h) * LL + i) * 33;
        float run = 0.f;
        dst[32] = 0.f;
        for (int t = 31; t >= 0; t--) { run += qws[h*64 + sg*32 + t]; dst[t] = run; }
    }
}

// ---------------- flash attention, 128x128 tile, 8x8 micro-tile, f32x2 -----
__global__ __launch_bounds__(256, 1)
void attn_kernel() {
    extern __shared__ float sm[];
    float* Qst = sm;                    // [64][128] k-major, swizzled, pre-scaled
    float* Kst = Qst + 64*128;          // [64][128] k-major, swizzled
    float* Vs  = Kst + 64*128;          // [128][64] row-major
    float* Ps  = Vs  + 128*64;          // [128][128]
    float* Sus = Ps  + 128*128;         // [128][33]
    float* Sss = Sus + 128*33;          // [128][33]
    float* uks = Sss + 128*33;          // [128]
    int*   tms = (int*)(uks + 128);     // [1024]

    const int b = blockIdx.z, h = blockIdx.y;
    const int i0 = blockIdx.x * 128;
    const int tid = threadIdx.x;
    const int ty = tid >> 4, tx = tid & 15;

    {
        const float* qg = g_q + (size_t)(b*LL + i0) * HD + h*64;
        for (int x = tid; x < 128*16; x += 256) {
            int jj = x >> 4, c4 = x & 15;
            float4 qv = *(const float4*)(qg + (size_t)jj*HD + (c4 << 2));
            int k0 = c4 << 2;
            Qst[(k0+0)*128 + SWC(k0+0, jj)] = qv.x * 0.125f;
            Qst[(k0+1)*128 + SWC(k0+1, jj)] = qv.y * 0.125f;
            Qst[(k0+2)*128 + SWC(k0+2, jj)] = qv.z * 0.125f;
            Qst[(k0+3)*128 + SWC(k0+3, jj)] = qv.w * 0.125f;
        }
        const float* sub = g_Su + (size_t)((b*HH + h)*LL + i0) * 33;
        const float* ssb = g_Ss + (size_t)((b*HH + h)*LL + i0) * 33;
        const float* vu  = g_Vu  + h*33;
        const float* vsg = g_Vsg + h*33;
        for (int x = tid; x < 128*33; x += 256) {
            int t = x % 33;
            Sus[x] = (sub[x] + vu[t])  * 0.125f;
            Sss[x] = (ssb[x] + vsg[t]) * 0.125f;
        }
        for (int x = tid; x < LL; x += 256) tms[x] = g_tmin[x];
    }

    float m8[8], l8[8];
    u64 O2[8][2];
    #pragma unroll
    for (int u = 0; u < 8; u++) {
        m8[u] = -INFINITY; l8[u] = 0.f; O2[u][0] = 0ull; O2[u][1] = 0ull;
    }

    const int ibase = i0 + ty*8;

    for (int j0 = 0; j0 < LL; j0 += 128) {
        __syncthreads();
        const float* kg = g_k + (size_t)(b*LL + j0) * HD + h*64;
        const float* vg = g_v + (size_t)(b*LL + j0) * HD + h*64;
        for (int x = tid; x < 128*16; x += 256) {
            int jj = x >> 4, c4 = x & 15;
            float4 kv = *(const float4*)(kg + (size_t)jj*HD + (c4 << 2));
            int k0 = c4 << 2;
            Kst[(k0+0)*128 + SWC(k0+0, jj)] = kv.x;
            Kst[(k0+1)*128 + SWC(k0+1, jj)] = kv.y;
            Kst[(k0+2)*128 + SWC(k0+2, jj)] = kv.z;
            Kst[(k0+3)*128 + SWC(k0+3, jj)] = kv.w;
            *(float4*)(Vs + jj*64 + (c4 << 2)) =
                *(const float4*)(vg + (size_t)jj*HD + (c4 << 2));
        }
        if (tid < 128) uks[tid] = g_uk[(size_t)(b*HH + h)*LL + j0 + tid] * 0.125f;
        __syncthreads();

        u64 S2[8][4];
        #pragma unroll
        for (int u = 0; u < 8; u++)
            #pragma unroll
            for (int w = 0; w < 4; w++) S2[u][w] = 0ull;

        #pragma unroll 4
        for (int kk = 0; kk < 64; kk++) {
            int f = kk & 15;
            const ulonglong2* kp = (const ulonglong2*)(Kst + kk*128 + ((tx ^ f) << 3));
            ulonglong2 kA = kp[0], kB = kp[1];
            u64 kw[4] = {kA.x, kA.y, kB.x, kB.y};
            const float4* qp = (const float4*)(Qst + kk*128 + ((ty ^ f) << 3));
            float4 qa = qp[0], qb = qp[1];
            float qr[8] = {qa.x, qa.y, qa.z, qa.w, qb.x, qb.y, qb.z, qb.w};
            #pragma unroll
            for (int u = 0; u < 8; u++) {
                u64 qd = dup2(qr[u]);
                #pragma unroll
                for (int w = 0; w < 4; w++) fma2(S2[u][w], qd, kw[w]);
            }
        }

        float4 uka = *(const float4*)(uks + tx*8);
        float4 ukb = *(const float4*)(uks + tx*8 + 4);
        float ukr[8] = {uka.x, uka.y, uka.z, uka.w, ukb.x, ukb.y, ukb.z, ukb.w};
        const int jbase = j0 + tx*8;
        #pragma unroll
        for (int u = 0; u < 8; u++) {
            float s[8];
            #pragma unroll
            for (int w = 0; w < 4; w++) {
                float2 t = unp2(S2[u][w]);
                s[2*w] = t.x; s[2*w+1] = t.y;
            }
            const int i = ibase + u;
            const float* suR = Sus + (ty*8 + u)*33;
            const float* ssR = Sss + (ty*8 + u)*33;
            #pragma unroll
            for (int w = 0; w < 8; w++) {
                int d = jbase + w - i;
                int a = d < 0 ? -d : d;
                int t = tms[a];
                float sg = (float)((d > 0) - (d < 0));
                s[w] += suR[t] + sg * ssR[t] + ukr[w];
            }
            float mt = s[0];
            #pragma unroll
            for (int w = 1; w < 8; w++) mt = fmaxf(mt, s[w]);
            #pragma unroll
            for (int off = 1; off <= 8; off <<= 1)
                mt = fmaxf(mt, __shfl_xor_sync(0xffffffffu, mt, off));
            float mn = fmaxf(m8[u], mt);
            float alpha = __expf(m8[u] - mn);
            float ps = 0.f;
            #pragma unroll
            for (int w = 0; w < 8; w++) { s[w] = __expf(s[w] - mn); ps += s[w]; }
            #pragma unroll
            for (int off = 1; off <= 8; off <<= 1)
                ps += __shfl_xor_sync(0xffffffffu, ps, off);
            l8[u] = l8[u] * alpha + ps;
            m8[u] = mn;
            u64 a2 = dup2(alpha);
            O2[u][0] = mul2(O2[u][0], a2);
            O2[u][1] = mul2(O2[u][1], a2);
            *(float4*)(Ps + (ty*8 + u)*128 + tx*8) =
                make_float4(s[0], s[1], s[2], s[3]);
            *(float4*)(Ps + (ty*8 + u)*128 + tx*8 + 4) =
                make_float4(s[4], s[5], s[6], s[7]);
        }
        __syncthreads();

        #pragma unroll 2
        for (int jg = 0; jg < 32; jg++) {
            ulonglong2 v0 = *(const ulonglong2*)(Vs + (jg*4 + 0)*64 + (tx << 2));
            ulonglong2 v1 = *(const ulonglong2*)(Vs + (jg*4 + 1)*64 + (tx << 2));
            ulonglong2 v2 = *(const ulonglong2*)(Vs + (jg*4 + 2)*64 + (tx << 2));
            ulonglong2 v3 = *(const ulonglong2*)(Vs + (jg*4 + 3)*64 + (tx << 2));
            #pragma unroll
            for (int u = 0; u < 8; u++) {
                float4 p = *(const float4*)(Ps + (ty*8 + u)*128 + (jg << 2));
                u64 p0 = dup2(p.x), p1 = dup2(p.y), p2 = dup2(p.z), p3 = dup2(p.w);
                fma2(O2[u][0], p0, v0.x); fma2(O2[u][1], p0, v0.y);
                fma2(O2[u][0], p1, v1.x); fma2(O2[u][1], p1, v1.y);
                fma2(O2[u][0], p2, v2.x); fma2(O2[u][1], p2, v2.y);
                fma2(O2[u][0], p3, v3.x); fma2(O2[u][1], p3, v3.y);
            }
        }
    }

    #pragma unroll
    for (int u = 0; u < 8; u++) {
        u64 iv = dup2(1.f / l8[u]);
        float2 a = unp2(mul2(O2[u][0], iv));
        float2 c = unp2(mul2(O2[u][1], iv));
        *(float4*)(g_ao + (size_t)(b*LL + ibase + u) * HD + h*64 + (tx << 2)) =
            make_float4(a.x, a.y, c.x, c.y);
    }
}

// ---------------------------------------------------------------------------
extern "C" void kernel_launch(void* const* d_in, const int* in_sizes, int n_in,
                              void* d_out, int out_size) {
    const float* x  = (const float*)d_in[0];
    const float* Wq = (const float*)d_in[1];
    const float* Wk = (const float*)d_in[2];
    const float* Wv = (const float*)d_in[3];
    const float* Wo = (const float*)d_in[4];
    const float* bo = (const float*)d_in[5];
    const float* ub = (const float*)d_in[6];
    const float* vb = (const float*)d_in[7];
    const float* wp = (const float*)d_in[8];
    float* out = (float*)d_out;

    __nv_bfloat16 *pxh, *pxl, *pwh, *pwl, *pwoh, *pwol, *paoh, *paol;
    float* pao;
    cudaGetSymbolAddress((void**)&pxh,  g_xhi);
    cudaGetSymbolAddress((void**)&pxl,  g_xlo);
    cudaGetSymbolAddress((void**)&pwh,  g_whi);
    cudaGetSymbolAddress((void**)&pwl,  g_wlo);
    cudaGetSymbolAddress((void**)&pwoh, g_wohi);
    cudaGetSymbolAddress((void**)&pwol, g_wolo);
    cudaGetSymbolAddress((void**)&paoh, g_aohi);
    cudaGetSymbolAddress((void**)&paol, g_aolo);
    cudaGetSymbolAddress((void**)&pao,  g_ao);

    prep_kernel<<<1, 256>>>(vb, wp);

    // bf16 split conversions
    conv_kernel<<<1536, 256>>>(x,  pxh, pxl, BB*LL*DMM/4);
    conv_kernel<<<384, 256>>>(Wq, pwh,             pwl,             HD*DMM/4);
    conv_kernel<<<384, 256>>>(Wk, pwh + HD*DMM,    pwl + HD*DMM,    HD*DMM/4);
    conv_kernel<<<384, 256>>>(Wv, pwh + 2*HD*DMM,  pwl + 2*HD*DMM,  HD*DMM/4);
    conv_kernel<<<384, 256>>>(Wo, pwoh, pwol, DMM*HD/4);

    const int GEMM_SMEM = 65536;
    cudaFuncSetAttribute(qkv_mma_kernel, cudaFuncAttributeMaxDynamicSharedMemorySize, GEMM_SMEM);
    cudaFuncSetAttribute(out_mma_kernel, cudaFuncAttributeMaxDynamicSharedMemorySize, GEMM_SMEM);

    qkv_mma_kernel<<<dim3(16, 12), 256, GEMM_SMEM>>>();

    bias_prep_kernel<<<BB*LL, 256>>>(wp, ub);

    const int ATTN_SMEM = (64*128*2 + 128*64 + 128*128 + 128*33*2 + 128 + 1024) * 4;
    cudaFuncSetAttribute(attn_kernel, cudaFuncAttributeMaxDynamicSharedMemorySize, ATTN_SMEM);
    attn_kernel<<<dim3(LL/128, HH, BB), 256, ATTN_SMEM>>>();

    conv_kernel<<<1024, 256>>>(pao, paoh, paol, BB*LL*HD/4);
    out_mma_kernel<<<dim3(16, 6), 256, GEMM_SMEM>>>(bo, out);
}

// round 9
// speedup vs baseline: 3.6281x; 1.1976x over previous
#include <cuda_runtime.h>
#include <cuda_bf16.h>
#include <math.h>
#include <stdint.h>

#define BB 2
#define LL 1024
#define HH 8
#define DD 64
#define DMM 768
#define HD 512

typedef unsigned long long u64;

// ---------------- mma.sync helpers (baseline ISA, works on sm_103) ---------
__device__ __forceinline__ uint32_t smem_u32(const void* p) {
    uint32_t a;
    asm("{ .reg .u64 t; cvta.to.shared.u64 t, %1; cvt.u32.u64 %0, t; }"
        : "=r"(a) : "l"(p));
    return a;
}
__device__ __forceinline__ void ldsm_x4(uint32_t& r0, uint32_t& r1,
                                        uint32_t& r2, uint32_t& r3, uint32_t addr) {
    asm volatile("ldmatrix.sync.aligned.m8n8.x4.shared.b16 {%0,%1,%2,%3}, [%4];"
                 : "=r"(r0), "=r"(r1), "=r"(r2), "=r"(r3) : "r"(addr));
}
__device__ __forceinline__ void mma_bf16(float* c, const uint32_t* a,
                                         uint32_t b0, uint32_t b1) {
    asm volatile(
        "mma.sync.aligned.m16n8k16.row.col.f32.bf16.bf16.f32 "
        "{%0,%1,%2,%3}, {%4,%5,%6,%7}, {%8,%9}, {%0,%1,%2,%3};"
        : "+f"(c[0]), "+f"(c[1]), "+f"(c[2]), "+f"(c[3])
        : "r"(a[0]), "r"(a[1]), "r"(a[2]), "r"(a[3]), "r"(b0), "r"(b1));
}
// split two floats into packed-bf16 hi and lo words
__device__ __forceinline__ void split2(float a, float b, uint32_t& hi, uint32_t& lo) {
    __nv_bfloat16 ha = __float2bfloat16(a), hb = __float2bfloat16(b);
    __nv_bfloat16 la = __float2bfloat16(a - __bfloat162float(ha));
    __nv_bfloat16 lb = __float2bfloat16(b - __bfloat162float(hb));
    hi = (uint32_t)*(unsigned short*)&ha | ((uint32_t)*(unsigned short*)&hb << 16);
    lo = (uint32_t)*(unsigned short*)&la | ((uint32_t)*(unsigned short*)&lb << 16);
}

// ---------------- scratch (static device globals; no allocs) ----------------
__device__ float g_q [BB*LL*HD];
__device__ float g_k [BB*LL*HD];
__device__ float g_v [BB*LL*HD];
__device__ float g_Su[BB*HH*LL*33];
__device__ float g_Ss[BB*HH*LL*33];
__device__ float g_uk[BB*HH*LL];
__device__ float g_Vu[HH*33];
__device__ float g_Vsg[HH*33];
__device__ int   g_tmin[LL];
__device__ float g_ao[BB*LL*HD];

// bf16-split operand buffers
__device__ __align__(16) __nv_bfloat16 g_xhi [BB*LL*DMM];
__device__ __align__(16) __nv_bfloat16 g_xlo [BB*LL*DMM];
__device__ __align__(16) __nv_bfloat16 g_whi [3*HD*DMM];
__device__ __align__(16) __nv_bfloat16 g_wlo [3*HD*DMM];
__device__ __align__(16) __nv_bfloat16 g_wohi[DMM*HD];
__device__ __align__(16) __nv_bfloat16 g_wolo[DMM*HD];
__device__ __align__(16) __nv_bfloat16 g_aohi[BB*LL*HD];
__device__ __align__(16) __nv_bfloat16 g_aolo[BB*LL*HD];
__device__ __align__(16) __nv_bfloat16 g_qh[BB*LL*HD];
__device__ __align__(16) __nv_bfloat16 g_ql[BB*LL*HD];
__device__ __align__(16) __nv_bfloat16 g_kh[BB*LL*HD];
__device__ __align__(16) __nv_bfloat16 g_kl[BB*LL*HD];
__device__ __align__(16) __nv_bfloat16 g_vh[BB*LL*HD];
__device__ __align__(16) __nv_bfloat16 g_vl[BB*LL*HD];

// ---------------- f32 -> bf16 hi/lo split (optional scale) -----------------
__global__ __launch_bounds__(256)
void conv_kernel(const float* __restrict__ src, __nv_bfloat16* __restrict__ hi,
                 __nv_bfloat16* __restrict__ lo, int n4, float scale) {
    int i = blockIdx.x * 256 + threadIdx.x;
    if (i >= n4) return;
    float4 x = ((const float4*)src)[i];
    x.x *= scale; x.y *= scale; x.z *= scale; x.w *= scale;
    uint32_t h0, l0, h1, l1;
    split2(x.x, x.y, h0, l0);
    split2(x.z, x.w, h1, l1);
    ((uint32_t*)hi)[2*i]     = h0;
    ((uint32_t*)hi)[2*i + 1] = h1;
    ((uint32_t*)lo)[2*i]     = l0;
    ((uint32_t*)lo)[2*i + 1] = l1;
}

// ---------------- mma.sync bf16-split GEMM body ----------------------------
__device__ __forceinline__ void gemm_mma_body(
    const __nv_bfloat16* __restrict__ Ahi, const __nv_bfloat16* __restrict__ Alo,
    const __nv_bfloat16* __restrict__ Bhi, const __nv_bfloat16* __restrict__ Blo,
    int Kt, float* __restrict__ Cout, int Cstride, const float* __restrict__ bias)
{
    extern __shared__ char gsm[];
    const uint32_t sb = smem_u32(gsm);
    const int tid = threadIdx.x;
    const int wid = tid >> 5, lane = tid & 31;
    const int wm = wid >> 2, wn = wid & 3;

    float acc[4][4][4];
    #pragma unroll
    for (int mt = 0; mt < 4; mt++)
        #pragma unroll
        for (int nt = 0; nt < 4; nt++)
            #pragma unroll
            for (int r = 0; r < 4; r++) acc[mt][nt][r] = 0.f;

    const int lr  = lane & 15;
    const int lk8 = lane >> 4;

    const __nv_bfloat16* srcs[4] = {Ahi, Alo, Bhi, Blo};
    const int NCH = Kt >> 6;

    for (int ch = 0; ch < NCH; ch++) {
        const int k0 = ch << 6;
        #pragma unroll
        for (int t = 0; t < 4; t++) {
            const __nv_bfloat16* s = srcs[t] + k0;
            char* dp = gsm + t * 16384;
            #pragma unroll
            for (int u = 0; u < 4; u++) {
                int e = tid + u * 256;
                int row = e >> 3, seg = e & 7;
                uint4 v = *(const uint4*)(s + (size_t)row * Kt + seg * 8);
                *(uint4*)(dp + row * 128 + ((seg ^ (row & 7)) << 4)) = v;
            }
        }
        __syncthreads();

        #pragma unroll
        for (int ks = 0; ks < 4; ks++) {
            const int kseg = (ks << 1) + lk8;
            uint32_t ah[4][4], al[4][4];
            #pragma unroll
            for (int mt = 0; mt < 4; mt++) {
                int row = wm * 64 + mt * 16 + lr;
                uint32_t off = row * 128 + (((kseg ^ (row & 7))) << 4);
                ldsm_x4(ah[mt][0], ah[mt][1], ah[mt][2], ah[mt][3], sb + off);
                ldsm_x4(al[mt][0], al[mt][1], al[mt][2], al[mt][3], sb + 16384 + off);
            }
            uint32_t bh[2][4], bl[2][4];
            #pragma unroll
            for (int bt = 0; bt < 2; bt++) {
                int row = wn * 32 + bt * 16 + lr;
                uint32_t off = row * 128 + (((kseg ^ (row & 7))) << 4);
                ldsm_x4(bh[bt][0], bh[bt][1], bh[bt][2], bh[bt][3], sb + 32768 + off);
                ldsm_x4(bl[bt][0], bl[bt][1], bl[bt][2], bl[bt][3], sb + 49152 + off);
            }
            #pragma unroll
            for (int mt = 0; mt < 4; mt++) {
                #pragma unroll
                for (int nt = 0; nt < 4; nt++) {
                    int bt = nt >> 1, hi = nt & 1;
                    mma_bf16(acc[mt][nt], ah[mt], bh[bt][hi], bh[bt][hi + 2]);
                    mma_bf16(acc[mt][nt], ah[mt], bl[bt][hi], bl[bt][hi + 2]);
                    mma_bf16(acc[mt][nt], al[mt], bh[bt][hi], bh[bt][hi + 2]);
                }
            }
        }
        __syncthreads();
    }

    const int er = lane >> 2, ec = (lane & 3) << 1;
    #pragma unroll
    for (int mt = 0; mt < 4; mt++) {
        #pragma unroll
        for (int nt = 0; nt < 4; nt++) {
            int m = wm * 64 + mt * 16 + er;
            int n = wn * 32 + nt * 8 + ec;
            float b0 = 0.f, b1 = 0.f;
            if (bias) { b0 = bias[n]; b1 = bias[n + 1]; }
            *(float2*)(Cout + (size_t)m * Cstride + n) =
                make_float2(acc[mt][nt][0] + b0, acc[mt][nt][1] + b1);
            *(float2*)(Cout + (size_t)(m + 8) * Cstride + n) =
                make_float2(acc[mt][nt][2] + b0, acc[mt][nt][3] + b1);
        }
    }
}

__global__ __launch_bounds__(256)
void qkv_mma_kernel() {
    int m0 = blockIdx.x * 128;
    int nglob = blockIdx.y * 128;
    int sel = nglob >> 9, ncol = nglob & 511;
    float* base = sel == 0 ? g_q : (sel == 1 ? g_k : g_v);
    gemm_mma_body(g_xhi + (size_t)m0 * DMM, g_xlo + (size_t)m0 * DMM,
                  g_whi + (size_t)nglob * DMM, g_wlo + (size_t)nglob * DMM,
                  DMM, base + (size_t)m0 * HD + ncol, HD, nullptr);
}

__global__ __launch_bounds__(256)
void out_mma_kernel(const float* __restrict__ bo, float* __restrict__ out) {
    int m0 = blockIdx.x * 128;
    int n0 = blockIdx.y * 128;
    gemm_mma_body(g_aohi + (size_t)m0 * HD, g_aolo + (size_t)m0 * HD,
                  g_wohi + (size_t)n0 * HD, g_wolo + (size_t)n0 * HD,
                  HD, out + (size_t)m0 * DMM + n0, DMM, bo + n0);
}

// ---------------- prep: tmin LUT + per-head Vu/Vsg suffix tables -----------
__global__ void prep_kernel(const float* __restrict__ v_bias,
                            const float* __restrict__ w_pos) {
    __shared__ double cw[32];
    __shared__ float  vws[512];
    int tid = threadIdx.x;
    if (tid < 32)
        cw[tid] = exp((double)(tid + 1) * log((double)(LL + 1) / 2.0) / 32.0);
    __syncthreads();
    for (int a = tid; a < LL; a += 256) {
        int t = 32;
        for (int j = 31; j >= 0; j--) if ((double)a <= cw[j]) t = j;
        g_tmin[a] = t;
    }
    for (int o = tid; o < 512; o += 256) {
        int h = o >> 6, n = o & 63;
        float s = 0.f;
        for (int d = 0; d < 64; d++)
            s += v_bias[h*64 + d] * w_pos[h*4096 + d*64 + n];
        vws[o] = s;
    }
    __syncthreads();
    if (tid < 16) {
        int h = tid >> 1, sg = tid & 1;
        float run = 0.f;
        float* dst = (sg ? g_Vsg : g_Vu) + h*33;
        dst[32] = 0.f;
        for (int t = 31; t >= 0; t--) { run += vws[h*64 + sg*32 + t]; dst[t] = run; }
    }
}

// -------- bias prep: qw suffix sums (Su/Ss) + uk, one block per (b,i) ------
__global__ __launch_bounds__(256)
void bias_prep_kernel(const float* __restrict__ w_pos,
                      const float* __restrict__ u_bias) {
    int row = blockIdx.x;
    int tid = threadIdx.x;
    __shared__ float qs[512], ks[512], qws[512];
    qs[tid]       = g_q[(size_t)row * HD + tid];
    qs[tid + 256] = g_q[(size_t)row * HD + tid + 256];
    ks[tid]       = g_k[(size_t)row * HD + tid];
    ks[tid + 256] = g_k[(size_t)row * HD + tid + 256];
    __syncthreads();
    for (int o = tid; o < 512; o += 256) {
        int h = o >> 6, n = o & 63;
        const float* wp = w_pos + h*4096 + n;
        float s = 0.f;
        #pragma unroll 8
        for (int d = 0; d < 64; d++) s += qs[h*64 + d] * wp[d << 6];
        qws[o] = s;
    }
    {
        int wid = tid >> 5, lane = tid & 31;
        float us = ks[wid*64 + lane]      * u_bias[wid*64 + lane]
                 + ks[wid*64 + 32 + lane] * u_bias[wid*64 + 32 + lane];
        #pragma unroll
        for (int off = 16; off; off >>= 1) us += __shfl_xor_sync(0xffffffffu, us, off);
        if (lane == 0) {
            int b = row >> 10, i = row & 1023;
            g_uk[(b*HH + wid) * LL + i] = us;
        }
    }
    __syncthreads();
    if (tid < 16) {
        int h = tid >> 1, sg = tid & 1;
        int b = row >> 10, i = row & 1023;
        float* dst = (sg ? g_Ss : g_Su) + (size_t)((b*HH + h) * LL + i) * 33;
        float run = 0.f;
        dst[32] = 0.f;
        for (int t = 31; t >= 0; t--) { run += qws[h*64 + sg*32 + t]; dst[t] = run; }
    }
}

// ---------------- flash attention via mma.sync, 128x128 tile ----------------
// 8 warps; warp w owns i-rows [w*16, w*16+16) x full 128 j.
#define A_QH  0
#define A_QL  16384
#define A_KH  32768
#define A_KL  49152
#define A_VTH 65536              // 64 rows x 272B (padded, 16B-aligned)
#define A_VTL 82944
#define A_SUS 100352             // 128*33 f32
#define A_SSS 117248
#define A_UKS 134144             // 128 f32
#define A_TMS 134656             // 1024 int
#define ATTN_SMEM 138752

__global__ __launch_bounds__(256, 1)
void attn_kernel() {
    extern __shared__ char smc[];
    const uint32_t sb = smem_u32(smc);
    float* Sus = (float*)(smc + A_SUS);
    float* Sss = (float*)(smc + A_SSS);
    float* uks = (float*)(smc + A_UKS);
    int*   tms = (int*)  (smc + A_TMS);

    const int b = blockIdx.z, h = blockIdx.y;
    const int i0 = blockIdx.x * 128;
    const int tid = threadIdx.x;
    const int wid = tid >> 5, lane = tid & 31;
    const int lr = lane & 15, lk8 = lane >> 4;

    // ---- prologue: Q tiles (bf16 hi/lo, pre-scaled) + bias tables ----
    {
        const __nv_bfloat16* qh = g_qh + (size_t)(b*LL + i0) * HD + h*64;
        const __nv_bfloat16* ql = g_ql + (size_t)(b*LL + i0) * HD + h*64;
        for (int x = tid; x < 1024; x += 256) {
            int row = x >> 3, seg = x & 7;
            uint32_t off = row * 128 + ((seg ^ (row & 7)) << 4);
            *(uint4*)(smc + A_QH + off) = *(const uint4*)(qh + (size_t)row*HD + seg*8);
            *(uint4*)(smc + A_QL + off) = *(const uint4*)(ql + (size_t)row*HD + seg*8);
        }
        const float* sub = g_Su + (size_t)((b*HH + h)*LL + i0) * 33;
        const float* ssb = g_Ss + (size_t)((b*HH + h)*LL + i0) * 33;
        const float* vu  = g_Vu  + h*33;
        const float* vsg = g_Vsg + h*33;
        for (int x = tid; x < 128*33; x += 256) {
            int t = x % 33;
            Sus[x] = (sub[x] + vu[t])  * 0.125f;
            Sss[x] = (ssb[x] + vsg[t]) * 0.125f;
        }
        for (int x = tid; x < LL; x += 256) tms[x] = g_tmin[x];
    }

    float m0 = -INFINITY, m1 = -INFINITY, l0 = 0.f, l1 = 0.f;
    float oacc[8][4];
    #pragma unroll
    for (int ot = 0; ot < 8; ot++)
        #pragma unroll
        for (int r = 0; r < 4; r++) oacc[ot][r] = 0.f;

    const int r0 = wid*16 + (lane >> 2);       // lane's first i-row (within tile)
    const int ig0 = i0 + r0, ig1 = ig0 + 8;
    const float* suR0 = Sus + r0*33;
    const float* ssR0 = Sss + r0*33;
    const float* suR1 = suR0 + 8*33;
    const float* ssR1 = ssR0 + 8*33;

    for (int j0 = 0; j0 < LL; j0 += 128) {
        __syncthreads();
        // K tiles
        {
            const __nv_bfloat16* kh = g_kh + (size_t)(b*LL + j0) * HD + h*64;
            const __nv_bfloat16* kl = g_kl + (size_t)(b*LL + j0) * HD + h*64;
            for (int x = tid; x < 1024; x += 256) {
                int row = x >> 3, seg = x & 7;
                uint32_t off = row * 128 + ((seg ^ (row & 7)) << 4);
                *(uint4*)(smc + A_KH + off) = *(const uint4*)(kh + (size_t)row*HD + seg*8);
                *(uint4*)(smc + A_KL + off) = *(const uint4*)(kl + (size_t)row*HD + seg*8);
            }
        }
        // V tiles, transposed to [dv][j] with 272B rows
        {
            const __nv_bfloat16* vh = g_vh + (size_t)(b*LL + j0) * HD + h*64;
            const __nv_bfloat16* vl = g_vl + (size_t)(b*LL + j0) * HD + h*64;
            for (int x = tid; x < 2048; x += 256) {
                int jj = x >> 4, c4 = x & 15;
                u64 hv = *(const u64*)(vh + (size_t)jj*HD + c4*4);
                u64 lv = *(const u64*)(vl + (size_t)jj*HD + c4*4);
                #pragma unroll
                for (int e = 0; e < 4; e++) {
                    int r = c4*4 + e;
                    *(unsigned short*)(smc + A_VTH + r*272 + jj*2) =
                        (unsigned short)(hv >> (16*e));
                    *(unsigned short*)(smc + A_VTL + r*272 + jj*2) =
                        (unsigned short)(lv >> (16*e));
                }
            }
        }
        if (tid < 128) uks[tid] = g_uk[(size_t)(b*HH + h)*LL + j0 + tid] * 0.125f;
        __syncthreads();

        // ---- S = Q K^T (3-term bf16 split) ----
        float sacc[16][4];
        #pragma unroll
        for (int nt = 0; nt < 16; nt++)
            #pragma unroll
            for (int r = 0; r < 4; r++) sacc[nt][r] = 0.f;

        #pragma unroll
        for (int ks = 0; ks < 4; ks++) {
            const int kseg = (ks << 1) + lk8;
            int arow = wid*16 + lr;
            uint32_t aoff = arow * 128 + ((kseg ^ (arow & 7)) << 4);
            uint32_t aH[4], aL[4];
            ldsm_x4(aH[0], aH[1], aH[2], aH[3], sb + A_QH + aoff);
            ldsm_x4(aL[0], aL[1], aL[2], aL[3], sb + A_QL + aoff);
            #pragma unroll
            for (int bt = 0; bt < 8; bt++) {
                int brow = bt*16 + lr;
                uint32_t boff = brow * 128 + ((kseg ^ (brow & 7)) << 4);
                uint32_t bH[4], bL[4];
                ldsm_x4(bH[0], bH[1], bH[2], bH[3], sb + A_KH + boff);
                ldsm_x4(bL[0], bL[1], bL[2], bL[3], sb + A_KL + boff);
                #pragma unroll
                for (int hi = 0; hi < 2; hi++) {
                    mma_bf16(sacc[bt*2 + hi], aH, bH[hi], bH[hi + 2]);
                    mma_bf16(sacc[bt*2 + hi], aH, bL[hi], bL[hi + 2]);
                    mma_bf16(sacc[bt*2 + hi], aL, bH[hi], bH[hi + 2]);
                }
            }
        }

        // ---- bias + online softmax (rows r0, r0+8) ----
        float mx0 = -INFINITY, mx1 = -INFINITY;
        #pragma unroll
        for (int nt = 0; nt < 16; nt++) {
            int cb = nt*8 + (lane & 3)*2;
            #pragma unroll
            for (int e = 0; e < 2; e++) {
                int j = j0 + cb + e;
                float ukv = uks[cb + e];
                {
                    int d = j - ig0;
                    int a = d < 0 ? -d : d;
                    int t = tms[a];
                    float sg = (float)((d > 0) - (d < 0));
                    sacc[nt][e] += suR0[t] + sg * ssR0[t] + ukv;
                    mx0 = fmaxf(mx0, sacc[nt][e]);
                }
                {
                    int d = j - ig1;
                    int a = d < 0 ? -d : d;
                    int t = tms[a];
                    float sg = (float)((d > 0) - (d < 0));
                    sacc[nt][2 + e] += suR1[t] + sg * ssR1[t] + ukv;
                    mx1 = fmaxf(mx1, sacc[nt][2 + e]);
                }
            }
        }
        mx0 = fmaxf(mx0, __shfl_xor_sync(0xffffffffu, mx0, 1));
        mx0 = fmaxf(mx0, __shfl_xor_sync(0xffffffffu, mx0, 2));
        mx1 = fmaxf(mx1, __shfl_xor_sync(0xffffffffu, mx1, 1));
        mx1 = fmaxf(mx1, __shfl_xor_sync(0xffffffffu, mx1, 2));
        float mn0 = fmaxf(m0, mx0), mn1 = fmaxf(m1, mx1);
        float al0 = __expf(m0 - mn0), al1 = __expf(m1 - mn1);
        m0 = mn0; m1 = mn1;
        float sum0 = 0.f, sum1 = 0.f;
        #pragma unroll
        for (int nt = 0; nt < 16; nt++) {
            #pragma unroll
            for (int e = 0; e < 2; e++) {
                sacc[nt][e]     = __expf(sacc[nt][e]     - mn0); sum0 += sacc[nt][e];
                sacc[nt][2 + e] = __expf(sacc[nt][2 + e] - mn1); sum1 += sacc[nt][2 + e];
            }
        }
        sum0 += __shfl_xor_sync(0xffffffffu, sum0, 1);
        sum0 += __shfl_xor_sync(0xffffffffu, sum0, 2);
        sum1 += __shfl_xor_sync(0xffffffffu, sum1, 1);
        sum1 += __shfl_xor_sync(0xffffffffu, sum1, 2);
        l0 = l0 * al0 + sum0;
        l1 = l1 * al1 + sum1;
        #pragma unroll
        for (int ot = 0; ot < 8; ot++) {
            oacc[ot][0] *= al0; oacc[ot][1] *= al0;
            oacc[ot][2] *= al1; oacc[ot][3] *= al1;
        }

        // ---- PV: O += P V (3-term split, P from registers) ----
        #pragma unroll
        for (int kt = 0; kt < 8; kt++) {
            uint32_t pH[4], pL[4];
            split2(sacc[2*kt][0],     sacc[2*kt][1],     pH[0], pL[0]);
            split2(sacc[2*kt][2],     sacc[2*kt][3],     pH[1], pL[1]);
            split2(sacc[2*kt + 1][0], sacc[2*kt + 1][1], pH[2], pL[2]);
            split2(sacc[2*kt + 1][2], sacc[2*kt + 1][3], pH[3], pL[3]);
            #pragma unroll
            for (int bt = 0; bt < 4; bt++) {
                int vrow = bt*16 + lr;
                uint32_t voff = vrow * 272 + (kt*2 + lk8) * 16;
                uint32_t vH[4], vL[4];
                ldsm_x4(vH[0], vH[1], vH[2], vH[3], sb + A_VTH + voff);
                ldsm_x4(vL[0], vL[1], vL[2], vL[3], sb + A_VTL + voff);
                #pragma unroll
                for (int hi = 0; hi < 2; hi++) {
                    mma_bf16(oacc[bt*2 + hi], pH, vH[hi], vH[hi + 2]);
                    mma_bf16(oacc[bt*2 + hi], pH, vL[hi], vL[hi + 2]);
                    mma_bf16(oacc[bt*2 + hi], pL, vH[hi], vH[hi + 2]);
                }
            }
        }
    }

    // ---- epilogue ----
    float inv0 = 1.f / l0, inv1 = 1.f / l1;
    #pragma unroll
    for (int ot = 0; ot < 8; ot++) {
        int col = ot*8 + (lane & 3)*2;
        *(float2*)(g_ao + (size_t)(b*LL + ig0) * HD + h*64 + col) =
            make_float2(oacc[ot][0]*inv0, oacc[ot][1]*inv0);
        *(float2*)(g_ao + (size_t)(b*LL + ig1) * HD + h*64 + col) =
            make_float2(oacc[ot][2]*inv1, oacc[ot][3]*inv1);
    }
}

// ---------------------------------------------------------------------------
extern "C" void kernel_launch(void* const* d_in, const int* in_sizes, int n_in,
                              void* d_out, int out_size) {
    const float* x  = (const float*)d_in[0];
    const float* Wq = (const float*)d_in[1];
    const float* Wk = (const float*)d_in[2];
    const float* Wv = (const float*)d_in[3];
    const float* Wo = (const float*)d_in[4];
    const float* bo = (const float*)d_in[5];
    const float* ub = (const float*)d_in[6];
    const float* vb = (const float*)d_in[7];
    const float* wp = (const float*)d_in[8];
    float* out = (float*)d_out;

    __nv_bfloat16 *pxh, *pxl, *pwh, *pwl, *pwoh, *pwol, *paoh, *paol;
    __nv_bfloat16 *pqh, *pql, *pkh, *pkl, *pvh, *pvl;
    float *pao, *pq, *pk, *pv;
    cudaGetSymbolAddress((void**)&pxh,  g_xhi);
    cudaGetSymbolAddress((void**)&pxl,  g_xlo);
    cudaGetSymbolAddress((void**)&pwh,  g_whi);
    cudaGetSymbolAddress((void**)&pwl,  g_wlo);
    cudaGetSymbolAddress((void**)&pwoh, g_wohi);
    cudaGetSymbolAddress((void**)&pwol, g_wolo);
    cudaGetSymbolAddress((void**)&paoh, g_aohi);
    cudaGetSymbolAddress((void**)&paol, g_aolo);
    cudaGetSymbolAddress((void**)&pao,  g_ao);
    cudaGetSymbolAddress((void**)&pq,   g_q);
    cudaGetSymbolAddress((void**)&pk,   g_k);
    cudaGetSymbolAddress((void**)&pv,   g_v);
    cudaGetSymbolAddress((void**)&pqh,  g_qh);
    cudaGetSymbolAddress((void**)&pql,  g_ql);
    cudaGetSymbolAddress((void**)&pkh,  g_kh);
    cudaGetSymbolAddress((void**)&pkl,  g_kl);
    cudaGetSymbolAddress((void**)&pvh,  g_vh);
    cudaGetSymbolAddress((void**)&pvl,  g_vl);

    prep_kernel<<<1, 256>>>(vb, wp);

    conv_kernel<<<1536, 256>>>(x,  pxh, pxl, BB*LL*DMM/4, 1.f);
    conv_kernel<<<384, 256>>>(Wq, pwh,            pwl,            HD*DMM/4, 1.f);
    conv_kernel<<<384, 256>>>(Wk, pwh + HD*DMM,   pwl + HD*DMM,   HD*DMM/4, 1.f);
    conv_kernel<<<384, 256>>>(Wv, pwh + 2*HD*DMM, pwl + 2*HD*DMM, HD*DMM/4, 1.f);
    conv_kernel<<<384, 256>>>(Wo, pwoh, pwol, DMM*HD/4, 1.f);

    const int GEMM_SMEM = 65536;
    cudaFuncSetAttribute(qkv_mma_kernel, cudaFuncAttributeMaxDynamicSharedMemorySize, GEMM_SMEM);
    cudaFuncSetAttribute(out_mma_kernel, cudaFuncAttributeMaxDynamicSharedMemorySize, GEMM_SMEM);

    qkv_mma_kernel<<<dim3(16, 12), 256, GEMM_SMEM>>>();

    // bf16 splits of q (pre-scaled), k, v for the attention MMAs
    conv_kernel<<<1024, 256>>>(pq, pqh, pql, BB*LL*HD/4, 0.125f);
    conv_kernel<<<1024, 256>>>(pk, pkh, pkl, BB*LL*HD/4, 1.f);
    conv_kernel<<<1024, 256>>>(pv, pvh, pvl, BB*LL*HD/4, 1.f);

    bias_prep_kernel<<<BB*LL, 256>>>(wp, ub);

    cudaFuncSetAttribute(attn_kernel, cudaFuncAttributeMaxDynamicSharedMemorySize, ATTN_SMEM);
    attn_kernel<<<dim3(LL/128, HH, BB), 256, ATTN_SMEM>>>();

    conv_kernel<<<1024, 256>>>(pao, paoh, paol, BB*LL*HD/4, 1.f);
    out_mma_kernel<<<dim3(16, 6), 256, GEMM_SMEM>>>(bo, out);
}

// round 10
// speedup vs baseline: 3.6538x; 1.0071x over previous
#include <cuda_runtime.h>
#include <cuda_bf16.h>
#include <math.h>
#include <stdint.h>

#define BB 2
#define LL 1024
#define HH 8
#define DD 64
#define DMM 768
#define HD 512

typedef unsigned long long u64;

// ---------------- mma.sync helpers (baseline ISA, works on sm_103) ---------
__device__ __forceinline__ uint32_t smem_u32(const void* p) {
    uint32_t a;
    asm("{ .reg .u64 t; cvta.to.shared.u64 t, %1; cvt.u32.u64 %0, t; }"
        : "=r"(a) : "l"(p));
    return a;
}
__device__ __forceinline__ void ldsm_x4(uint32_t& r0, uint32_t& r1,
                                        uint32_t& r2, uint32_t& r3, uint32_t addr) {
    asm volatile("ldmatrix.sync.aligned.m8n8.x4.shared.b16 {%0,%1,%2,%3}, [%4];"
                 : "=r"(r0), "=r"(r1), "=r"(r2), "=r"(r3) : "r"(addr));
}
__device__ __forceinline__ void mma_bf16(float* c, const uint32_t* a,
                                         uint32_t b0, uint32_t b1) {
    asm volatile(
        "mma.sync.aligned.m16n8k16.row.col.f32.bf16.bf16.f32 "
        "{%0,%1,%2,%3}, {%4,%5,%6,%7}, {%8,%9}, {%0,%1,%2,%3};"
        : "+f"(c[0]), "+f"(c[1]), "+f"(c[2]), "+f"(c[3])
        : "r"(a[0]), "r"(a[1]), "r"(a[2]), "r"(a[3]), "r"(b0), "r"(b1));
}
// split two floats into packed-bf16 hi and lo words
__device__ __forceinline__ void split2(float a, float b, uint32_t& hi, uint32_t& lo) {
    __nv_bfloat16 ha = __float2bfloat16(a), hb = __float2bfloat16(b);
    __nv_bfloat16 la = __float2bfloat16(a - __bfloat162float(ha));
    __nv_bfloat16 lb = __float2bfloat16(b - __bfloat162float(hb));
    hi = (uint32_t)*(unsigned short*)&ha | ((uint32_t)*(unsigned short*)&hb << 16);
    lo = (uint32_t)*(unsigned short*)&la | ((uint32_t)*(unsigned short*)&lb << 16);
}

// ---------------- scratch (static device globals; no allocs) ----------------
__device__ float g_q [BB*LL*HD];
__device__ float g_k [BB*LL*HD];
__device__ float g_Su[BB*HH*LL*33];
__device__ float g_Ss[BB*HH*LL*33];
__device__ float g_uk[BB*HH*LL];
__device__ float g_Vu[HH*33];
__device__ float g_Vsg[HH*33];
__device__ int   g_tmin[LL];

// bf16-split operand buffers
__device__ __align__(16) __nv_bfloat16 g_xhi [BB*LL*DMM];
__device__ __align__(16) __nv_bfloat16 g_xlo [BB*LL*DMM];
__device__ __align__(16) __nv_bfloat16 g_whi [3*HD*DMM];
__device__ __align__(16) __nv_bfloat16 g_wlo [3*HD*DMM];
__device__ __align__(16) __nv_bfloat16 g_wohi[DMM*HD];
__device__ __align__(16) __nv_bfloat16 g_wolo[DMM*HD];
__device__ __align__(16) __nv_bfloat16 g_aohi[BB*LL*HD];
__device__ __align__(16) __nv_bfloat16 g_aolo[BB*LL*HD];
__device__ __align__(16) __nv_bfloat16 g_qh[BB*LL*HD];
__device__ __align__(16) __nv_bfloat16 g_ql[BB*LL*HD];
__device__ __align__(16) __nv_bfloat16 g_kh[BB*LL*HD];
__device__ __align__(16) __nv_bfloat16 g_kl[BB*LL*HD];
__device__ __align__(16) __nv_bfloat16 g_vh[BB*LL*HD];
__device__ __align__(16) __nv_bfloat16 g_vl[BB*LL*HD];

// ---------------- fused f32 -> bf16 hi/lo split for x + 4 weights ----------
// blocks: [0,1536) x | [1536,1920) Wq | [1920,2304) Wk | [2304,2688) Wv | [2688,3072) Wo
__global__ __launch_bounds__(256)
void conv_all_kernel(const float* __restrict__ x,  const float* __restrict__ Wq,
                     const float* __restrict__ Wk, const float* __restrict__ Wv,
                     const float* __restrict__ Wo) {
    int bi = blockIdx.x;
    const float* src;
    __nv_bfloat16 *hi, *lo;
    int lb;
    if (bi < 1536)      { src = x;  hi = g_xhi;            lo = g_xlo;            lb = bi; }
    else if (bi < 1920) { src = Wq; hi = g_whi;            lo = g_wlo;            lb = bi - 1536; }
    else if (bi < 2304) { src = Wk; hi = g_whi + HD*DMM;   lo = g_wlo + HD*DMM;   lb = bi - 1920; }
    else if (bi < 2688) { src = Wv; hi = g_whi + 2*HD*DMM; lo = g_wlo + 2*HD*DMM; lb = bi - 2304; }
    else                { src = Wo; hi = g_wohi;           lo = g_wolo;           lb = bi - 2688; }
    int i = lb * 256 + threadIdx.x;
    float4 v = ((const float4*)src)[i];
    uint32_t h0, l0, h1, l1;
    split2(v.x, v.y, h0, l0);
    split2(v.z, v.w, h1, l1);
    ((uint32_t*)hi)[2*i]     = h0;
    ((uint32_t*)hi)[2*i + 1] = h1;
    ((uint32_t*)lo)[2*i]     = l0;
    ((uint32_t*)lo)[2*i + 1] = l1;
}

// ---------------- mma.sync bf16-split GEMM body ----------------------------
// C[128,128] tile = A[128,Kt] @ B[128,Kt]^T  (3-term bf16 split, fp32 acc)
// Optionally writes fp32 C and/or bf16 hi/lo split of C*sc.
__device__ __forceinline__ void gemm_mma_body(
    const __nv_bfloat16* __restrict__ Ahi, const __nv_bfloat16* __restrict__ Alo,
    const __nv_bfloat16* __restrict__ Bhi, const __nv_bfloat16* __restrict__ Blo,
    int Kt, float* __restrict__ Cout, __nv_bfloat16* __restrict__ Chi,
    __nv_bfloat16* __restrict__ Clo, float sc, int Cstride,
    const float* __restrict__ bias)
{
    extern __shared__ char gsm[];
    const uint32_t sb = smem_u32(gsm);
    const int tid = threadIdx.x;
    const int wid = tid >> 5, lane = tid & 31;
    const int wm = wid >> 2, wn = wid & 3;

    float acc[4][4][4];
    #pragma unroll
    for (int mt = 0; mt < 4; mt++)
        #pragma unroll
        for (int nt = 0; nt < 4; nt++)
            #pragma unroll
            for (int r = 0; r < 4; r++) acc[mt][nt][r] = 0.f;

    const int lr  = lane & 15;
    const int lk8 = lane >> 4;

    const __nv_bfloat16* srcs[4] = {Ahi, Alo, Bhi, Blo};
    const int NCH = Kt >> 6;

    for (int ch = 0; ch < NCH; ch++) {
        const int k0 = ch << 6;
        #pragma unroll
        for (int t = 0; t < 4; t++) {
            const __nv_bfloat16* s = srcs[t] + k0;
            char* dp = gsm + t * 16384;
            #pragma unroll
            for (int u = 0; u < 4; u++) {
                int e = tid + u * 256;
                int row = e >> 3, seg = e & 7;
                uint4 v = *(const uint4*)(s + (size_t)row * Kt + seg * 8);
                *(uint4*)(dp + row * 128 + ((seg ^ (row & 7)) << 4)) = v;
            }
        }
        __syncthreads();

        #pragma unroll
        for (int ks = 0; ks < 4; ks++) {
            const int kseg = (ks << 1) + lk8;
            uint32_t ah[4][4], al[4][4];
            #pragma unroll
            for (int mt = 0; mt < 4; mt++) {
                int row = wm * 64 + mt * 16 + lr;
                uint32_t off = row * 128 + (((kseg ^ (row & 7))) << 4);
                ldsm_x4(ah[mt][0], ah[mt][1], ah[mt][2], ah[mt][3], sb + off);
                ldsm_x4(al[mt][0], al[mt][1], al[mt][2], al[mt][3], sb + 16384 + off);
            }
            uint32_t bh[2][4], bl[2][4];
            #pragma unroll
            for (int bt = 0; bt < 2; bt++) {
                int row = wn * 32 + bt * 16 + lr;
                uint32_t off = row * 128 + (((kseg ^ (row & 7))) << 4);
                ldsm_x4(bh[bt][0], bh[bt][1], bh[bt][2], bh[bt][3], sb + 32768 + off);
                ldsm_x4(bl[bt][0], bl[bt][1], bl[bt][2], bl[bt][3], sb + 49152 + off);
            }
            #pragma unroll
            for (int mt = 0; mt < 4; mt++) {
                #pragma unroll
                for (int nt = 0; nt < 4; nt++) {
                    int bt = nt >> 1, hi = nt & 1;
                    mma_bf16(acc[mt][nt], ah[mt], bh[bt][hi], bh[bt][hi + 2]);
                    mma_bf16(acc[mt][nt], ah[mt], bl[bt][hi], bl[bt][hi + 2]);
                    mma_bf16(acc[mt][nt], al[mt], bh[bt][hi], bh[bt][hi + 2]);
                }
            }
        }
        __syncthreads();
    }

    const int er = lane >> 2, ec = (lane & 3) << 1;
    #pragma unroll
    for (int mt = 0; mt < 4; mt++) {
        #pragma unroll
        for (int nt = 0; nt < 4; nt++) {
            int m = wm * 64 + mt * 16 + er;
            int n = wn * 32 + nt * 8 + ec;
            float b0 = 0.f, b1 = 0.f;
            if (bias) { b0 = bias[n]; b1 = bias[n + 1]; }
            float v0 = acc[mt][nt][0] + b0, v1 = acc[mt][nt][1] + b1;
            float v2 = acc[mt][nt][2] + b0, v3 = acc[mt][nt][3] + b1;
            if (Cout) {
                *(float2*)(Cout + (size_t)m * Cstride + n)       = make_float2(v0, v1);
                *(float2*)(Cout + (size_t)(m + 8) * Cstride + n) = make_float2(v2, v3);
            }
            if (Chi) {
                uint32_t h0, l0, h1, l1;
                split2(v0 * sc, v1 * sc, h0, l0);
                split2(v2 * sc, v3 * sc, h1, l1);
                *(uint32_t*)(Chi + (size_t)m * Cstride + n)       = h0;
                *(uint32_t*)(Clo + (size_t)m * Cstride + n)       = l0;
                *(uint32_t*)(Chi + (size_t)(m + 8) * Cstride + n) = h1;
                *(uint32_t*)(Clo + (size_t)(m + 8) * Cstride + n) = l1;
            }
        }
    }
}

// QKV: grid (16 M-tiles, 12 N-tiles over concatenated 1536)
__global__ __launch_bounds__(256)
void qkv_mma_kernel() {
    int m0 = blockIdx.x * 128;
    int nglob = blockIdx.y * 128;
    int sel = nglob >> 9, ncol = nglob & 511;
    size_t co = (size_t)m0 * HD + ncol;
    float* fbase = sel == 0 ? g_q : (sel == 1 ? g_k : nullptr);  // v fp32 unused
    __nv_bfloat16* hb = (sel == 0 ? g_qh : (sel == 1 ? g_kh : g_vh)) + co;
    __nv_bfloat16* lb = (sel == 0 ? g_ql : (sel == 1 ? g_kl : g_vl)) + co;
    float sc = sel == 0 ? 0.125f : 1.f;
    gemm_mma_body(g_xhi + (size_t)m0 * DMM, g_xlo + (size_t)m0 * DMM,
                  g_whi + (size_t)nglob * DMM, g_wlo + (size_t)nglob * DMM,
                  DMM, fbase ? fbase + co : nullptr, hb, lb, sc, HD, nullptr);
}

// out: grid (16 M-tiles, 6 N-tiles over 768)
__global__ __launch_bounds__(256)
void out_mma_kernel(const float* __restrict__ bo, float* __restrict__ out) {
    int m0 = blockIdx.x * 128;
    int n0 = blockIdx.y * 128;
    gemm_mma_body(g_aohi + (size_t)m0 * HD, g_aolo + (size_t)m0 * HD,
                  g_wohi + (size_t)n0 * HD, g_wolo + (size_t)n0 * HD,
                  HD, out + (size_t)m0 * DMM + n0, nullptr, nullptr, 1.f,
                  DMM, bo + n0);
}

// ---------------- prep: tmin LUT + per-head Vu/Vsg suffix tables -----------
__global__ void prep_kernel(const float* __restrict__ v_bias,
                            const float* __restrict__ w_pos) {
    __shared__ double cw[32];
    __shared__ float  vws[512];
    int tid = threadIdx.x;
    if (tid < 32)
        cw[tid] = exp((double)(tid + 1) * log((double)(LL + 1) / 2.0) / 32.0);
    __syncthreads();
    for (int a = tid; a < LL; a += 256) {
        int t = 32;
        for (int j = 31; j >= 0; j--) if ((double)a <= cw[j]) t = j;
        g_tmin[a] = t;
    }
    for (int o = tid; o < 512; o += 256) {
        int h = o >> 6, n = o & 63;
        float s = 0.f;
        for (int d = 0; d < 64; d++)
            s += v_bias[h*64 + d] * w_pos[h*4096 + d*64 + n];
        vws[o] = s;
    }
    __syncthreads();
    if (tid < 16) {
        int h = tid >> 1, sg = tid & 1;
        float run = 0.f;
        float* dst = (sg ? g_Vsg : g_Vu) + h*33;
        dst[32] = 0.f;
        for (int t = 31; t >= 0; t--) { run += vws[h*64 + sg*32 + t]; dst[t] = run; }
    }
}

// -------- bias prep v2: one block per (b, h, 128 i-rows); w_pos in smem ----
__global__ __launch_bounds__(256)
void bias_prep2_kernel(const float* __restrict__ w_pos,
                       const float* __restrict__ u_bias) {
    extern __shared__ float bs[];
    float* wps = bs;            // [64][64]
    float* qs  = bs + 4096;     // [128][64]
    float* qws = bs + 12288;    // [128][64]
    const int b = blockIdx.z, h = blockIdx.y;
    const int i0 = blockIdx.x * 128;
    const int tid = threadIdx.x;

    for (int o = tid; o < 1024; o += 256)
        *(float4*)(wps + o*4) = *(const float4*)(w_pos + h*4096 + o*4);
    const float* qg = g_q + (size_t)(b*LL + i0) * HD + h*64;
    for (int o = tid; o < 2048; o += 256) {
        int r = o >> 4, c4 = o & 15;
        *(float4*)(qs + r*64 + c4*4) = *(const float4*)(qg + (size_t)r*HD + c4*4);
    }
    __syncthreads();

    for (int o = tid; o < 8192; o += 256) {
        int r = o >> 6, n = o & 63;
        const float* qr = qs + r*64;
        float s = 0.f;
        #pragma unroll 16
        for (int d = 0; d < 64; d++) s += qr[d] * wps[d*64 + n];
        qws[o] = s;
    }
    if (tid < 128) {
        const float* kg = g_k + (size_t)(b*LL + i0 + tid) * HD + h*64;
        float s = 0.f;
        #pragma unroll
        for (int c4 = 0; c4 < 16; c4++) {
            float4 kv = *(const float4*)(kg + c4*4);
            float4 uv = *(const float4*)(u_bias + h*64 + c4*4);
            s += kv.x*uv.x + kv.y*uv.y + kv.z*uv.z + kv.w*uv.w;
        }
        g_uk[(size_t)(b*HH + h)*LL + i0 + tid] = s;
    }
    __syncthreads();
    {
        int r = tid >> 1, sg = tid & 1;
        float* dst = (sg ? g_Ss : g_Su) + (size_t)((b*HH + h)*LL + i0 + r) * 33;
        float run = 0.f;
        dst[32] = 0.f;
        const float* src = qws + r*64 + sg*32;
        #pragma unroll
        for (int t = 31; t >= 0; t--) { run += src[t]; dst[t] = run; }
    }
}

// ---------------- flash attention via mma.sync, 128x128 tile ----------------
#define A_QH  0
#define A_QL  16384
#define A_KH  32768
#define A_KL  49152
#define A_VTH 65536              // 64 rows x 272B (padded, 16B-aligned)
#define A_VTL 82944
#define A_SUS 100352             // 128*33 f32
#define A_SSS 117248
#define A_UKS 134144             // 128 f32
#define A_TMS 134656             // 1024 int
#define ATTN_SMEM 138752

__global__ __launch_bounds__(256, 1)
void attn_kernel() {
    extern __shared__ char smc[];
    const uint32_t sb = smem_u32(smc);
    float* Sus = (float*)(smc + A_SUS);
    float* Sss = (float*)(smc + A_SSS);
    float* uks = (float*)(smc + A_UKS);
    int*   tms = (int*)  (smc + A_TMS);

    const int b = blockIdx.z, h = blockIdx.y;
    const int i0 = blockIdx.x * 128;
    const int tid = threadIdx.x;
    const int wid = tid >> 5, lane = tid & 31;
    const int lr = lane & 15, lk8 = lane >> 4;

    {
        const __nv_bfloat16* qh = g_qh + (size_t)(b*LL + i0) * HD + h*64;
        const __nv_bfloat16* ql = g_ql + (size_t)(b*LL + i0) * HD + h*64;
        for (int x = tid; x < 1024; x += 256) {
            int row = x >> 3, seg = x & 7;
            uint32_t off = row * 128 + ((seg ^ (row & 7)) << 4);
            *(uint4*)(smc + A_QH + off) = *(const uint4*)(qh + (size_t)row*HD + seg*8);
            *(uint4*)(smc + A_QL + off) = *(const uint4*)(ql + (size_t)row*HD + seg*8);
        }
        const float* sub = g_Su + (size_t)((b*HH + h)*LL + i0) * 33;
        const float* ssb = g_Ss + (size_t)((b*HH + h)*LL + i0) * 33;
        const float* vu  = g_Vu  + h*33;
        const float* vsg = g_Vsg + h*33;
        for (int x = tid; x < 128*33; x += 256) {
            int t = x % 33;
            Sus[x] = (sub[x] + vu[t])  * 0.125f;
            Sss[x] = (ssb[x] + vsg[t]) * 0.125f;
        }
        for (int x = tid; x < LL; x += 256) tms[x] = g_tmin[x];
    }

    float m0 = -INFINITY, m1 = -INFINITY, l0 = 0.f, l1 = 0.f;
    float oacc[8][4];
    #pragma unroll
    for (int ot = 0; ot < 8; ot++)
        #pragma unroll
        for (int r = 0; r < 4; r++) oacc[ot][r] = 0.f;

    const int r0 = wid*16 + (lane >> 2);
    const int ig0 = i0 + r0, ig1 = ig0 + 8;
    const float* suR0 = Sus + r0*33;
    const float* ssR0 = Sss + r0*33;
    const float* suR1 = suR0 + 8*33;
    const float* ssR1 = ssR0 + 8*33;

    for (int j0 = 0; j0 < LL; j0 += 128) {
        __syncthreads();
        {
            const __nv_bfloat16* kh = g_kh + (size_t)(b*LL + j0) * HD + h*64;
            const __nv_bfloat16* kl = g_kl + (size_t)(b*LL + j0) * HD + h*64;
            for (int x = tid; x < 1024; x += 256) {
                int row = x >> 3, seg = x & 7;
                uint32_t off = row * 128 + ((seg ^ (row & 7)) << 4);
                *(uint4*)(smc + A_KH + off) = *(const uint4*)(kh + (size_t)row*HD + seg*8);
                *(uint4*)(smc + A_KL + off) = *(const uint4*)(kl + (size_t)row*HD + seg*8);
            }
        }
        {
            const __nv_bfloat16* vh = g_vh + (size_t)(b*LL + j0) * HD + h*64;
            const __nv_bfloat16* vl = g_vl + (size_t)(b*LL + j0) * HD + h*64;
            for (int x = tid; x < 2048; x += 256) {
                int jj = x >> 4, c4 = x & 15;
                u64 hv = *(const u64*)(vh + (size_t)jj*HD + c4*4);
                u64 lv = *(const u64*)(vl + (size_t)jj*HD + c4*4);
                #pragma unroll
                for (int e = 0; e < 4; e++) {
                    int r = c4*4 + e;
                    *(unsigned short*)(smc + A_VTH + r*272 + jj*2) =
                        (unsigned short)(hv >> (16*e));
                    *(unsigned short*)(smc + A_VTL + r*272 + jj*2) =
                        (unsigned short)(lv >> (16*e));
                }
            }
        }
        if (tid < 128) uks[tid] = g_uk[(size_t)(b*HH + h)*LL + j0 + tid] * 0.125f;
        __syncthreads();

        float sacc[16][4];
        #pragma unroll
        for (int nt = 0; nt < 16; nt++)
            #pragma unroll
            for (int r = 0; r < 4; r++) sacc[nt][r] = 0.f;

        #pragma unroll
        for (int ks = 0; ks < 4; ks++) {
            const int kseg = (ks << 1) + lk8;
            int arow = wid*16 + lr;
            uint32_t aoff = arow * 128 + ((kseg ^ (arow & 7)) << 4);
            uint32_t aH[4], aL[4];
            ldsm_x4(aH[0], aH[1], aH[2], aH[3], sb + A_QH + aoff);
            ldsm_x4(aL[0], aL[1], aL[2], aL[3], sb + A_QL + aoff);
            #pragma unroll
            for (int bt = 0; bt < 8; bt++) {
                int brow = bt*16 + lr;
                uint32_t boff = brow * 128 + ((kseg ^ (brow & 7)) << 4);
                uint32_t bH[4], bL[4];
                ldsm_x4(bH[0], bH[1], bH[2], bH[3], sb + A_KH + boff);
                ldsm_x4(bL[0], bL[1], bL[2], bL[3], sb + A_KL + boff);
                #pragma unroll
                for (int hi = 0; hi < 2; hi++) {
                    mma_bf16(sacc[bt*2 + hi], aH, bH[hi], bH[hi + 2]);
                    mma_bf16(sacc[bt*2 + hi], aH, bL[hi], bL[hi + 2]);
                    mma_bf16(sacc[bt*2 + hi], aL, bH[hi], bH[hi + 2]);
                }
            }
        }

        float mx0 = -INFINITY, mx1 = -INFINITY;
        #pragma unroll
        for (int nt = 0; nt < 16; nt++) {
            int cb = nt*8 + (lane & 3)*2;
            #pragma unroll
            for (int e = 0; e < 2; e++) {
                int j = j0 + cb + e;
                float ukv = uks[cb + e];
                {
                    int d = j - ig0;
                    int a = d < 0 ? -d : d;
                    int t = tms[a];
                    float sg = (float)((d > 0) - (d < 0));
                    sacc[nt][e] += suR0[t] + sg * ssR0[t] + ukv;
                    mx0 = fmaxf(mx0, sacc[nt][e]);
                }
                {
                    int d = j - ig1;
                    int a = d < 0 ? -d : d;
                    int t = tms[a];
                    float sg = (float)((d > 0) - (d < 0));
                    sacc[nt][2 + e] += suR1[t] + sg * ssR1[t] + ukv;
                    mx1 = fmaxf(mx1, sacc[nt][2 + e]);
                }
            }
        }
        mx0 = fmaxf(mx0, __shfl_xor_sync(0xffffffffu, mx0, 1));
        mx0 = fmaxf(mx0, __shfl_xor_sync(0xffffffffu, mx0, 2));
        mx1 = fmaxf(mx1, __shfl_xor_sync(0xffffffffu, mx1, 1));
        mx1 = fmaxf(mx1, __shfl_xor_sync(0xffffffffu, mx1, 2));
        float mn0 = fmaxf(m0, mx0), mn1 = fmaxf(m1, mx1);
        float al0 = __expf(m0 - mn0), al1 = __expf(m1 - mn1);
        m0 = mn0; m1 = mn1;
        float sum0 = 0.f, sum1 = 0.f;
        #pragma unroll
        for (int nt = 0; nt < 16; nt++) {
            #pragma unroll
            for (int e = 0; e < 2; e++) {
                sacc[nt][e]     = __expf(sacc[nt][e]     - mn0); sum0 += sacc[nt][e];
                sacc[nt][2 + e] = __expf(sacc[nt][2 + e] - mn1); sum1 += sacc[nt][2 + e];
            }
        }
        sum0 += __shfl_xor_sync(0xffffffffu, sum0, 1);
        sum0 += __shfl_xor_sync(0xffffffffu, sum0, 2);
        sum1 += __shfl_xor_sync(0xffffffffu, sum1, 1);
        sum1 += __shfl_xor_sync(0xffffffffu, sum1, 2);
        l0 = l0 * al0 + sum0;
        l1 = l1 * al1 + sum1;
        #pragma unroll
        for (int ot = 0; ot < 8; ot++) {
            oacc[ot][0] *= al0; oacc[ot][1] *= al0;
            oacc[ot][2] *= al1; oacc[ot][3] *= al1;
        }

        #pragma unroll
        for (int kt = 0; kt < 8; kt++) {
            uint32_t pH[4], pL[4];
            split2(sacc[2*kt][0],     sacc[2*kt][1],     pH[0], pL[0]);
            split2(sacc[2*kt][2],     sacc[2*kt][3],     pH[1], pL[1]);
            split2(sacc[2*kt + 1][0], sacc[2*kt + 1][1], pH[2], pL[2]);
            split2(sacc[2*kt + 1][2], sacc[2*kt + 1][3], pH[3], pL[3]);
            #pragma unroll
            for (int bt = 0; bt < 4; bt++) {
                int vrow = bt*16 + lr;
                uint32_t voff = vrow * 272 + (kt*2 + lk8) * 16;
                uint32_t vH[4], vL[4];
                ldsm_x4(vH[0], vH[1], vH[2], vH[3], sb + A_VTH + voff);
                ldsm_x4(vL[0], vL[1], vL[2], vL[3], sb + A_VTL + voff);
                #pragma unroll
                for (int hi = 0; hi < 2; hi++) {
                    mma_bf16(oacc[bt*2 + hi], pH, vH[hi], vH[hi + 2]);
                    mma_bf16(oacc[bt*2 + hi], pH, vL[hi], vL[hi + 2]);
                    mma_bf16(oacc[bt*2 + hi], pL, vH[hi], vH[hi + 2]);
                }
            }
        }
    }

    // ---- epilogue: write bf16 hi/lo split of O directly ----
    float inv0 = 1.f / l0, inv1 = 1.f / l1;
    #pragma unroll
    for (int ot = 0; ot < 8; ot++) {
        int col = ot*8 + (lane & 3)*2;
        size_t p0 = (size_t)(b*LL + ig0) * HD + h*64 + col;
        size_t p1 = (size_t)(b*LL + ig1) * HD + h*64 + col;
        uint32_t h0, lo0, h1, lo1;
        split2(oacc[ot][0]*inv0, oacc[ot][1]*inv0, h0, lo0);
        split2(oacc[ot][2]*inv1, oacc[ot][3]*inv1, h1, lo1);
        *(uint32_t*)(g_aohi + p0) = h0;
        *(uint32_t*)(g_aolo + p0) = lo0;
        *(uint32_t*)(g_aohi + p1) = h1;
        *(uint32_t*)(g_aolo + p1) = lo1;
    }
}

// ---------------------------------------------------------------------------
extern "C" void kernel_launch(void* const* d_in, const int* in_sizes, int n_in,
                              void* d_out, int out_size) {
    const float* x  = (const float*)d_in[0];
    const float* Wq = (const float*)d_in[1];
    const float* Wk = (const float*)d_in[2];
    const float* Wv = (const float*)d_in[3];
    const float* Wo = (const float*)d_in[4];
    const float* bo = (const float*)d_in[5];
    const float* ub = (const float*)d_in[6];
    const float* vb = (const float*)d_in[7];
    const float* wp = (const float*)d_in[8];
    float* out = (float*)d_out;

    prep_kernel<<<1, 256>>>(vb, wp);

    conv_all_kernel<<<3072, 256>>>(x, Wq, Wk, Wv, Wo);

    const int GEMM_SMEM = 65536;
    cudaFuncSetAttribute(qkv_mma_kernel, cudaFuncAttributeMaxDynamicSharedMemorySize, GEMM_SMEM);
    cudaFuncSetAttribute(out_mma_kernel, cudaFuncAttributeMaxDynamicSharedMemorySize, GEMM_SMEM);

    qkv_mma_kernel<<<dim3(16, 12), 256, GEMM_SMEM>>>();

    const int BP_SMEM = 81920;
    cudaFuncSetAttribute(bias_prep2_kernel, cudaFuncAttributeMaxDynamicSharedMemorySize, BP_SMEM);
    bias_prep2_kernel<<<dim3(8, HH, BB), 256, BP_SMEM>>>(wp, ub);

    cudaFuncSetAttribute(attn_kernel, cudaFuncAttributeMaxDynamicSharedMemorySize, ATTN_SMEM);
    attn_kernel<<<dim3(LL/128, HH, BB), 256, ATTN_SMEM>>>();

    out_mma_kernel<<<dim3(16, 6), 256, GEMM_SMEM>>>(bo, out);
}

// round 13
// speedup vs baseline: 4.0004x; 1.0949x over previous
#include <cuda_runtime.h>
#include <cuda_bf16.h>
#include <math.h>
#include <stdint.h>

#define BB 2
#define LL 1024
#define HH 8
#define DD 64
#define DMM 768
#define HD 512

typedef unsigned long long u64;

// ---------------- mma.sync helpers (baseline ISA, works on sm_103) ---------
__device__ __forceinline__ uint32_t smem_u32(const void* p) {
    uint32_t a;
    asm("{ .reg .u64 t; cvta.to.shared.u64 t, %1; cvt.u32.u64 %0, t; }"
        : "=r"(a) : "l"(p));
    return a;
}
__device__ __forceinline__ void ldsm_x4(uint32_t& r0, uint32_t& r1,
                                        uint32_t& r2, uint32_t& r3, uint32_t addr) {
    asm volatile("ldmatrix.sync.aligned.m8n8.x4.shared.b16 {%0,%1,%2,%3}, [%4];"
                 : "=r"(r0), "=r"(r1), "=r"(r2), "=r"(r3) : "r"(addr));
}
__device__ __forceinline__ void mma_bf16(float* c, const uint32_t* a,
                                         uint32_t b0, uint32_t b1) {
    asm volatile(
        "mma.sync.aligned.m16n8k16.row.col.f32.bf16.bf16.f32 "
        "{%0,%1,%2,%3}, {%4,%5,%6,%7}, {%8,%9}, {%0,%1,%2,%3};"
        : "+f"(c[0]), "+f"(c[1]), "+f"(c[2]), "+f"(c[3])
        : "r"(a[0]), "r"(a[1]), "r"(a[2]), "r"(a[3]), "r"(b0), "r"(b1));
}
__device__ __forceinline__ void split2(float a, float b, uint32_t& hi, uint32_t& lo) {
    __nv_bfloat16 ha = __float2bfloat16(a), hb = __float2bfloat16(b);
    __nv_bfloat16 la = __float2bfloat16(a - __bfloat162float(ha));
    __nv_bfloat16 lb = __float2bfloat16(b - __bfloat162float(hb));
    hi = (uint32_t)*(unsigned short*)&ha | ((uint32_t)*(unsigned short*)&hb << 16);
    lo = (uint32_t)*(unsigned short*)&la | ((uint32_t)*(unsigned short*)&lb << 16);
}

// ---------------- scratch (static device globals; no allocs) ----------------
__device__ float g_Su[BB*HH*LL*33];
__device__ float g_Ss[BB*HH*LL*33];
__device__ float g_uk[BB*HH*LL];
__device__ float g_Vu[HH*33];      // pre-scaled x0.125
__device__ float g_Vsg[HH*33];     // pre-scaled x0.125
__device__ int   g_tmin[LL];

__device__ __align__(16) __nv_bfloat16 g_xhi [BB*LL*DMM];
__device__ __align__(16) __nv_bfloat16 g_xlo [BB*LL*DMM];
__device__ __align__(16) __nv_bfloat16 g_whi [3*HD*DMM];
__device__ __align__(16) __nv_bfloat16 g_wlo [3*HD*DMM];
__device__ __align__(16) __nv_bfloat16 g_wohi[DMM*HD];
__device__ __align__(16) __nv_bfloat16 g_wolo[DMM*HD];
__device__ __align__(16) __nv_bfloat16 g_aohi[BB*LL*HD];
__device__ __align__(16) __nv_bfloat16 g_aolo[BB*LL*HD];
__device__ __align__(16) __nv_bfloat16 g_qh[BB*LL*HD];   // q x0.125 split
__device__ __align__(16) __nv_bfloat16 g_ql[BB*LL*HD];
__device__ __align__(16) __nv_bfloat16 g_kh[BB*LL*HD];
__device__ __align__(16) __nv_bfloat16 g_kl[BB*LL*HD];
__device__ __align__(16) __nv_bfloat16 g_vh[BB*LL*HD];
__device__ __align__(16) __nv_bfloat16 g_vl[BB*LL*HD];
__device__ __align__(16) __nv_bfloat16 g_wth[HH*64*64];  // w_pos^T [h][n][d] split
__device__ __align__(16) __nv_bfloat16 g_wtl[HH*64*64];
__device__ __align__(16) __nv_bfloat16 g_vth[BB*HH*64*LL]; // V^T [b][h][dv][j]
__device__ __align__(16) __nv_bfloat16 g_vtl[BB*HH*64*LL];

// ---------------- fused f32 -> bf16 hi/lo split for x + 4 weights ----------
__global__ __launch_bounds__(256)
void conv_all_kernel(const float* __restrict__ x,  const float* __restrict__ Wq,
                     const float* __restrict__ Wk, const float* __restrict__ Wv,
                     const float* __restrict__ Wo) {
    int bi = blockIdx.x;
    const float* src;
    __nv_bfloat16 *hi, *lo;
    int lb;
    if (bi < 1536)      { src = x;  hi = g_xhi;            lo = g_xlo;            lb = bi; }
    else if (bi < 1920) { src = Wq; hi = g_whi;            lo = g_wlo;            lb = bi - 1536; }
    else if (bi < 2304) { src = Wk; hi = g_whi + HD*DMM;   lo = g_wlo + HD*DMM;   lb = bi - 1920; }
    else if (bi < 2688) { src = Wv; hi = g_whi + 2*HD*DMM; lo = g_wlo + 2*HD*DMM; lb = bi - 2304; }
    else                { src = Wo; hi = g_wohi;           lo = g_wolo;           lb = bi - 2688; }
    int i = lb * 256 + threadIdx.x;
    float4 v = ((const float4*)src)[i];
    uint32_t h0, l0, h1, l1;
    split2(v.x, v.y, h0, l0);
    split2(v.z, v.w, h1, l1);
    ((uint32_t*)hi)[2*i]     = h0;
    ((uint32_t*)hi)[2*i + 1] = h1;
    ((uint32_t*)lo)[2*i]     = l0;
    ((uint32_t*)lo)[2*i + 1] = l1;
}

// ---------------- mma.sync bf16-split GEMM body ----------------------------
__device__ __forceinline__ void gemm_mma_body(
    const __nv_bfloat16* __restrict__ Ahi, const __nv_bfloat16* __restrict__ Alo,
    const __nv_bfloat16* __restrict__ Bhi, const __nv_bfloat16* __restrict__ Blo,
    int Kt, float* __restrict__ Cout, __nv_bfloat16* __restrict__ Chi,
    __nv_bfloat16* __restrict__ Clo, float sc, int Cstride,
    const float* __restrict__ bias)
{
    extern __shared__ char gsm[];
    const uint32_t sb = smem_u32(gsm);
    const int tid = threadIdx.x;
    const int wid = tid >> 5, lane = tid & 31;
    const int wm = wid >> 2, wn = wid & 3;

    float acc[4][4][4];
    #pragma unroll
    for (int mt = 0; mt < 4; mt++)
        #pragma unroll
        for (int nt = 0; nt < 4; nt++)
            #pragma unroll
            for (int r = 0; r < 4; r++) acc[mt][nt][r] = 0.f;

    const int lr  = lane & 15;
    const int lk8 = lane >> 4;

    const __nv_bfloat16* srcs[4] = {Ahi, Alo, Bhi, Blo};
    const int NCH = Kt >> 6;

    for (int ch = 0; ch < NCH; ch++) {
        const int k0 = ch << 6;
        #pragma unroll
        for (int t = 0; t < 4; t++) {
            const __nv_bfloat16* s = srcs[t] + k0;
            char* dp = gsm + t * 16384;
            #pragma unroll
            for (int u = 0; u < 4; u++) {
                int e = tid + u * 256;
                int row = e >> 3, seg = e & 7;
                uint4 v = *(const uint4*)(s + (size_t)row * Kt + seg * 8);
                *(uint4*)(dp + row * 128 + ((seg ^ (row & 7)) << 4)) = v;
            }
        }
        __syncthreads();

        #pragma unroll
        for (int ks = 0; ks < 4; ks++) {
            const int kseg = (ks << 1) + lk8;
            uint32_t ah[4][4], al[4][4];
            #pragma unroll
            for (int mt = 0; mt < 4; mt++) {
                int row = wm * 64 + mt * 16 + lr;
                uint32_t off = row * 128 + (((kseg ^ (row & 7))) << 4);
                ldsm_x4(ah[mt][0], ah[mt][1], ah[mt][2], ah[mt][3], sb + off);
                ldsm_x4(al[mt][0], al[mt][1], al[mt][2], al[mt][3], sb + 16384 + off);
            }
            uint32_t bh[2][4], bl[2][4];
            #pragma unroll
            for (int bt = 0; bt < 2; bt++) {
                int row = wn * 32 + bt * 16 + lr;
                uint32_t off = row * 128 + (((kseg ^ (row & 7))) << 4);
                ldsm_x4(bh[bt][0], bh[bt][1], bh[bt][2], bh[bt][3], sb + 32768 + off);
                ldsm_x4(bl[bt][0], bl[bt][1], bl[bt][2], bl[bt][3], sb + 49152 + off);
            }
            #pragma unroll
            for (int mt = 0; mt < 4; mt++) {
                #pragma unroll
                for (int nt = 0; nt < 4; nt++) {
                    int bt = nt >> 1, hi = nt & 1;
                    mma_bf16(acc[mt][nt], ah[mt], bh[bt][hi], bh[bt][hi + 2]);
                    mma_bf16(acc[mt][nt], ah[mt], bl[bt][hi], bl[bt][hi + 2]);
                    mma_bf16(acc[mt][nt], al[mt], bh[bt][hi], bh[bt][hi + 2]);
                }
            }
        }
        __syncthreads();
    }

    const int er = lane >> 2, ec = (lane & 3) << 1;
    #pragma unroll
    for (int mt = 0; mt < 4; mt++) {
        #pragma unroll
        for (int nt = 0; nt < 4; nt++) {
            int m = wm * 64 + mt * 16 + er;
            int n = wn * 32 + nt * 8 + ec;
            float b0 = 0.f, b1 = 0.f;
            if (bias) { b0 = bias[n]; b1 = bias[n + 1]; }
            float v0 = acc[mt][nt][0] + b0, v1 = acc[mt][nt][1] + b1;
            float v2 = acc[mt][nt][2] + b0, v3 = acc[mt][nt][3] + b1;
            if (Cout) {
                *(float2*)(Cout + (size_t)m * Cstride + n)       = make_float2(v0, v1);
                *(float2*)(Cout + (size_t)(m + 8) * Cstride + n) = make_float2(v2, v3);
            }
            if (Chi) {
                uint32_t h0, l0, h1, l1;
                split2(v0 * sc, v1 * sc, h0, l0);
                split2(v2 * sc, v3 * sc, h1, l1);
                *(uint32_t*)(Chi + (size_t)m * Cstride + n)       = h0;
                *(uint32_t*)(Clo + (size_t)m * Cstride + n)       = l0;
                *(uint32_t*)(Chi + (size_t)(m + 8) * Cstride + n) = h1;
                *(uint32_t*)(Clo + (size_t)(m + 8) * Cstride + n) = l1;
            }
        }
    }
}

__global__ __launch_bounds__(256)
void qkv_mma_kernel() {
    int m0 = blockIdx.x * 128;
    int nglob = blockIdx.y * 128;
    int sel = nglob >> 9, ncol = nglob & 511;
    size_t co = (size_t)m0 * HD + ncol;
    __nv_bfloat16* hb = (sel == 0 ? g_qh : (sel == 1 ? g_kh : g_vh)) + co;
    __nv_bfloat16* lb = (sel == 0 ? g_ql : (sel == 1 ? g_kl : g_vl)) + co;
    float sc = sel == 0 ? 0.125f : 1.f;
    gemm_mma_body(g_xhi + (size_t)m0 * DMM, g_xlo + (size_t)m0 * DMM,
                  g_whi + (size_t)nglob * DMM, g_wlo + (size_t)nglob * DMM,
                  DMM, nullptr, hb, lb, sc, HD, nullptr);
}

__global__ __launch_bounds__(256)
void out_mma_kernel(const float* __restrict__ bo, float* __restrict__ out) {
    int m0 = blockIdx.x * 128;
    int n0 = blockIdx.y * 128;
    gemm_mma_body(g_aohi + (size_t)m0 * HD, g_aolo + (size_t)m0 * HD,
                  g_wohi + (size_t)n0 * HD, g_wolo + (size_t)n0 * HD,
                  HD, out + (size_t)m0 * DMM + n0, nullptr, nullptr, 1.f,
                  DMM, bo + n0);
}

// ---------------- prep: tmin LUT + per-head Vu/Vsg (x0.125) ----------------
__global__ void prep_kernel(const float* __restrict__ v_bias,
                            const float* __restrict__ w_pos) {
    __shared__ double cw[32];
    __shared__ float  vws[512];
    int tid = threadIdx.x;
    if (tid < 32)
        cw[tid] = exp((double)(tid + 1) * log((double)(LL + 1) / 2.0) / 32.0);
    __syncthreads();
    for (int a = tid; a < LL; a += 256) {
        int t = 32;
        for (int j = 31; j >= 0; j--) if ((double)a <= cw[j]) t = j;
        g_tmin[a] = t;
    }
    for (int o = tid; o < 512; o += 256) {
        int h = o >> 6, n = o & 63;
        float s = 0.f;
        for (int d = 0; d < 64; d++)
            s += v_bias[h*64 + d] * w_pos[h*4096 + d*64 + n];
        vws[o] = s;
    }
    __syncthreads();
    if (tid < 16) {
        int h = tid >> 1, sg = tid & 1;
        float run = 0.f;
        float* dst = (sg ? g_Vsg : g_Vu) + h*33;
        dst[32] = 0.f;
        for (int t = 31; t >= 0; t--) {
            run += vws[h*64 + sg*32 + t];
            dst[t] = run * 0.125f;
        }
    }
}

// w_pos^T bf16 split: [h][d][n] -> [h][n][d]
__global__ __launch_bounds__(256)
void wtrans_kernel(const float* __restrict__ w_pos) {
    int idx = blockIdx.x * 256 + threadIdx.x;       // 32768
    int h = idx >> 12, rem = idx & 4095;
    int n = rem >> 6, d = rem & 63;
    float v = w_pos[h*4096 + d*64 + n];
    __nv_bfloat16 hi = __float2bfloat16(v);
    __nv_bfloat16 lo = __float2bfloat16(v - __bfloat162float(hi));
    g_wth[idx] = hi;
    g_wtl[idx] = lo;
}

// uk[b,h,j] = u . (kh+kl)
__global__ __launch_bounds__(256)
void uk_kernel(const float* __restrict__ u_bias) {
    int idx = blockIdx.x * 256 + threadIdx.x;       // 16384
    int b = idx >> 13, rem = idx & 8191;
    int h = rem >> 10, j = rem & 1023;
    const __nv_bfloat16* kh = g_kh + (size_t)(b*LL + j) * HD + h*64;
    const __nv_bfloat16* kl = g_kl + (size_t)(b*LL + j) * HD + h*64;
    const float* u = u_bias + h*64;
    float s = 0.f;
    #pragma unroll
    for (int d = 0; d < 64; d++)
        s += (__bfloat162float(kh[d]) + __bfloat162float(kl[d])) * u[d];
    g_uk[idx] = s;
}

// V^T: [b][j][h][dv] -> [b][h][dv][j] (hi & lo)
__global__ __launch_bounds__(256)
void vtrans_kernel() {
    __shared__ unsigned short sh[128*72], sl[128*72];
    const int b = blockIdx.z, h = blockIdx.y;
    const int j0 = blockIdx.x * 128;
    const int tid = threadIdx.x;
    for (int x = tid; x < 1024; x += 256) {
        int j = x >> 3, seg = x & 7;
        size_t src = (size_t)(b*LL + j0 + j) * HD + h*64 + seg*8;
        *(uint4*)(sh + j*72 + seg*8) = *(const uint4*)(g_vh + src);
        *(uint4*)(sl + j*72 + seg*8) = *(const uint4*)(g_vl + src);
    }
    __syncthreads();
    for (int x = tid; x < 1024; x += 256) {
        int dv = x >> 4, jw = x & 15;
        unsigned short oh[8], ol[8];
        #pragma unroll
        for (int e = 0; e < 8; e++) {
            oh[e] = sh[(jw*8 + e)*72 + dv];
            ol[e] = sl[(jw*8 + e)*72 + dv];
        }
        size_t dst = ((size_t)(b*HH + h)*64 + dv)*LL + j0 + jw*8;
        *(uint4*)(g_vth + dst) = *(uint4*)oh;
        *(uint4*)(g_vtl + dst) = *(uint4*)ol;
    }
}

// -------- qw via mma + suffix sums: one block per (b, h, 128 i-rows) -------
// FIXED smem layout: Q tiles are 16 KB each (128 rows x 128 B)
#define QW_QH 0
#define QW_QL 16384
#define QW_WH 32768
#define QW_WL 40960
#define QW_QW 49152          // fp32 [128][65]
#define QW_SMEM (49152 + 128*65*4)

__global__ __launch_bounds__(256)
void qw_suffix_kernel() {
    extern __shared__ char qsm[];
    const uint32_t sb = smem_u32(qsm);
    float* qws = (float*)(qsm + QW_QW);
    const int b = blockIdx.z, h = blockIdx.y;
    const int i0 = blockIdx.x * 128;
    const int tid = threadIdx.x;
    const int wid = tid >> 5, lane = tid & 31;
    const int lr = lane & 15, lk8 = lane >> 4;

    {
        const __nv_bfloat16* qh = g_qh + (size_t)(b*LL + i0) * HD + h*64;
        const __nv_bfloat16* ql = g_ql + (size_t)(b*LL + i0) * HD + h*64;
        for (int x = tid; x < 1024; x += 256) {
            int row = x >> 3, seg = x & 7;
            uint32_t off = row * 128 + ((seg ^ (row & 7)) << 4);
            *(uint4*)(qsm + QW_QH + off) = *(const uint4*)(qh + (size_t)row*HD + seg*8);
            *(uint4*)(qsm + QW_QL + off) = *(const uint4*)(ql + (size_t)row*HD + seg*8);
        }
        const __nv_bfloat16* wth = g_wth + h*4096;
        const __nv_bfloat16* wtl = g_wtl + h*4096;
        for (int x = tid; x < 512; x += 256) {
            int row = x >> 3, seg = x & 7;
            uint32_t off = row * 128 + ((seg ^ (row & 7)) << 4);
            *(uint4*)(qsm + QW_WH + off) = *(const uint4*)(wth + row*64 + seg*8);
            *(uint4*)(qsm + QW_WL + off) = *(const uint4*)(wtl + row*64 + seg*8);
        }
    }
    __syncthreads();

    float sacc[8][4];
    #pragma unroll
    for (int p = 0; p < 8; p++)
        #pragma unroll
        for (int r = 0; r < 4; r++) sacc[p][r] = 0.f;

    #pragma unroll
    for (int ks = 0; ks < 4; ks++) {
        const int kseg = (ks << 1) + lk8;
        int arow = wid*16 + lr;
        uint32_t aoff = arow * 128 + ((kseg ^ (arow & 7)) << 4);
        uint32_t aH[4], aL[4];
        ldsm_x4(aH[0], aH[1], aH[2], aH[3], sb + QW_QH + aoff);
        ldsm_x4(aL[0], aL[1], aL[2], aL[3], sb + QW_QL + aoff);
        #pragma unroll
        for (int bt = 0; bt < 4; bt++) {
            int brow = bt*16 + lr;
            uint32_t boff = brow * 128 + ((kseg ^ (brow & 7)) << 4);
            uint32_t bH[4], bL[4];
            ldsm_x4(bH[0], bH[1], bH[2], bH[3], sb + QW_WH + boff);
            ldsm_x4(bL[0], bL[1], bL[2], bL[3], sb + QW_WL + boff);
            #pragma unroll
            for (int hi = 0; hi < 2; hi++) {
                mma_bf16(sacc[bt*2 + hi], aH, bH[hi], bH[hi + 2]);
                mma_bf16(sacc[bt*2 + hi], aH, bL[hi], bL[hi + 2]);
                mma_bf16(sacc[bt*2 + hi], aL, bH[hi], bH[hi + 2]);
            }
        }
    }

    const int er = lane >> 2, ec = (lane & 3) << 1;
    #pragma unroll
    for (int p = 0; p < 8; p++) {
        int r0 = wid*16 + er, n = p*8 + ec;
        qws[r0*65 + n]       = sacc[p][0];
        qws[r0*65 + n + 1]   = sacc[p][1];
        qws[(r0+8)*65 + n]     = sacc[p][2];
        qws[(r0+8)*65 + n + 1] = sacc[p][3];
    }
    __syncthreads();

    {
        int r = tid >> 1, sg = tid & 1;
        float* dst = (sg ? g_Ss : g_Su) + (size_t)((b*HH + h)*LL + i0 + r) * 33;
        float run = 0.f;
        dst[32] = 0.f;
        const float* src = qws + r*65 + sg*32;
        #pragma unroll
        for (int t = 31; t >= 0; t--) { run += src[t]; dst[t] = run; }
    }
}

// ---------------- flash attention via mma.sync, 128x128 tile ----------------
#define A_QH  0
#define A_QL  16384
#define A_KH  32768
#define A_KL  49152
#define A_VTH 65536              // 64 rows x 256B (V^T, swizzled)
#define A_VTL 81920
#define A_SUS 98304              // 128*33 f32
#define A_SSS 115200
#define A_UKS 132096             // 128 f32
#define A_TMS 132608             // 1024 int
#define ATTN_SMEM 136704

__global__ __launch_bounds__(256, 1)
void attn_kernel() {
    extern __shared__ char smc[];
    const uint32_t sb = smem_u32(smc);
    float* Sus = (float*)(smc + A_SUS);
    float* Sss = (float*)(smc + A_SSS);
    float* uks = (float*)(smc + A_UKS);
    int*   tms = (int*)  (smc + A_TMS);

    const int b = blockIdx.z, h = blockIdx.y;
    const int i0 = blockIdx.x * 128;
    const int tid = threadIdx.x;
    const int wid = tid >> 5, lane = tid & 31;
    const int lr = lane & 15, lk8 = lane >> 4;

    {
        const __nv_bfloat16* qh = g_qh + (size_t)(b*LL + i0) * HD + h*64;
        const __nv_bfloat16* ql = g_ql + (size_t)(b*LL + i0) * HD + h*64;
        for (int x = tid; x < 1024; x += 256) {
            int row = x >> 3, seg = x & 7;
            uint32_t off = row * 128 + ((seg ^ (row & 7)) << 4);
            *(uint4*)(smc + A_QH + off) = *(const uint4*)(qh + (size_t)row*HD + seg*8);
            *(uint4*)(smc + A_QL + off) = *(const uint4*)(ql + (size_t)row*HD + seg*8);
        }
        const float* sub = g_Su + (size_t)((b*HH + h)*LL + i0) * 33;
        const float* ssb = g_Ss + (size_t)((b*HH + h)*LL + i0) * 33;
        const float* vu  = g_Vu  + h*33;
        const float* vsg = g_Vsg + h*33;
        for (int x = tid; x < 128*33; x += 256) {
            int t = x % 33;
            Sus[x] = sub[x] + vu[t];
            Sss[x] = ssb[x] + vsg[t];
        }
        for (int x = tid; x < LL; x += 256) tms[x] = g_tmin[x];
    }

    float m0 = -INFINITY, m1 = -INFINITY, l0 = 0.f, l1 = 0.f;
    float oacc[8][4];
    #pragma unroll
    for (int ot = 0; ot < 8; ot++)
        #pragma unroll
        for (int r = 0; r < 4; r++) oacc[ot][r] = 0.f;

    const int r0 = wid*16 + (lane >> 2);
    const int ig0 = i0 + r0, ig1 = ig0 + 8;
    const float* suR0 = Sus + r0*33;
    const float* ssR0 = Sss + r0*33;
    const float* suR1 = suR0 + 8*33;
    const float* ssR1 = ssR0 + 8*33;

    for (int j0 = 0; j0 < LL; j0 += 128) {
        __syncthreads();
        {
            const __nv_bfloat16* kh = g_kh + (size_t)(b*LL + j0) * HD + h*64;
            const __nv_bfloat16* kl = g_kl + (size_t)(b*LL + j0) * HD + h*64;
            for (int x = tid; x < 1024; x += 256) {
                int row = x >> 3, seg = x & 7;
                uint32_t off = row * 128 + ((seg ^ (row & 7)) << 4);
                *(uint4*)(smc + A_KH + off) = *(const uint4*)(kh + (size_t)row*HD + seg*8);
                *(uint4*)(smc + A_KL + off) = *(const uint4*)(kl + (size_t)row*HD + seg*8);
            }
            const __nv_bfloat16* vth = g_vth + ((size_t)(b*HH + h)*64)*LL + j0;
            const __nv_bfloat16* vtl = g_vtl + ((size_t)(b*HH + h)*64)*LL + j0;
            for (int x = tid; x < 1024; x += 256) {
                int row = x >> 4, seg = x & 15;
                uint32_t off = row * 256 + ((seg ^ (row & 15)) << 4);
                *(uint4*)(smc + A_VTH + off) = *(const uint4*)(vth + (size_t)row*LL + seg*8);
                *(uint4*)(smc + A_VTL + off) = *(const uint4*)(vtl + (size_t)row*LL + seg*8);
            }
        }
        if (tid < 128) uks[tid] = g_uk[(size_t)(b*HH + h)*LL + j0 + tid] * 0.125f;
        __syncthreads();

        float sacc[16][4];
        #pragma unroll
        for (int nt = 0; nt < 16; nt++)
            #pragma unroll
            for (int r = 0; r < 4; r++) sacc[nt][r] = 0.f;

        #pragma unroll
        for (int ks = 0; ks < 4; ks++) {
            const int kseg = (ks << 1) + lk8;
            int arow = wid*16 + lr;
            uint32_t aoff = arow * 128 + ((kseg ^ (arow & 7)) << 4);
            uint32_t aH[4], aL[4];
            ldsm_x4(aH[0], aH[1], aH[2], aH[3], sb + A_QH + aoff);
            ldsm_x4(aL[0], aL[1], aL[2], aL[3], sb + A_QL + aoff);
            #pragma unroll
            for (int bt = 0; bt < 8; bt++) {
                int brow = bt*16 + lr;
                uint32_t boff = brow * 128 + ((kseg ^ (brow & 7)) << 4);
                uint32_t bH[4], bL[4];
                ldsm_x4(bH[0], bH[1], bH[2], bH[3], sb + A_KH + boff);
                ldsm_x4(bL[0], bL[1], bL[2], bL[3], sb + A_KL + boff);
                #pragma unroll
                for (int hi = 0; hi < 2; hi++) {
                    mma_bf16(sacc[bt*2 + hi], aH, bH[hi], bH[hi + 2]);
                    mma_bf16(sacc[bt*2 + hi], aH, bL[hi], bL[hi + 2]);
                    mma_bf16(sacc[bt*2 + hi], aL, bH[hi], bH[hi + 2]);
                }
            }
        }

        float mx0 = -INFINITY, mx1 = -INFINITY;
        #pragma unroll
        for (int nt = 0; nt < 16; nt++) {
            int cb = nt*8 + (lane & 3)*2;
            #pragma unroll
            for (int e = 0; e < 2; e++) {
                int j = j0 + cb + e;
                float ukv = uks[cb + e];
                {
                    int d = j - ig0;
                    int a = d < 0 ? -d : d;
                    int t = tms[a];
                    float sg = (float)((d > 0) - (d < 0));
                    sacc[nt][e] += suR0[t] + sg * ssR0[t] + ukv;
                    mx0 = fmaxf(mx0, sacc[nt][e]);
                }
                {
                    int d = j - ig1;
                    int a = d < 0 ? -d : d;
                    int t = tms[a];
                    float sg = (float)((d > 0) - (d < 0));
                    sacc[nt][2 + e] += suR1[t] + sg * ssR1[t] + ukv;
                    mx1 = fmaxf(mx1, sacc[nt][2 + e]);
                }
            }
        }
        mx0 = fmaxf(mx0, __shfl_xor_sync(0xffffffffu, mx0, 1));
        mx0 = fmaxf(mx0, __shfl_xor_sync(0xffffffffu, mx0, 2));
        mx1 = fmaxf(mx1, __shfl_xor_sync(0xffffffffu, mx1, 1));
        mx1 = fmaxf(mx1, __shfl_xor_sync(0xffffffffu, mx1, 2));
        float mn0 = fmaxf(m0, mx0), mn1 = fmaxf(m1, mx1);
        float al0 = __expf(m0 - mn0), al1 = __expf(m1 - mn1);
        m0 = mn0; m1 = mn1;
        float sum0 = 0.f, sum1 = 0.f;
        #pragma unroll
        for (int nt = 0; nt < 16; nt++) {
            #pragma unroll
            for (int e = 0; e < 2; e++) {
                sacc[nt][e]     = __expf(sacc[nt][e]     - mn0); sum0 += sacc[nt][e];
                sacc[nt][2 + e] = __expf(sacc[nt][2 + e] - mn1); sum1 += sacc[nt][2 + e];
            }
        }
        sum0 += __shfl_xor_sync(0xffffffffu, sum0, 1);
        sum0 += __shfl_xor_sync(0xffffffffu, sum0, 2);
        sum1 += __shfl_xor_sync(0xffffffffu, sum1, 1);
        sum1 += __shfl_xor_sync(0xffffffffu, sum1, 2);
        l0 = l0 * al0 + sum0;
        l1 = l1 * al1 + sum1;
        #pragma unroll
        for (int ot = 0; ot < 8; ot++) {
            oacc[ot][0] *= al0; oacc[ot][1] *= al0;
            oacc[ot][2] *= al1; oacc[ot][3] *= al1;
        }

        #pragma unroll
        for (int kt = 0; kt < 8; kt++) {
            uint32_t pH[4], pL[4];
            split2(sacc[2*kt][0],     sacc[2*kt][1],     pH[0], pL[0]);
            split2(sacc[2*kt][2],     sacc[2*kt][3],     pH[1], pL[1]);
            split2(sacc[2*kt + 1][0], sacc[2*kt + 1][1], pH[2], pL[2]);
            split2(sacc[2*kt + 1][2], sacc[2*kt + 1][3], pH[3], pL[3]);
            #pragma unroll
            for (int bt = 0; bt < 4; bt++) {
                int vrow = bt*16 + lr;
                uint32_t voff = vrow * 256 + (((kt*2 + lk8) ^ (vrow & 15)) << 4);
                uint32_t vH[4], vL[4];
                ldsm_x4(vH[0], vH[1], vH[2], vH[3], sb + A_VTH + voff);
                ldsm_x4(vL[0], vL[1], vL[2], vL[3], sb + A_VTL + voff);
                #pragma unroll
                for (int hi = 0; hi < 2; hi++) {
                    mma_bf16(oacc[bt*2 + hi], pH, vH[hi], vH[hi + 2]);
                    mma_bf16(oacc[bt*2 + hi], pH, vL[hi], vL[hi + 2]);
                    mma_bf16(oacc[bt*2 + hi], pL, vH[hi], vH[hi + 2]);
                }
            }
        }
    }

    float inv0 = 1.f / l0, inv1 = 1.f / l1;
    #pragma unroll
    for (int ot = 0; ot < 8; ot++) {
        int col = ot*8 + (lane & 3)*2;
        size_t p0 = (size_t)(b*LL + ig0) * HD + h*64 + col;
        size_t p1 = (size_t)(b*LL + ig1) * HD + h*64 + col;
        uint32_t h0, lo0, h1, lo1;
        split2(oacc[ot][0]*inv0, oacc[ot][1]*inv0, h0, lo0);
        split2(oacc[ot][2]*inv1, oacc[ot][3]*inv1, h1, lo1);
        *(uint32_t*)(g_aohi + p0) = h0;
        *(uint32_t*)(g_aolo + p0) = lo0;
        *(uint32_t*)(g_aohi + p1) = h1;
        *(uint32_t*)(g_aolo + p1) = lo1;
    }
}

// ---------------------------------------------------------------------------
extern "C" void kernel_launch(void* const* d_in, const int* in_sizes, int n_in,
                              void* d_out, int out_size) {
    const float* x  = (const float*)d_in[0];
    const float* Wq = (const float*)d_in[1];
    const float* Wk = (const float*)d_in[2];
    const float* Wv = (const float*)d_in[3];
    const float* Wo = (const float*)d_in[4];
    const float* bo = (const float*)d_in[5];
    const float* ub = (const float*)d_in[6];
    const float* vb = (const float*)d_in[7];
    const float* wp = (const float*)d_in[8];
    float* out = (float*)d_out;

    prep_kernel<<<1, 256>>>(vb, wp);
    wtrans_kernel<<<128, 256>>>(wp);
    conv_all_kernel<<<3072, 256>>>(x, Wq, Wk, Wv, Wo);

    const int GEMM_SMEM = 65536;
    cudaFuncSetAttribute(qkv_mma_kernel, cudaFuncAttributeMaxDynamicSharedMemorySize, GEMM_SMEM);
    cudaFuncSetAttribute(out_mma_kernel, cudaFuncAttributeMaxDynamicSharedMemorySize, GEMM_SMEM);

    qkv_mma_kernel<<<dim3(16, 12), 256, GEMM_SMEM>>>();

    vtrans_kernel<<<dim3(8, HH, BB), 256>>>();
    uk_kernel<<<64, 256>>>(ub);

    cudaFuncSetAttribute(qw_suffix_kernel, cudaFuncAttributeMaxDynamicSharedMemorySize, QW_SMEM);
    qw_suffix_kernel<<<dim3(8, HH, BB), 256, QW_SMEM>>>();

    cudaFuncSetAttribute(attn_kernel, cudaFuncAttributeMaxDynamicSharedMemorySize, ATTN_SMEM);
    attn_kernel<<<dim3(LL/128, HH, BB), 256, ATTN_SMEM>>>();

    out_mma_kernel<<<dim3(16, 6), 256, GEMM_SMEM>>>(bo, out);
}

// round 14
// speedup vs baseline: 4.2249x; 1.0561x over previous
#include <cuda_runtime.h>
#include <cuda_bf16.h>
#include <math.h>
#include <stdint.h>

#define BB 2
#define LL 1024
#define HH 8
#define DD 64
#define DMM 768
#define HD 512

typedef unsigned long long u64;

// ---------------- mma.sync / cp.async helpers (baseline ISA) ---------------
__device__ __forceinline__ uint32_t smem_u32(const void* p) {
    uint32_t a;
    asm("{ .reg .u64 t; cvta.to.shared.u64 t, %1; cvt.u32.u64 %0, t; }"
        : "=r"(a) : "l"(p));
    return a;
}
__device__ __forceinline__ void ldsm_x4(uint32_t& r0, uint32_t& r1,
                                        uint32_t& r2, uint32_t& r3, uint32_t addr) {
    asm volatile("ldmatrix.sync.aligned.m8n8.x4.shared.b16 {%0,%1,%2,%3}, [%4];"
                 : "=r"(r0), "=r"(r1), "=r"(r2), "=r"(r3) : "r"(addr));
}
__device__ __forceinline__ void mma_bf16(float* c, const uint32_t* a,
                                         uint32_t b0, uint32_t b1) {
    asm volatile(
        "mma.sync.aligned.m16n8k16.row.col.f32.bf16.bf16.f32 "
        "{%0,%1,%2,%3}, {%4,%5,%6,%7}, {%8,%9}, {%0,%1,%2,%3};"
        : "+f"(c[0]), "+f"(c[1]), "+f"(c[2]), "+f"(c[3])
        : "r"(a[0]), "r"(a[1]), "r"(a[2]), "r"(a[3]), "r"(b0), "r"(b1));
}
__device__ __forceinline__ void split2(float a, float b, uint32_t& hi, uint32_t& lo) {
    __nv_bfloat16 ha = __float2bfloat16(a), hb = __float2bfloat16(b);
    __nv_bfloat16 la = __float2bfloat16(a - __bfloat162float(ha));
    __nv_bfloat16 lb = __float2bfloat16(b - __bfloat162float(hb));
    hi = (uint32_t)*(unsigned short*)&ha | ((uint32_t)*(unsigned short*)&hb << 16);
    lo = (uint32_t)*(unsigned short*)&la | ((uint32_t)*(unsigned short*)&lb << 16);
}
__device__ __forceinline__ void cp16(uint32_t dst, const void* src) {
    asm volatile("cp.async.cg.shared.global [%0], [%1], 16;" :: "r"(dst), "l"(src));
}
#define CP_COMMIT() asm volatile("cp.async.commit_group;" ::: "memory")
#define CP_WAIT1()  asm volatile("cp.async.wait_group 1;" ::: "memory")
#define CP_WAIT0()  asm volatile("cp.async.wait_group 0;" ::: "memory")
// SW64 swizzle for 64B rows
#define SW64(o) ((o) ^ (((o) >> 3) & 0x30))

// ---------------- scratch (static device globals; no allocs) ----------------
__device__ float g_Su[BB*HH*LL*33];
__device__ float g_Ss[BB*HH*LL*33];
__device__ float g_uk[BB*HH*LL];
__device__ float g_Vu[HH*33];      // pre-scaled x0.125
__device__ float g_Vsg[HH*33];     // pre-scaled x0.125
__device__ int   g_tmin[LL];

__device__ __align__(16) __nv_bfloat16 g_xhi [BB*LL*DMM];
__device__ __align__(16) __nv_bfloat16 g_xlo [BB*LL*DMM];
__device__ __align__(16) __nv_bfloat16 g_whi [3*HD*DMM];
__device__ __align__(16) __nv_bfloat16 g_wlo [3*HD*DMM];
__device__ __align__(16) __nv_bfloat16 g_wohi[DMM*HD];
__device__ __align__(16) __nv_bfloat16 g_wolo[DMM*HD];
__device__ __align__(16) __nv_bfloat16 g_aohi[BB*LL*HD];
__device__ __align__(16) __nv_bfloat16 g_aolo[BB*LL*HD];
__device__ __align__(16) __nv_bfloat16 g_qh[BB*LL*HD];   // q x0.125 split
__device__ __align__(16) __nv_bfloat16 g_ql[BB*LL*HD];
__device__ __align__(16) __nv_bfloat16 g_kh[BB*LL*HD];
__device__ __align__(16) __nv_bfloat16 g_kl[BB*LL*HD];
__device__ __align__(16) __nv_bfloat16 g_vh[BB*LL*HD];
__device__ __align__(16) __nv_bfloat16 g_vl[BB*LL*HD];
__device__ __align__(16) __nv_bfloat16 g_wth[HH*64*64];  // w_pos^T [h][n][d] split
__device__ __align__(16) __nv_bfloat16 g_wtl[HH*64*64];
__device__ __align__(16) __nv_bfloat16 g_vth[BB*HH*64*LL]; // V^T [b][h][dv][j]
__device__ __align__(16) __nv_bfloat16 g_vtl[BB*HH*64*LL];

// ---------------- fused f32 -> bf16 hi/lo split for x + 4 weights ----------
__global__ __launch_bounds__(256)
void conv_all_kernel(const float* __restrict__ x,  const float* __restrict__ Wq,
                     const float* __restrict__ Wk, const float* __restrict__ Wv,
                     const float* __restrict__ Wo) {
    int bi = blockIdx.x;
    const float* src;
    __nv_bfloat16 *hi, *lo;
    int lb;
    if (bi < 1536)      { src = x;  hi = g_xhi;            lo = g_xlo;            lb = bi; }
    else if (bi < 1920) { src = Wq; hi = g_whi;            lo = g_wlo;            lb = bi - 1536; }
    else if (bi < 2304) { src = Wk; hi = g_whi + HD*DMM;   lo = g_wlo + HD*DMM;   lb = bi - 1920; }
    else if (bi < 2688) { src = Wv; hi = g_whi + 2*HD*DMM; lo = g_wlo + 2*HD*DMM; lb = bi - 2304; }
    else                { src = Wo; hi = g_wohi;           lo = g_wolo;           lb = bi - 2688; }
    int i = lb * 256 + threadIdx.x;
    float4 v = ((const float4*)src)[i];
    uint32_t h0, l0, h1, l1;
    split2(v.x, v.y, h0, l0);
    split2(v.z, v.w, h1, l1);
    ((uint32_t*)hi)[2*i]     = h0;
    ((uint32_t*)hi)[2*i + 1] = h1;
    ((uint32_t*)lo)[2*i]     = l0;
    ((uint32_t*)lo)[2*i + 1] = l1;
}

// ---------------- pipelined mma.sync bf16-split GEMM body ------------------
// Stage = 4 tiles x [128 rows x 64B] = 32KB; 2 stages; K-chunk 32.
__device__ __forceinline__ void gemm_issue_chunk(
    const __nv_bfloat16* const* srcs, int Kt, int k0, uint32_t sbase, int tid) {
    #pragma unroll
    for (int u = 0; u < 8; u++) {
        int e = tid + u * 256;
        int t = e >> 9, rem = e & 511;
        int row = rem >> 2, seg = rem & 3;
        const __nv_bfloat16* s = srcs[t] + k0 + (size_t)row * Kt + seg * 8;
        uint32_t off = (uint32_t)(row * 64 + seg * 16);
        cp16(sbase + t * 8192 + SW64(off), s);
    }
    CP_COMMIT();
}

__device__ __forceinline__ void gemm_mma_body(
    const __nv_bfloat16* __restrict__ Ahi, const __nv_bfloat16* __restrict__ Alo,
    const __nv_bfloat16* __restrict__ Bhi, const __nv_bfloat16* __restrict__ Blo,
    int Kt, float* __restrict__ Cout, __nv_bfloat16* __restrict__ Chi,
    __nv_bfloat16* __restrict__ Clo, float sc, int Cstride,
    const float* __restrict__ bias)
{
    extern __shared__ char gsm[];
    const uint32_t sb = smem_u32(gsm);
    const int tid = threadIdx.x;
    const int wid = tid >> 5, lane = tid & 31;
    const int wm = wid >> 2, wn = wid & 3;

    float acc[4][4][4];
    #pragma unroll
    for (int mt = 0; mt < 4; mt++)
        #pragma unroll
        for (int nt = 0; nt < 4; nt++)
            #pragma unroll
            for (int r = 0; r < 4; r++) acc[mt][nt][r] = 0.f;

    const int lr  = lane & 15;
    const int lk8 = lane >> 4;

    const __nv_bfloat16* srcs[4] = {Ahi, Alo, Bhi, Blo};
    const int NCH = Kt >> 5;       // K=32 chunks

    gemm_issue_chunk(srcs, Kt, 0, sb, tid);

    for (int ch = 0; ch < NCH; ch++) {
        if (ch + 1 < NCH) {
            gemm_issue_chunk(srcs, Kt, (ch + 1) << 5, sb + ((ch + 1) & 1) * 32768, tid);
            CP_WAIT1();
        } else {
            CP_WAIT0();
        }
        __syncthreads();
        const uint32_t st = sb + (ch & 1) * 32768;

        #pragma unroll
        for (int ks = 0; ks < 2; ks++) {
            const int kseg = (ks << 1) + lk8;
            uint32_t ah[4][4], al[4][4];
            #pragma unroll
            for (int mt = 0; mt < 4; mt++) {
                int row = wm * 64 + mt * 16 + lr;
                uint32_t off = (uint32_t)(row * 64 + kseg * 16);
                off = SW64(off);
                ldsm_x4(ah[mt][0], ah[mt][1], ah[mt][2], ah[mt][3], st + off);
                ldsm_x4(al[mt][0], al[mt][1], al[mt][2], al[mt][3], st + 8192 + off);
            }
            uint32_t bh[2][4], bl[2][4];
            #pragma unroll
            for (int bt = 0; bt < 2; bt++) {
                int row = wn * 32 + bt * 16 + lr;
                uint32_t off = (uint32_t)(row * 64 + kseg * 16);
                off = SW64(off);
                ldsm_x4(bh[bt][0], bh[bt][1], bh[bt][2], bh[bt][3], st + 16384 + off);
                ldsm_x4(bl[bt][0], bl[bt][1], bl[bt][2], bl[bt][3], st + 24576 + off);
            }
            #pragma unroll
            for (int mt = 0; mt < 4; mt++) {
                #pragma unroll
                for (int nt = 0; nt < 4; nt++) {
                    int bt = nt >> 1, hi = nt & 1;
                    mma_bf16(acc[mt][nt], ah[mt], bh[bt][hi], bh[bt][hi + 2]);
                    mma_bf16(acc[mt][nt], ah[mt], bl[bt][hi], bl[bt][hi + 2]);
                    mma_bf16(acc[mt][nt], al[mt], bh[bt][hi], bh[bt][hi + 2]);
                }
            }
        }
        __syncthreads();
    }

    const int er = lane >> 2, ec = (lane & 3) << 1;
    #pragma unroll
    for (int mt = 0; mt < 4; mt++) {
        #pragma unroll
        for (int nt = 0; nt < 4; nt++) {
            int m = wm * 64 + mt * 16 + er;
            int n = wn * 32 + nt * 8 + ec;
            float b0 = 0.f, b1 = 0.f;
            if (bias) { b0 = bias[n]; b1 = bias[n + 1]; }
            float v0 = acc[mt][nt][0] + b0, v1 = acc[mt][nt][1] + b1;
            float v2 = acc[mt][nt][2] + b0, v3 = acc[mt][nt][3] + b1;
            if (Cout) {
                *(float2*)(Cout + (size_t)m * Cstride + n)       = make_float2(v0, v1);
                *(float2*)(Cout + (size_t)(m + 8) * Cstride + n) = make_float2(v2, v3);
            }
            if (Chi) {
                uint32_t h0, l0, h1, l1;
                split2(v0 * sc, v1 * sc, h0, l0);
                split2(v2 * sc, v3 * sc, h1, l1);
                *(uint32_t*)(Chi + (size_t)m * Cstride + n)       = h0;
                *(uint32_t*)(Clo + (size_t)m * Cstride + n)       = l0;
                *(uint32_t*)(Chi + (size_t)(m + 8) * Cstride + n) = h1;
                *(uint32_t*)(Clo + (size_t)(m + 8) * Cstride + n) = l1;
            }
        }
    }
}

__global__ __launch_bounds__(256)
void qkv_mma_kernel() {
    int m0 = blockIdx.x * 128;
    int nglob = blockIdx.y * 128;
    int sel = nglob >> 9, ncol = nglob & 511;
    size_t co = (size_t)m0 * HD + ncol;
    __nv_bfloat16* hb = (sel == 0 ? g_qh : (sel == 1 ? g_kh : g_vh)) + co;
    __nv_bfloat16* lb = (sel == 0 ? g_ql : (sel == 1 ? g_kl : g_vl)) + co;
    float sc = sel == 0 ? 0.125f : 1.f;
    gemm_mma_body(g_xhi + (size_t)m0 * DMM, g_xlo + (size_t)m0 * DMM,
                  g_whi + (size_t)nglob * DMM, g_wlo + (size_t)nglob * DMM,
                  DMM, nullptr, hb, lb, sc, HD, nullptr);
}

__global__ __launch_bounds__(256)
void out_mma_kernel(const float* __restrict__ bo, float* __restrict__ out) {
    int m0 = blockIdx.x * 128;
    int n0 = blockIdx.y * 128;
    gemm_mma_body(g_aohi + (size_t)m0 * HD, g_aolo + (size_t)m0 * HD,
                  g_wohi + (size_t)n0 * HD, g_wolo + (size_t)n0 * HD,
                  HD, out + (size_t)m0 * DMM + n0, nullptr, nullptr, 1.f,
                  DMM, bo + n0);
}

// ---------------- prep: tmin LUT + per-head Vu/Vsg (x0.125) ----------------
__global__ void prep_kernel(const float* __restrict__ v_bias,
                            const float* __restrict__ w_pos) {
    __shared__ double cw[32];
    __shared__ float  vws[512];
    int tid = threadIdx.x;
    if (tid < 32)
        cw[tid] = exp((double)(tid + 1) * log((double)(LL + 1) / 2.0) / 32.0);
    __syncthreads();
    for (int a = tid; a < LL; a += 256) {
        int t = 32;
        for (int j = 31; j >= 0; j--) if ((double)a <= cw[j]) t = j;
        g_tmin[a] = t;
    }
    for (int o = tid; o < 512; o += 256) {
        int h = o >> 6, n = o & 63;
        float s = 0.f;
        for (int d = 0; d < 64; d++)
            s += v_bias[h*64 + d] * w_pos[h*4096 + d*64 + n];
        vws[o] = s;
    }
    __syncthreads();
    if (tid < 16) {
        int h = tid >> 1, sg = tid & 1;
        float run = 0.f;
        float* dst = (sg ? g_Vsg : g_Vu) + h*33;
        dst[32] = 0.f;
        for (int t = 31; t >= 0; t--) {
            run += vws[h*64 + sg*32 + t];
            dst[t] = run * 0.125f;
        }
    }
}

// w_pos^T bf16 split: [h][d][n] -> [h][n][d]
__global__ __launch_bounds__(256)
void wtrans_kernel(const float* __restrict__ w_pos) {
    int idx = blockIdx.x * 256 + threadIdx.x;       // 32768
    int h = idx >> 12, rem = idx & 4095;
    int n = rem >> 6, d = rem & 63;
    float v = w_pos[h*4096 + d*64 + n];
    __nv_bfloat16 hi = __float2bfloat16(v);
    __nv_bfloat16 lo = __float2bfloat16(v - __bfloat162float(hi));
    g_wth[idx] = hi;
    g_wtl[idx] = lo;
}

// uk[b,h,j] = u . (kh+kl)
__global__ __launch_bounds__(256)
void uk_kernel(const float* __restrict__ u_bias) {
    int idx = blockIdx.x * 256 + threadIdx.x;       // 16384
    int b = idx >> 13, rem = idx & 8191;
    int h = rem >> 10, j = rem & 1023;
    const __nv_bfloat16* kh = g_kh + (size_t)(b*LL + j) * HD + h*64;
    const __nv_bfloat16* kl = g_kl + (size_t)(b*LL + j) * HD + h*64;
    const float* u = u_bias + h*64;
    float s = 0.f;
    #pragma unroll
    for (int d = 0; d < 64; d++)
        s += (__bfloat162float(kh[d]) + __bfloat162float(kl[d])) * u[d];
    g_uk[idx] = s;
}

// V^T: [b][j][h][dv] -> [b][h][dv][j] (hi & lo)
__global__ __launch_bounds__(256)
void vtrans_kernel() {
    __shared__ unsigned short sh[128*72], sl[128*72];
    const int b = blockIdx.z, h = blockIdx.y;
    const int j0 = blockIdx.x * 128;
    const int tid = threadIdx.x;
    for (int x = tid; x < 1024; x += 256) {
        int j = x >> 3, seg = x & 7;
        size_t src = (size_t)(b*LL + j0 + j) * HD + h*64 + seg*8;
        *(uint4*)(sh + j*72 + seg*8) = *(const uint4*)(g_vh + src);
        *(uint4*)(sl + j*72 + seg*8) = *(const uint4*)(g_vl + src);
    }
    __syncthreads();
    for (int x = tid; x < 1024; x += 256) {
        int dv = x >> 4, jw = x & 15;
        unsigned short oh[8], ol[8];
        #pragma unroll
        for (int e = 0; e < 8; e++) {
            oh[e] = sh[(jw*8 + e)*72 + dv];
            ol[e] = sl[(jw*8 + e)*72 + dv];
        }
        size_t dst = ((size_t)(b*HH + h)*64 + dv)*LL + j0 + jw*8;
        *(uint4*)(g_vth + dst) = *(uint4*)oh;
        *(uint4*)(g_vtl + dst) = *(uint4*)ol;
    }
}

// -------- qw via mma + suffix sums: one block per (b, h, 128 i-rows) -------
#define QW_QH 0
#define QW_QL 16384
#define QW_WH 32768
#define QW_WL 40960
#define QW_QW 49152          // fp32 [128][65]
#define QW_SMEM (49152 + 128*65*4)

__global__ __launch_bounds__(256)
void qw_suffix_kernel() {
    extern __shared__ char qsm[];
    const uint32_t sb = smem_u32(qsm);
    float* qws = (float*)(qsm + QW_QW);
    const int b = blockIdx.z, h = blockIdx.y;
    const int i0 = blockIdx.x * 128;
    const int tid = threadIdx.x;
    const int wid = tid >> 5, lane = tid & 31;
    const int lr = lane & 15, lk8 = lane >> 4;

    {
        const __nv_bfloat16* qh = g_qh + (size_t)(b*LL + i0) * HD + h*64;
        const __nv_bfloat16* ql = g_ql + (size_t)(b*LL + i0) * HD + h*64;
        for (int x = tid; x < 1024; x += 256) {
            int row = x >> 3, seg = x & 7;
            uint32_t off = row * 128 + ((seg ^ (row & 7)) << 4);
            *(uint4*)(qsm + QW_QH + off) = *(const uint4*)(qh + (size_t)row*HD + seg*8);
            *(uint4*)(qsm + QW_QL + off) = *(const uint4*)(ql + (size_t)row*HD + seg*8);
        }
        const __nv_bfloat16* wth = g_wth + h*4096;
        const __nv_bfloat16* wtl = g_wtl + h*4096;
        for (int x = tid; x < 512; x += 256) {
            int row = x >> 3, seg = x & 7;
            uint32_t off = row * 128 + ((seg ^ (row & 7)) << 4);
            *(uint4*)(qsm + QW_WH + off) = *(const uint4*)(wth + row*64 + seg*8);
            *(uint4*)(qsm + QW_WL + off) = *(const uint4*)(wtl + row*64 + seg*8);
        }
    }
    __syncthreads();

    float sacc[8][4];
    #pragma unroll
    for (int p = 0; p < 8; p++)
        #pragma unroll
        for (int r = 0; r < 4; r++) sacc[p][r] = 0.f;

    #pragma unroll
    for (int ks = 0; ks < 4; ks++) {
        const int kseg = (ks << 1) + lk8;
        int arow = wid*16 + lr;
        uint32_t aoff = arow * 128 + ((kseg ^ (arow & 7)) << 4);
        uint32_t aH[4], aL[4];
        ldsm_x4(aH[0], aH[1], aH[2], aH[3], sb + QW_QH + aoff);
        ldsm_x4(aL[0], aL[1], aL[2], aL[3], sb + QW_QL + aoff);
        #pragma unroll
        for (int bt = 0; bt < 4; bt++) {
            int brow = bt*16 + lr;
            uint32_t boff = brow * 128 + ((kseg ^ (brow & 7)) << 4);
            uint32_t bH[4], bL[4];
            ldsm_x4(bH[0], bH[1], bH[2], bH[3], sb + QW_WH + boff);
            ldsm_x4(bL[0], bL[1], bL[2], bL[3], sb + QW_WL + boff);
            #pragma unroll
            for (int hi = 0; hi < 2; hi++) {
                mma_bf16(sacc[bt*2 + hi], aH, bH[hi], bH[hi + 2]);
                mma_bf16(sacc[bt*2 + hi], aH, bL[hi], bL[hi + 2]);
                mma_bf16(sacc[bt*2 + hi], aL, bH[hi], bH[hi + 2]);
            }
        }
    }

    const int er = lane >> 2, ec = (lane & 3) << 1;
    #pragma unroll
    for (int p = 0; p < 8; p++) {
        int r0 = wid*16 + er, n = p*8 + ec;
        qws[r0*65 + n]       = sacc[p][0];
        qws[r0*65 + n + 1]   = sacc[p][1];
        qws[(r0+8)*65 + n]     = sacc[p][2];
        qws[(r0+8)*65 + n + 1] = sacc[p][3];
    }
    __syncthreads();

    {
        int r = tid >> 1, sg = tid & 1;
        float* dst = (sg ? g_Ss : g_Su) + (size_t)((b*HH + h)*LL + i0 + r) * 33;
        float run = 0.f;
        dst[32] = 0.f;
        const float* src = qws + r*65 + sg*32;
        #pragma unroll
        for (int t = 31; t >= 0; t--) { run += src[t]; dst[t] = run; }
    }
}

// ---------------- flash attention via mma.sync, pipelined K/V ---------------
#define A_QH   0
#define A_QL   16384
#define A_STG0 32768             // stage: KH(16K) KL(16K) VTH(16K) VTL(16K)
#define A_STG1 98304
#define A_SUS  163840            // 128*33 f32
#define A_SSS  180736
#define A_UKS  197632            // 1024 f32 (full row, pre-scaled)
#define A_TMS  201728            // 1024 int
#define ATTN_SMEM 205824

__device__ __forceinline__ void attn_issue_chunk(
    const __nv_bfloat16* kh, const __nv_bfloat16* kl,
    const __nv_bfloat16* vth, const __nv_bfloat16* vtl,
    int j0, uint32_t sbase, int tid)
{
    #pragma unroll
    for (int u = 0; u < 16; u++) {
        int e = tid + u * 256;
        int t = e >> 10, rem = e & 1023;
        if (t < 2) {
            int row = rem >> 3, seg = rem & 7;
            const __nv_bfloat16* s = (t == 0 ? kh : kl) + (size_t)(j0 + row) * HD + seg * 8;
            cp16(sbase + t * 16384 + row * 128 + ((seg ^ (row & 7)) << 4), s);
        } else {
            int row = rem >> 4, seg = rem & 15;
            const __nv_bfloat16* s = (t == 2 ? vth : vtl) + (size_t)row * LL + j0 + seg * 8;
            cp16(sbase + t * 16384 + row * 256 + ((seg ^ (row & 15)) << 4), s);
        }
    }
    CP_COMMIT();
}

__global__ __launch_bounds__(256, 1)
void attn_kernel() {
    extern __shared__ char smc[];
    const uint32_t sb = smem_u32(smc);
    float* Sus = (float*)(smc + A_SUS);
    float* Sss = (float*)(smc + A_SSS);
    float* uks = (float*)(smc + A_UKS);
    int*   tms = (int*)  (smc + A_TMS);

    const int b = blockIdx.z, h = blockIdx.y;
    const int i0 = blockIdx.x * 128;
    const int tid = threadIdx.x;
    const int wid = tid >> 5, lane = tid & 31;
    const int lr = lane & 15, lk8 = lane >> 4;

    const __nv_bfloat16* kh_g  = g_kh + (size_t)(b*LL) * HD + h*64;
    const __nv_bfloat16* kl_g  = g_kl + (size_t)(b*LL) * HD + h*64;
    const __nv_bfloat16* vth_g = g_vth + ((size_t)(b*HH + h)*64)*LL;
    const __nv_bfloat16* vtl_g = g_vtl + ((size_t)(b*HH + h)*64)*LL;

    // issue first K/V chunk immediately
    attn_issue_chunk(kh_g, kl_g, vth_g, vtl_g, 0, sb + A_STG0, tid);

    // prologue: Q tiles + bias tables + full uk row
    {
        const __nv_bfloat16* qh = g_qh + (size_t)(b*LL + i0) * HD + h*64;
        const __nv_bfloat16* ql = g_ql + (size_t)(b*LL + i0) * HD + h*64;
        for (int x = tid; x < 1024; x += 256) {
            int row = x >> 3, seg = x & 7;
            uint32_t off = row * 128 + ((seg ^ (row & 7)) << 4);
            *(uint4*)(smc + A_QH + off) = *(const uint4*)(qh + (size_t)row*HD + seg*8);
            *(uint4*)(smc + A_QL + off) = *(const uint4*)(ql + (size_t)row*HD + seg*8);
        }
        const float* sub = g_Su + (size_t)((b*HH + h)*LL + i0) * 33;
        const float* ssb = g_Ss + (size_t)((b*HH + h)*LL + i0) * 33;
        const float* vu  = g_Vu  + h*33;
        const float* vsg = g_Vsg + h*33;
        for (int x = tid; x < 128*33; x += 256) {
            int t = x % 33;
            Sus[x] = sub[x] + vu[t];
            Sss[x] = ssb[x] + vsg[t];
        }
        const float* ukg = g_uk + (size_t)(b*HH + h)*LL;
        for (int x = tid; x < LL; x += 256) {
            tms[x] = g_tmin[x];
            uks[x] = ukg[x] * 0.125f;
        }
    }

    float m0 = -INFINITY, m1 = -INFINITY, l0 = 0.f, l1 = 0.f;
    float oacc[8][4];
    #pragma unroll
    for (int ot = 0; ot < 8; ot++)
        #pragma unroll
        for (int r = 0; r < 4; r++) oacc[ot][r] = 0.f;

    const int r0 = wid*16 + (lane >> 2);
    const int ig0 = i0 + r0, ig1 = ig0 + 8;
    const float* suR0 = Sus + r0*33;
    const float* ssR0 = Sss + r0*33;
    const float* suR1 = suR0 + 8*33;
    const float* ssR1 = ssR0 + 8*33;

    for (int jt = 0; jt < 8; jt++) {
        const int j0 = jt * 128;
        if (jt + 1 < 8) {
            attn_issue_chunk(kh_g, kl_g, vth_g, vtl_g, j0 + 128,
                             sb + (((jt + 1) & 1) ? A_STG1 : A_STG0), tid);
            CP_WAIT1();
        } else {
            CP_WAIT0();
        }
        __syncthreads();
        const uint32_t st = sb + ((jt & 1) ? A_STG1 : A_STG0);

        float sacc[16][4];
        #pragma unroll
        for (int nt = 0; nt < 16; nt++)
            #pragma unroll
            for (int r = 0; r < 4; r++) sacc[nt][r] = 0.f;

        #pragma unroll
        for (int ks = 0; ks < 4; ks++) {
            const int kseg = (ks << 1) + lk8;
            int arow = wid*16 + lr;
            uint32_t aoff = arow * 128 + ((kseg ^ (arow & 7)) << 4);
            uint32_t aH[4], aL[4];
            ldsm_x4(aH[0], aH[1], aH[2], aH[3], sb + A_QH + aoff);
            ldsm_x4(aL[0], aL[1], aL[2], aL[3], sb + A_QL + aoff);
            #pragma unroll
            for (int bt = 0; bt < 8; bt++) {
                int brow = bt*16 + lr;
                uint32_t boff = brow * 128 + ((kseg ^ (brow & 7)) << 4);
                uint32_t bH[4], bL[4];
                ldsm_x4(bH[0], bH[1], bH[2], bH[3], st + boff);
                ldsm_x4(bL[0], bL[1], bL[2], bL[3], st + 16384 + boff);
                #pragma unroll
                for (int hi = 0; hi < 2; hi++) {
                    mma_bf16(sacc[bt*2 + hi], aH, bH[hi], bH[hi + 2]);
                    mma_bf16(sacc[bt*2 + hi], aH, bL[hi], bL[hi + 2]);
                    mma_bf16(sacc[bt*2 + hi], aL, bH[hi], bH[hi + 2]);
                }
            }
        }

        float mx0 = -INFINITY, mx1 = -INFINITY;
        #pragma unroll
        for (int nt = 0; nt < 16; nt++) {
            int cb = nt*8 + (lane & 3)*2;
            #pragma unroll
            for (int e = 0; e < 2; e++) {
                int j = j0 + cb + e;
                float ukv = uks[j];
                {
                    int d = j - ig0;
                    int a = d < 0 ? -d : d;
                    int t = tms[a];
                    float sg = (float)((d > 0) - (d < 0));
                    sacc[nt][e] += suR0[t] + sg * ssR0[t] + ukv;
                    mx0 = fmaxf(mx0, sacc[nt][e]);
                }
                {
                    int d = j - ig1;
                    int a = d < 0 ? -d : d;
                    int t = tms[a];
                    float sg = (float)((d > 0) - (d < 0));
                    sacc[nt][2 + e] += suR1[t] + sg * ssR1[t] + ukv;
                    mx1 = fmaxf(mx1, sacc[nt][2 + e]);
                }
            }
        }
        mx0 = fmaxf(mx0, __shfl_xor_sync(0xffffffffu, mx0, 1));
        mx0 = fmaxf(mx0, __shfl_xor_sync(0xffffffffu, mx0, 2));
        mx1 = fmaxf(mx1, __shfl_xor_sync(0xffffffffu, mx1, 1));
        mx1 = fmaxf(mx1, __shfl_xor_sync(0xffffffffu, mx1, 2));
        float mn0 = fmaxf(m0, mx0), mn1 = fmaxf(m1, mx1);
        float al0 = __expf(m0 - mn0), al1 = __expf(m1 - mn1);
        m0 = mn0; m1 = mn1;
        float sum0 = 0.f, sum1 = 0.f;
        #pragma unroll
        for (int nt = 0; nt < 16; nt++) {
            #pragma unroll
            for (int e = 0; e < 2; e++) {
                sacc[nt][e]     = __expf(sacc[nt][e]     - mn0); sum0 += sacc[nt][e];
                sacc[nt][2 + e] = __expf(sacc[nt][2 + e] - mn1); sum1 += sacc[nt][2 + e];
            }
        }
        sum0 += __shfl_xor_sync(0xffffffffu, sum0, 1);
        sum0 += __shfl_xor_sync(0xffffffffu, sum0, 2);
        sum1 += __shfl_xor_sync(0xffffffffu, sum1, 1);
        sum1 += __shfl_xor_sync(0xffffffffu, sum1, 2);
        l0 = l0 * al0 + sum0;
        l1 = l1 * al1 + sum1;
        #pragma unroll
        for (int ot = 0; ot < 8; ot++) {
            oacc[ot][0] *= al0; oacc[ot][1] *= al0;
            oacc[ot][2] *= al1; oacc[ot][3] *= al1;
        }

        #pragma unroll
        for (int kt = 0; kt < 8; kt++) {
            uint32_t pH[4], pL[4];
            split2(sacc[2*kt][0],     sacc[2*kt][1],     pH[0], pL[0]);
            split2(sacc[2*kt][2],     sacc[2*kt][3],     pH[1], pL[1]);
            split2(sacc[2*kt + 1][0], sacc[2*kt + 1][1], pH[2], pL[2]);
            split2(sacc[2*kt + 1][2], sacc[2*kt + 1][3], pH[3], pL[3]);
            #pragma unroll
            for (int bt = 0; bt < 4; bt++) {
                int vrow = bt*16 + lr;
                uint32_t voff = vrow * 256 + (((kt*2 + lk8) ^ (vrow & 15)) << 4);
                uint32_t vH[4], vL[4];
                ldsm_x4(vH[0], vH[1], vH[2], vH[3], st + 32768 + voff);
                ldsm_x4(vL[0], vL[1], vL[2], vL[3], st + 49152 + voff);
                #pragma unroll
                for (int hi = 0; hi < 2; hi++) {
                    mma_bf16(oacc[bt*2 + hi], pH, vH[hi], vH[hi + 2]);
                    mma_bf16(oacc[bt*2 + hi], pH, vL[hi], vL[hi + 2]);
                    mma_bf16(oacc[bt*2 + hi], pL, vH[hi], vH[hi + 2]);
                }
            }
        }
        __syncthreads();
    }

    float inv0 = 1.f / l0, inv1 = 1.f / l1;
    #pragma unroll
    for (int ot = 0; ot < 8; ot++) {
        int col = ot*8 + (lane & 3)*2;
        size_t p0 = (size_t)(b*LL + ig0) * HD + h*64 + col;
        size_t p1 = (size_t)(b*LL + ig1) * HD + h*64 + col;
        uint32_t h0, lo0, h1, lo1;
        split2(oacc[ot][0]*inv0, oacc[ot][1]*inv0, h0, lo0);
        split2(oacc[ot][2]*inv1, oacc[ot][3]*inv1, h1, lo1);
        *(uint32_t*)(g_aohi + p0) = h0;
        *(uint32_t*)(g_aolo + p0) = lo0;
        *(uint32_t*)(g_aohi + p1) = h1;
        *(uint32_t*)(g_aolo + p1) = lo1;
    }
}

// ---------------------------------------------------------------------------
extern "C" void kernel_launch(void* const* d_in, const int* in_sizes, int n_in,
                              void* d_out, int out_size) {
    const float* x  = (const float*)d_in[0];
    const float* Wq = (const float*)d_in[1];
    const float* Wk = (const float*)d_in[2];
    const float* Wv = (const float*)d_in[3];
    const float* Wo = (const float*)d_in[4];
    const float* bo = (const float*)d_in[5];
    const float* ub = (const float*)d_in[6];
    const float* vb = (const float*)d_in[7];
    const float* wp = (const float*)d_in[8];
    float* out = (float*)d_out;

    prep_kernel<<<1, 256>>>(vb, wp);
    wtrans_kernel<<<128, 256>>>(wp);
    conv_all_kernel<<<3072, 256>>>(x, Wq, Wk, Wv, Wo);

    const int GEMM_SMEM = 65536;
    cudaFuncSetAttribute(qkv_mma_kernel, cudaFuncAttributeMaxDynamicSharedMemorySize, GEMM_SMEM);
    cudaFuncSetAttribute(out_mma_kernel, cudaFuncAttributeMaxDynamicSharedMemorySize, GEMM_SMEM);

    qkv_mma_kernel<<<dim3(16, 12), 256, GEMM_SMEM>>>();

    vtrans_kernel<<<dim3(8, HH, BB), 256>>>();
    uk_kernel<<<64, 256>>>(ub);

    cudaFuncSetAttribute(qw_suffix_kernel, cudaFuncAttributeMaxDynamicSharedMemorySize, QW_SMEM);
    qw_suffix_kernel<<<dim3(8, HH, BB), 256, QW_SMEM>>>();

    cudaFuncSetAttribute(attn_kernel, cudaFuncAttributeMaxDynamicSharedMemorySize, ATTN_SMEM);
    attn_kernel<<<dim3(LL/128, HH, BB), 256, ATTN_SMEM>>>();

    out_mma_kernel<<<dim3(16, 6), 256, GEMM_SMEM>>>(bo, out);
}

// round 15
// speedup vs baseline: 4.6421x; 1.0987x over previous
#include <cuda_runtime.h>
#include <cuda_bf16.h>
#include <math.h>
#include <stdint.h>

#define BB 2
#define LL 1024
#define HH 8
#define DD 64
#define DMM 768
#define HD 512

typedef unsigned long long u64;

// ---------------- mma.sync / cp.async helpers (baseline ISA) ---------------
__device__ __forceinline__ uint32_t smem_u32(const void* p) {
    uint32_t a;
    asm("{ .reg .u64 t; cvta.to.shared.u64 t, %1; cvt.u32.u64 %0, t; }"
        : "=r"(a) : "l"(p));
    return a;
}
__device__ __forceinline__ void ldsm_x4(uint32_t& r0, uint32_t& r1,
                                        uint32_t& r2, uint32_t& r3, uint32_t addr) {
    asm volatile("ldmatrix.sync.aligned.m8n8.x4.shared.b16 {%0,%1,%2,%3}, [%4];"
                 : "=r"(r0), "=r"(r1), "=r"(r2), "=r"(r3) : "r"(addr));
}
__device__ __forceinline__ void mma_bf16(float* c, const uint32_t* a,
                                         uint32_t b0, uint32_t b1) {
    asm volatile(
        "mma.sync.aligned.m16n8k16.row.col.f32.bf16.bf16.f32 "
        "{%0,%1,%2,%3}, {%4,%5,%6,%7}, {%8,%9}, {%0,%1,%2,%3};"
        : "+f"(c[0]), "+f"(c[1]), "+f"(c[2]), "+f"(c[3])
        : "r"(a[0]), "r"(a[1]), "r"(a[2]), "r"(a[3]), "r"(b0), "r"(b1));
}
__device__ __forceinline__ void split2(float a, float b, uint32_t& hi, uint32_t& lo) {
    __nv_bfloat16 ha = __float2bfloat16(a), hb = __float2bfloat16(b);
    __nv_bfloat16 la = __float2bfloat16(a - __bfloat162float(ha));
    __nv_bfloat16 lb = __float2bfloat16(b - __bfloat162float(hb));
    hi = (uint32_t)*(unsigned short*)&ha | ((uint32_t)*(unsigned short*)&hb << 16);
    lo = (uint32_t)*(unsigned short*)&la | ((uint32_t)*(unsigned short*)&lb << 16);
}
__device__ __forceinline__ void cp16(uint32_t dst, const void* src) {
    asm volatile("cp.async.cg.shared.global [%0], [%1], 16;" :: "r"(dst), "l"(src));
}
#define CP_COMMIT() asm volatile("cp.async.commit_group;" ::: "memory")
#define CP_WAIT1()  asm volatile("cp.async.wait_group 1;" ::: "memory")
#define CP_WAIT0()  asm volatile("cp.async.wait_group 0;" ::: "memory")

// ---------------- scratch (static device globals; no allocs) ----------------
__device__ float g_Su[BB*HH*LL*33];
__device__ float g_Ss[BB*HH*LL*33];
__device__ float g_uk[BB*HH*LL];
__device__ float g_Vu[HH*33];      // pre-scaled x0.125
__device__ float g_Vsg[HH*33];     // pre-scaled x0.125
__device__ int   g_tmin[LL];

__device__ __align__(16) __nv_bfloat16 g_xhi [BB*LL*DMM];
__device__ __align__(16) __nv_bfloat16 g_xlo [BB*LL*DMM];
__device__ __align__(16) __nv_bfloat16 g_whi [3*HD*DMM];
__device__ __align__(16) __nv_bfloat16 g_wlo [3*HD*DMM];
__device__ __align__(16) __nv_bfloat16 g_wohi[DMM*HD];
__device__ __align__(16) __nv_bfloat16 g_wolo[DMM*HD];
__device__ __align__(16) __nv_bfloat16 g_aohi[BB*LL*HD];
__device__ __align__(16) __nv_bfloat16 g_aolo[BB*LL*HD];
__device__ __align__(16) __nv_bfloat16 g_qh[BB*LL*HD];   // q x0.125 split
__device__ __align__(16) __nv_bfloat16 g_ql[BB*LL*HD];
__device__ __align__(16) __nv_bfloat16 g_kh[BB*LL*HD];
__device__ __align__(16) __nv_bfloat16 g_kl[BB*LL*HD];
__device__ __align__(16) __nv_bfloat16 g_vh[BB*LL*HD];
__device__ __align__(16) __nv_bfloat16 g_vl[BB*LL*HD];
__device__ __align__(16) __nv_bfloat16 g_wth[HH*64*64];  // w_pos^T [h][n][d] split
__device__ __align__(16) __nv_bfloat16 g_wtl[HH*64*64];
__device__ __align__(16) __nv_bfloat16 g_vth[BB*HH*64*LL]; // V^T [b][h][dv][j]
__device__ __align__(16) __nv_bfloat16 g_vtl[BB*HH*64*LL];

// ---------------- fused f32 -> bf16 hi/lo split for x + 4 weights ----------
__global__ __launch_bounds__(256)
void conv_all_kernel(const float* __restrict__ x,  const float* __restrict__ Wq,
                     const float* __restrict__ Wk, const float* __restrict__ Wv,
                     const float* __restrict__ Wo) {
    int bi = blockIdx.x;
    const float* src;
    __nv_bfloat16 *hi, *lo;
    int lb;
    if (bi < 1536)      { src = x;  hi = g_xhi;            lo = g_xlo;            lb = bi; }
    else if (bi < 1920) { src = Wq; hi = g_whi;            lo = g_wlo;            lb = bi - 1536; }
    else if (bi < 2304) { src = Wk; hi = g_whi + HD*DMM;   lo = g_wlo + HD*DMM;   lb = bi - 1920; }
    else if (bi < 2688) { src = Wv; hi = g_whi + 2*HD*DMM; lo = g_wlo + 2*HD*DMM; lb = bi - 2304; }
    else                { src = Wo; hi = g_wohi;           lo = g_wolo;           lb = bi - 2688; }
    int i = lb * 256 + threadIdx.x;
    float4 v = ((const float4*)src)[i];
    uint32_t h0, l0, h1, l1;
    split2(v.x, v.y, h0, l0);
    split2(v.z, v.w, h1, l1);
    ((uint32_t*)hi)[2*i]     = h0;
    ((uint32_t*)hi)[2*i + 1] = h1;
    ((uint32_t*)lo)[2*i]     = l0;
    ((uint32_t*)lo)[2*i + 1] = l1;
}

// ---------------- mma.sync bf16-split GEMM body: 128x64 tile ---------------
// Warps 4(M) x 2(N); warp tile 32x32. Single-buffered K-chunk 64; 48KB smem.
// __launch_bounds__(256, 2) on callers -> 2 blocks/SM.
#define G_AH 0
#define G_AL 16384
#define G_BH 32768
#define G_BL 40960
#define GEMM_SMEM 49152

__device__ __forceinline__ void gemm_mma_body(
    const __nv_bfloat16* __restrict__ Ahi, const __nv_bfloat16* __restrict__ Alo,
    const __nv_bfloat16* __restrict__ Bhi, const __nv_bfloat16* __restrict__ Blo,
    int Kt, float* __restrict__ Cout, __nv_bfloat16* __restrict__ Chi,
    __nv_bfloat16* __restrict__ Clo, float sc, int Cstride,
    const float* __restrict__ bias)
{
    extern __shared__ char gsm[];
    const uint32_t sb = smem_u32(gsm);
    const int tid = threadIdx.x;
    const int wid = tid >> 5, lane = tid & 31;
    const int wm = wid >> 1, wn = wid & 1;          // 4 x 2 warp grid

    float acc[2][4][4];
    #pragma unroll
    for (int mt = 0; mt < 2; mt++)
        #pragma unroll
        for (int nt = 0; nt < 4; nt++)
            #pragma unroll
            for (int r = 0; r < 4; r++) acc[mt][nt][r] = 0.f;

    const int lr  = lane & 15;
    const int lk8 = lane >> 4;
    const int NCH = Kt >> 6;

    for (int ch = 0; ch < NCH; ch++) {
        const int k0 = ch << 6;
        // A: 128 rows x 128B hi/lo; B: 64 rows x 128B hi/lo  (3072 uint4)
        #pragma unroll
        for (int u = 0; u < 12; u++) {
            int e = tid + u * 256;
            if (e < 2048) {
                int t = e >> 10, rem = e & 1023;
                int row = rem >> 3, seg = rem & 7;
                const __nv_bfloat16* s = (t ? Alo : Ahi) + (size_t)row * Kt + k0 + seg * 8;
                *(uint4*)(gsm + t * 16384 + row * 128 + ((seg ^ (row & 7)) << 4)) =
                    *(const uint4*)s;
            } else {
                int e2 = e - 2048;
                int t = e2 >> 9, rem = e2 & 511;
                int row = rem >> 3, seg = rem & 7;
                const __nv_bfloat16* s = (t ? Blo : Bhi) + (size_t)row * Kt + k0 + seg * 8;
                *(uint4*)(gsm + 32768 + t * 8192 + row * 128 + ((seg ^ (row & 7)) << 4)) =
                    *(const uint4*)s;
            }
        }
        __syncthreads();

        #pragma unroll
        for (int ks = 0; ks < 4; ks++) {
            const int kseg = (ks << 1) + lk8;
            uint32_t ah[2][4], al[2][4];
            #pragma unroll
            for (int mt = 0; mt < 2; mt++) {
                int row = wm * 32 + mt * 16 + lr;
                uint32_t off = row * 128 + (((kseg ^ (row & 7))) << 4);
                ldsm_x4(ah[mt][0], ah[mt][1], ah[mt][2], ah[mt][3], sb + off);
                ldsm_x4(al[mt][0], al[mt][1], al[mt][2], al[mt][3], sb + 16384 + off);
            }
            uint32_t bh[2][4], bl[2][4];
            #pragma unroll
            for (int bt = 0; bt < 2; bt++) {
                int row = wn * 32 + bt * 16 + lr;
                uint32_t off = row * 128 + (((kseg ^ (row & 7))) << 4);
                ldsm_x4(bh[bt][0], bh[bt][1], bh[bt][2], bh[bt][3], sb + 32768 + off);
                ldsm_x4(bl[bt][0], bl[bt][1], bl[bt][2], bl[bt][3], sb + 40960 + off);
            }
            #pragma unroll
            for (int mt = 0; mt < 2; mt++) {
                #pragma unroll
                for (int nt = 0; nt < 4; nt++) {
                    int bt = nt >> 1, hi = nt & 1;
                    mma_bf16(acc[mt][nt], ah[mt], bh[bt][hi], bh[bt][hi + 2]);
                    mma_bf16(acc[mt][nt], ah[mt], bl[bt][hi], bl[bt][hi + 2]);
                    mma_bf16(acc[mt][nt], al[mt], bh[bt][hi], bh[bt][hi + 2]);
                }
            }
        }
        __syncthreads();
    }

    const int er = lane >> 2, ec = (lane & 3) << 1;
    #pragma unroll
    for (int mt = 0; mt < 2; mt++) {
        #pragma unroll
        for (int nt = 0; nt < 4; nt++) {
            int m = wm * 32 + mt * 16 + er;
            int n = wn * 32 + nt * 8 + ec;
            float b0 = 0.f, b1 = 0.f;
            if (bias) { b0 = bias[n]; b1 = bias[n + 1]; }
            float v0 = acc[mt][nt][0] + b0, v1 = acc[mt][nt][1] + b1;
            float v2 = acc[mt][nt][2] + b0, v3 = acc[mt][nt][3] + b1;
            if (Cout) {
                *(float2*)(Cout + (size_t)m * Cstride + n)       = make_float2(v0, v1);
                *(float2*)(Cout + (size_t)(m + 8) * Cstride + n) = make_float2(v2, v3);
            }
            if (Chi) {
                uint32_t h0, l0, h1, l1;
                split2(v0 * sc, v1 * sc, h0, l0);
                split2(v2 * sc, v3 * sc, h1, l1);
                *(uint32_t*)(Chi + (size_t)m * Cstride + n)       = h0;
                *(uint32_t*)(Clo + (size_t)m * Cstride + n)       = l0;
                *(uint32_t*)(Chi + (size_t)(m + 8) * Cstride + n) = h1;
                *(uint32_t*)(Clo + (size_t)(m + 8) * Cstride + n) = l1;
            }
        }
    }
}

// QKV: grid (16 M-tiles, 24 N-tiles of 64 over concatenated 1536)
__global__ __launch_bounds__(256, 2)
void qkv_mma_kernel() {
    int m0 = blockIdx.x * 128;
    int nglob = blockIdx.y * 64;
    int sel = nglob >> 9, ncol = nglob & 511;
    size_t co = (size_t)m0 * HD + ncol;
    __nv_bfloat16* hb = (sel == 0 ? g_qh : (sel == 1 ? g_kh : g_vh)) + co;
    __nv_bfloat16* lb = (sel == 0 ? g_ql : (sel == 1 ? g_kl : g_vl)) + co;
    float sc = sel == 0 ? 0.125f : 1.f;
    gemm_mma_body(g_xhi + (size_t)m0 * DMM, g_xlo + (size_t)m0 * DMM,
                  g_whi + (size_t)nglob * DMM, g_wlo + (size_t)nglob * DMM,
                  DMM, nullptr, hb, lb, sc, HD, nullptr);
}

// out: grid (16 M-tiles, 12 N-tiles of 64 over 768)
__global__ __launch_bounds__(256, 2)
void out_mma_kernel(const float* __restrict__ bo, float* __restrict__ out) {
    int m0 = blockIdx.x * 128;
    int n0 = blockIdx.y * 64;
    gemm_mma_body(g_aohi + (size_t)m0 * HD, g_aolo + (size_t)m0 * HD,
                  g_wohi + (size_t)n0 * HD, g_wolo + (size_t)n0 * HD,
                  HD, out + (size_t)m0 * DMM + n0, nullptr, nullptr, 1.f,
                  DMM, bo + n0);
}

// ---------------- prep: tmin LUT + per-head Vu/Vsg (x0.125) ----------------
__global__ void prep_kernel(const float* __restrict__ v_bias,
                            const float* __restrict__ w_pos) {
    __shared__ double cw[32];
    __shared__ float  vws[512];
    int tid = threadIdx.x;
    if (tid < 32)
        cw[tid] = exp((double)(tid + 1) * log((double)(LL + 1) / 2.0) / 32.0);
    __syncthreads();
    for (int a = tid; a < LL; a += 256) {
        int t = 32;
        for (int j = 31; j >= 0; j--) if ((double)a <= cw[j]) t = j;
        g_tmin[a] = t;
    }
    for (int o = tid; o < 512; o += 256) {
        int h = o >> 6, n = o & 63;
        float s = 0.f;
        for (int d = 0; d < 64; d++)
            s += v_bias[h*64 + d] * w_pos[h*4096 + d*64 + n];
        vws[o] = s;
    }
    __syncthreads();
    if (tid < 16) {
        int h = tid >> 1, sg = tid & 1;
        float run = 0.f;
        float* dst = (sg ? g_Vsg : g_Vu) + h*33;
        dst[32] = 0.f;
        for (int t = 31; t >= 0; t--) {
            run += vws[h*64 + sg*32 + t];
            dst[t] = run * 0.125f;
        }
    }
}

// w_pos^T bf16 split: [h][d][n] -> [h][n][d]
__global__ __launch_bounds__(256)
void wtrans_kernel(const float* __restrict__ w_pos) {
    int idx = blockIdx.x * 256 + threadIdx.x;       // 32768
    int h = idx >> 12, rem = idx & 4095;
    int n = rem >> 6, d = rem & 63;
    float v = w_pos[h*4096 + d*64 + n];
    __nv_bfloat16 hi = __float2bfloat16(v);
    __nv_bfloat16 lo = __float2bfloat16(v - __bfloat162float(hi));
    g_wth[idx] = hi;
    g_wtl[idx] = lo;
}

// uk[b,h,j] = u . (kh+kl)
__global__ __launch_bounds__(256)
void uk_kernel(const float* __restrict__ u_bias) {
    int idx = blockIdx.x * 256 + threadIdx.x;       // 16384
    int b = idx >> 13, rem = idx & 8191;
    int h = rem >> 10, j = rem & 1023;
    const __nv_bfloat16* kh = g_kh + (size_t)(b*LL + j) * HD + h*64;
    const __nv_bfloat16* kl = g_kl + (size_t)(b*LL + j) * HD + h*64;
    const float* u = u_bias + h*64;
    float s = 0.f;
    #pragma unroll
    for (int d = 0; d < 64; d++)
        s += (__bfloat162float(kh[d]) + __bfloat162float(kl[d])) * u[d];
    g_uk[idx] = s;
}

// V^T: [b][j][h][dv] -> [b][h][dv][j] (hi & lo)
__global__ __launch_bounds__(256)
void vtrans_kernel() {
    __shared__ unsigned short sh[128*72], sl[128*72];
    const int b = blockIdx.z, h = blockIdx.y;
    const int j0 = blockIdx.x * 128;
    const int tid = threadIdx.x;
    for (int x = tid; x < 1024; x += 256) {
        int j = x >> 3, seg = x & 7;
        size_t src = (size_t)(b*LL + j0 + j) * HD + h*64 + seg*8;
        *(uint4*)(sh + j*72 + seg*8) = *(const uint4*)(g_vh + src);
        *(uint4*)(sl + j*72 + seg*8) = *(const uint4*)(g_vl + src);
    }
    __syncthreads();
    for (int x = tid; x < 1024; x += 256) {
        int dv = x >> 4, jw = x & 15;
        unsigned short oh[8], ol[8];
        #pragma unroll
        for (int e = 0; e < 8; e++) {
            oh[e] = sh[(jw*8 + e)*72 + dv];
            ol[e] = sl[(jw*8 + e)*72 + dv];
        }
        size_t dst = ((size_t)(b*HH + h)*64 + dv)*LL + j0 + jw*8;
        *(uint4*)(g_vth + dst) = *(uint4*)oh;
        *(uint4*)(g_vtl + dst) = *(uint4*)ol;
    }
}

// -------- qw via mma + suffix sums: one block per (b, h, 128 i-rows) -------
#define QW_QH 0
#define QW_QL 16384
#define QW_WH 32768
#define QW_WL 40960
#define QW_QW 49152          // fp32 [128][65]
#define QW_SMEM (49152 + 128*65*4)

__global__ __launch_bounds__(256)
void qw_suffix_kernel() {
    extern __shared__ char qsm[];
    const uint32_t sb = smem_u32(qsm);
    float* qws = (float*)(qsm + QW_QW);
    const int b = blockIdx.z, h = blockIdx.y;
    const int i0 = blockIdx.x * 128;
    const int tid = threadIdx.x;
    const int wid = tid >> 5, lane = tid & 31;
    const int lr = lane & 15, lk8 = lane >> 4;

    {
        const __nv_bfloat16* qh = g_qh + (size_t)(b*LL + i0) * HD + h*64;
        const __nv_bfloat16* ql = g_ql + (size_t)(b*LL + i0) * HD + h*64;
        for (int x = tid; x < 1024; x += 256) {
            int row = x >> 3, seg = x & 7;
            uint32_t off = row * 128 + ((seg ^ (row & 7)) << 4);
            *(uint4*)(qsm + QW_QH + off) = *(const uint4*)(qh + (size_t)row*HD + seg*8);
            *(uint4*)(qsm + QW_QL + off) = *(const uint4*)(ql + (size_t)row*HD + seg*8);
        }
        const __nv_bfloat16* wth = g_wth + h*4096;
        const __nv_bfloat16* wtl = g_wtl + h*4096;
        for (int x = tid; x < 512; x += 256) {
            int row = x >> 3, seg = x & 7;
            uint32_t off = row * 128 + ((seg ^ (row & 7)) << 4);
            *(uint4*)(qsm + QW_WH + off) = *(const uint4*)(wth + row*64 + seg*8);
            *(uint4*)(qsm + QW_WL + off) = *(const uint4*)(wtl + row*64 + seg*8);
        }
    }
    __syncthreads();

    float sacc[8][4];
    #pragma unroll
    for (int p = 0; p < 8; p++)
        #pragma unroll
        for (int r = 0; r < 4; r++) sacc[p][r] = 0.f;

    #pragma unroll
    for (int ks = 0; ks < 4; ks++) {
        const int kseg = (ks << 1) + lk8;
        int arow = wid*16 + lr;
        uint32_t aoff = arow * 128 + ((kseg ^ (arow & 7)) << 4);
        uint32_t aH[4], aL[4];
        ldsm_x4(aH[0], aH[1], aH[2], aH[3], sb + QW_QH + aoff);
        ldsm_x4(aL[0], aL[1], aL[2], aL[3], sb + QW_QL + aoff);
        #pragma unroll
        for (int bt = 0; bt < 4; bt++) {
            int brow = bt*16 + lr;
            uint32_t boff = brow * 128 + ((kseg ^ (brow & 7)) << 4);
            uint32_t bH[4], bL[4];
            ldsm_x4(bH[0], bH[1], bH[2], bH[3], sb + QW_WH + boff);
            ldsm_x4(bL[0], bL[1], bL[2], bL[3], sb + QW_WL + boff);
            #pragma unroll
            for (int hi = 0; hi < 2; hi++) {
                mma_bf16(sacc[bt*2 + hi], aH, bH[hi], bH[hi + 2]);
                mma_bf16(sacc[bt*2 + hi], aH, bL[hi], bL[hi + 2]);
                mma_bf16(sacc[bt*2 + hi], aL, bH[hi], bH[hi + 2]);
            }
        }
    }

    const int er = lane >> 2, ec = (lane & 3) << 1;
    #pragma unroll
    for (int p = 0; p < 8; p++) {
        int r0 = wid*16 + er, n = p*8 + ec;
        qws[r0*65 + n]       = sacc[p][0];
        qws[r0*65 + n + 1]   = sacc[p][1];
        qws[(r0+8)*65 + n]     = sacc[p][2];
        qws[(r0+8)*65 + n + 1] = sacc[p][3];
    }
    __syncthreads();

    {
        int r = tid >> 1, sg = tid & 1;
        float* dst = (sg ? g_Ss : g_Su) + (size_t)((b*HH + h)*LL + i0 + r) * 33;
        float run = 0.f;
        dst[32] = 0.f;
        const float* src = qws + r*65 + sg*32;
        #pragma unroll
        for (int t = 31; t >= 0; t--) { run += src[t]; dst[t] = run; }
    }
}

// ---------------- flash attention via mma.sync, pipelined K/V ---------------
#define A_QH   0
#define A_QL   16384
#define A_STG0 32768             // stage: KH(16K) KL(16K) VTH(16K) VTL(16K)
#define A_STG1 98304
#define A_SUS  163840            // 128*33 f32
#define A_SSS  180736
#define A_UKS  197632            // 1024 f32 (full row, pre-scaled)
#define A_TMS  201728            // 1024 int
#define ATTN_SMEM 205824

__device__ __forceinline__ void attn_issue_chunk(
    const __nv_bfloat16* kh, const __nv_bfloat16* kl,
    const __nv_bfloat16* vth, const __nv_bfloat16* vtl,
    int j0, uint32_t sbase, int tid)
{
    #pragma unroll
    for (int u = 0; u < 16; u++) {
        int e = tid + u * 256;
        int t = e >> 10, rem = e & 1023;
        if (t < 2) {
            int row = rem >> 3, seg = rem & 7;
            const __nv_bfloat16* s = (t == 0 ? kh : kl) + (size_t)(j0 + row) * HD + seg * 8;
            cp16(sbase + t * 16384 + row * 128 + ((seg ^ (row & 7)) << 4), s);
        } else {
            int row = rem >> 4, seg = rem & 15;
            const __nv_bfloat16* s = (t == 2 ? vth : vtl) + (size_t)row * LL + j0 + seg * 8;
            cp16(sbase + t * 16384 + row * 256 + ((seg ^ (row & 15)) << 4), s);
        }
    }
    CP_COMMIT();
}

__global__ __launch_bounds__(256, 1)
void attn_kernel() {
    extern __shared__ char smc[];
    const uint32_t sb = smem_u32(smc);
    float* Sus = (float*)(smc + A_SUS);
    float* Sss = (float*)(smc + A_SSS);
    float* uks = (float*)(smc + A_UKS);
    int*   tms = (int*)  (smc + A_TMS);

    const int b = blockIdx.z, h = blockIdx.y;
    const int i0 = blockIdx.x * 128;
    const int tid = threadIdx.x;
    const int wid = tid >> 5, lane = tid & 31;
    const int lr = lane & 15, lk8 = lane >> 4;

    const __nv_bfloat16* kh_g  = g_kh + (size_t)(b*LL) * HD + h*64;
    const __nv_bfloat16* kl_g  = g_kl + (size_t)(b*LL) * HD + h*64;
    const __nv_bfloat16* vth_g = g_vth + ((size_t)(b*HH + h)*64)*LL;
    const __nv_bfloat16* vtl_g = g_vtl + ((size_t)(b*HH + h)*64)*LL;

    attn_issue_chunk(kh_g, kl_g, vth_g, vtl_g, 0, sb + A_STG0, tid);

    {
        const __nv_bfloat16* qh = g_qh + (size_t)(b*LL + i0) * HD + h*64;
        const __nv_bfloat16* ql = g_ql + (size_t)(b*LL + i0) * HD + h*64;
        for (int x = tid; x < 1024; x += 256) {
            int row = x >> 3, seg = x & 7;
            uint32_t off = row * 128 + ((seg ^ (row & 7)) << 4);
            *(uint4*)(smc + A_QH + off) = *(const uint4*)(qh + (size_t)row*HD + seg*8);
            *(uint4*)(smc + A_QL + off) = *(const uint4*)(ql + (size_t)row*HD + seg*8);
        }
        const float* sub = g_Su + (size_t)((b*HH + h)*LL + i0) * 33;
        const float* ssb = g_Ss + (size_t)((b*HH + h)*LL + i0) * 33;
        const float* vu  = g_Vu  + h*33;
        const float* vsg = g_Vsg + h*33;
        for (int x = tid; x < 128*33; x += 256) {
            int t = x % 33;
            Sus[x] = sub[x] + vu[t];
            Sss[x] = ssb[x] + vsg[t];
        }
        const float* ukg = g_uk + (size_t)(b*HH + h)*LL;
        for (int x = tid; x < LL; x += 256) {
            tms[x] = g_tmin[x];
            uks[x] = ukg[x] * 0.125f;
        }
    }

    float m0 = -INFINITY, m1 = -INFINITY, l0 = 0.f, l1 = 0.f;
    float oacc[8][4];
    #pragma unroll
    for (int ot = 0; ot < 8; ot++)
        #pragma unroll
        for (int r = 0; r < 4; r++) oacc[ot][r] = 0.f;

    const int r0 = wid*16 + (lane >> 2);
    const int ig0 = i0 + r0, ig1 = ig0 + 8;
    const float* suR0 = Sus + r0*33;
    const float* ssR0 = Sss + r0*33;
    const float* suR1 = suR0 + 8*33;
    const float* ssR1 = ssR0 + 8*33;

    for (int jt = 0; jt < 8; jt++) {
        const int j0 = jt * 128;
        if (jt + 1 < 8) {
            attn_issue_chunk(kh_g, kl_g, vth_g, vtl_g, j0 + 128,
                             sb + (((jt + 1) & 1) ? A_STG1 : A_STG0), tid);
            CP_WAIT1();
        } else {
            CP_WAIT0();
        }
        __syncthreads();
        const uint32_t st = sb + ((jt & 1) ? A_STG1 : A_STG0);

        float sacc[16][4];
        #pragma unroll
        for (int nt = 0; nt < 16; nt++)
            #pragma unroll
            for (int r = 0; r < 4; r++) sacc[nt][r] = 0.f;

        #pragma unroll
        for (int ks = 0; ks < 4; ks++) {
            const int kseg = (ks << 1) + lk8;
            int arow = wid*16 + lr;
            uint32_t aoff = arow * 128 + ((kseg ^ (arow & 7)) << 4);
            uint32_t aH[4], aL[4];
            ldsm_x4(aH[0], aH[1], aH[2], aH[3], sb + A_QH + aoff);
            ldsm_x4(aL[0], aL[1], aL[2], aL[3], sb + A_QL + aoff);
            #pragma unroll
            for (int bt = 0; bt < 8; bt++) {
                int brow = bt*16 + lr;
                uint32_t boff = brow * 128 + ((kseg ^ (brow & 7)) << 4);
                uint32_t bH[4], bL[4];
                ldsm_x4(bH[0], bH[1], bH[2], bH[3], st + boff);
                ldsm_x4(bL[0], bL[1], bL[2], bL[3], st + 16384 + boff);
                #pragma unroll
                for (int hi = 0; hi < 2; hi++) {
                    mma_bf16(sacc[bt*2 + hi], aH, bH[hi], bH[hi + 2]);
                    mma_bf16(sacc[bt*2 + hi], aH, bL[hi], bL[hi + 2]);
                    mma_bf16(sacc[bt*2 + hi], aL, bH[hi], bH[hi + 2]);
                }
            }
        }

        float mx0 = -INFINITY, mx1 = -INFINITY;
        #pragma unroll
        for (int nt = 0; nt < 16; nt++) {
            int cb = nt*8 + (lane & 3)*2;
            #pragma unroll
            for (int e = 0; e < 2; e++) {
                int j = j0 + cb + e;
                float ukv = uks[j];
                {
                    int d = j - ig0;
                    int a = d < 0 ? -d : d;
                    int t = tms[a];
                    float sg = (float)((d > 0) - (d < 0));
                    sacc[nt][e] += suR0[t] + sg * ssR0[t] + ukv;
                    mx0 = fmaxf(mx0, sacc[nt][e]);
                }
                {
                    int d = j - ig1;
                    int a = d < 0 ? -d : d;
                    int t = tms[a];
                    float sg = (float)((d > 0) - (d < 0));
                    sacc[nt][2 + e] += suR1[t] + sg * ssR1[t] + ukv;
                    mx1 = fmaxf(mx1, sacc[nt][2 + e]);
                }
            }
        }
        mx0 = fmaxf(mx0, __shfl_xor_sync(0xffffffffu, mx0, 1));
        mx0 = fmaxf(mx0, __shfl_xor_sync(0xffffffffu, mx0, 2));
        mx1 = fmaxf(mx1, __shfl_xor_sync(0xffffffffu, mx1, 1));
        mx1 = fmaxf(mx1, __shfl_xor_sync(0xffffffffu, mx1, 2));
        float mn0 = fmaxf(m0, mx0), mn1 = fmaxf(m1, mx1);
        float al0 = __expf(m0 - mn0), al1 = __expf(m1 - mn1);
        m0 = mn0; m1 = mn1;
        float sum0 = 0.f, sum1 = 0.f;
        #pragma unroll
        for (int nt = 0; nt < 16; nt++) {
            #pragma unroll
            for (int e = 0; e < 2; e++) {
                sacc[nt][e]     = __expf(sacc[nt][e]     - mn0); sum0 += sacc[nt][e];
                sacc[nt][2 + e] = __expf(sacc[nt][2 + e] - mn1); sum1 += sacc[nt][2 + e];
            }
        }
        sum0 += __shfl_xor_sync(0xffffffffu, sum0, 1);
        sum0 += __shfl_xor_sync(0xffffffffu, sum0, 2);
        sum1 += __shfl_xor_sync(0xffffffffu, sum1, 1);
        sum1 += __shfl_xor_sync(0xffffffffu, sum1, 2);
        l0 = l0 * al0 + sum0;
        l1 = l1 * al1 + sum1;
        #pragma unroll
        for (int ot = 0; ot < 8; ot++) {
            oacc[ot][0] *= al0; oacc[ot][1] *= al0;
            oacc[ot][2] *= al1; oacc[ot][3] *= al1;
        }

        #pragma unroll
        for (int kt = 0; kt < 8; kt++) {
            uint32_t pH[4], pL[4];
            split2(sacc[2*kt][0],     sacc[2*kt][1],     pH[0], pL[0]);
            split2(sacc[2*kt][2],     sacc[2*kt][3],     pH[1], pL[1]);
            split2(sacc[2*kt + 1][0], sacc[2*kt + 1][1], pH[2], pL[2]);
            split2(sacc[2*kt + 1][2], sacc[2*kt + 1][3], pH[3], pL[3]);
            #pragma unroll
            for (int bt = 0; bt < 4; bt++) {
                int vrow = bt*16 + lr;
                uint32_t voff = vrow * 256 + (((kt*2 + lk8) ^ (vrow & 15)) << 4);
                uint32_t vH[4], vL[4];
                ldsm_x4(vH[0], vH[1], vH[2], vH[3], st + 32768 + voff);
                ldsm_x4(vL[0], vL[1], vL[2], vL[3], st + 49152 + voff);
                #pragma unroll
                for (int hi = 0; hi < 2; hi++) {
                    mma_bf16(oacc[bt*2 + hi], pH, vH[hi], vH[hi + 2]);
                    mma_bf16(oacc[bt*2 + hi], pH, vL[hi], vL[hi + 2]);
                    mma_bf16(oacc[bt*2 + hi], pL, vH[hi], vH[hi + 2]);
                }
            }
        }
        __syncthreads();
    }

    float inv0 = 1.f / l0, inv1 = 1.f / l1;
    #pragma unroll
    for (int ot = 0; ot < 8; ot++) {
        int col = ot*8 + (lane & 3)*2;
        size_t p0 = (size_t)(b*LL + ig0) * HD + h*64 + col;
        size_t p1 = (size_t)(b*LL + ig1) * HD + h*64 + col;
        uint32_t h0, lo0, h1, lo1;
        split2(oacc[ot][0]*inv0, oacc[ot][1]*inv0, h0, lo0);
        split2(oacc[ot][2]*inv1, oacc[ot][3]*inv1, h1, lo1);
        *(uint32_t*)(g_aohi + p0) = h0;
        *(uint32_t*)(g_aolo + p0) = lo0;
        *(uint32_t*)(g_aohi + p1) = h1;
        *(uint32_t*)(g_aolo + p1) = lo1;
    }
}

// ---------------------------------------------------------------------------
extern "C" void kernel_launch(void* const* d_in, const int* in_sizes, int n_in,
                              void* d_out, int out_size) {
    const float* x  = (const float*)d_in[0];
    const float* Wq = (const float*)d_in[1];
    const float* Wk = (const float*)d_in[2];
    const float* Wv = (const float*)d_in[3];
    const float* Wo = (const float*)d_in[4];
    const float* bo = (const float*)d_in[5];
    const float* ub = (const float*)d_in[6];
    const float* vb = (const float*)d_in[7];
    const float* wp = (const float*)d_in[8];
    float* out = (float*)d_out;

    prep_kernel<<<1, 256>>>(vb, wp);
    wtrans_kernel<<<128, 256>>>(wp);
    conv_all_kernel<<<3072, 256>>>(x, Wq, Wk, Wv, Wo);

    cudaFuncSetAttribute(qkv_mma_kernel, cudaFuncAttributeMaxDynamicSharedMemorySize, GEMM_SMEM);
    cudaFuncSetAttribute(out_mma_kernel, cudaFuncAttributeMaxDynamicSharedMemorySize, GEMM_SMEM);

    qkv_mma_kernel<<<dim3(16, 24), 256, GEMM_SMEM>>>();

    vtrans_kernel<<<dim3(8, HH, BB), 256>>>();
    uk_kernel<<<64, 256>>>(ub);

    cudaFuncSetAttribute(qw_suffix_kernel, cudaFuncAttributeMaxDynamicSharedMemorySize, QW_SMEM);
    qw_suffix_kernel<<<dim3(8, HH, BB), 256, QW_SMEM>>>();

    cudaFuncSetAttribute(attn_kernel, cudaFuncAttributeMaxDynamicSharedMemorySize, ATTN_SMEM);
    attn_kernel<<<dim3(LL/128, HH, BB), 256, ATTN_SMEM>>>();

    out_mma_kernel<<<dim3(16, 12), 256, GEMM_SMEM>>>(bo, out);
}

// round 17
// speedup vs baseline: 4.9768x; 1.0721x over previous
#include <cuda_runtime.h>
#include <cuda_bf16.h>
#include <math.h>
#include <stdint.h>

#define BB 2
#define LL 1024
#define HH 8
#define DD 64
#define DMM 768
#define HD 512

typedef unsigned long long u64;

// ---------------- mma.sync / cp.async helpers (baseline ISA) ---------------
__device__ __forceinline__ uint32_t smem_u32(const void* p) {
    uint32_t a;
    asm("{ .reg .u64 t; cvta.to.shared.u64 t, %1; cvt.u32.u64 %0, t; }"
        : "=r"(a) : "l"(p));
    return a;
}
__device__ __forceinline__ void ldsm_x4(uint32_t& r0, uint32_t& r1,
                                        uint32_t& r2, uint32_t& r3, uint32_t addr) {
    asm volatile("ldmatrix.sync.aligned.m8n8.x4.shared.b16 {%0,%1,%2,%3}, [%4];"
                 : "=r"(r0), "=r"(r1), "=r"(r2), "=r"(r3) : "r"(addr));
}
__device__ __forceinline__ void mma_bf16(float* c, const uint32_t* a,
                                         uint32_t b0, uint32_t b1) {
    asm volatile(
        "mma.sync.aligned.m16n8k16.row.col.f32.bf16.bf16.f32 "
        "{%0,%1,%2,%3}, {%4,%5,%6,%7}, {%8,%9}, {%0,%1,%2,%3};"
        : "+f"(c[0]), "+f"(c[1]), "+f"(c[2]), "+f"(c[3])
        : "r"(a[0]), "r"(a[1]), "r"(a[2]), "r"(a[3]), "r"(b0), "r"(b1));
}
__device__ __forceinline__ void split2(float a, float b, uint32_t& hi, uint32_t& lo) {
    __nv_bfloat16 ha = __float2bfloat16(a), hb = __float2bfloat16(b);
    __nv_bfloat16 la = __float2bfloat16(a - __bfloat162float(ha));
    __nv_bfloat16 lb = __float2bfloat16(b - __bfloat162float(hb));
    hi = (uint32_t)*(unsigned short*)&ha | ((uint32_t)*(unsigned short*)&hb << 16);
    lo = (uint32_t)*(unsigned short*)&la | ((uint32_t)*(unsigned short*)&lb << 16);
}
__device__ __forceinline__ void cp16(uint32_t dst, const void* src) {
    asm volatile("cp.async.cg.shared.global [%0], [%1], 16;" :: "r"(dst), "l"(src));
}
#define CP_COMMIT() asm volatile("cp.async.commit_group;" ::: "memory")
#define CP_WAIT1()  asm volatile("cp.async.wait_group 1;" ::: "memory")
#define CP_WAIT0()  asm volatile("cp.async.wait_group 0;" ::: "memory")

// ---------------- scratch (static device globals; no allocs) ----------------
__device__ float g_Su[BB*HH*LL*33];
__device__ float g_Ss[BB*HH*LL*33];
__device__ float g_uk[BB*HH*LL];
__device__ float g_Vu[HH*33];      // pre-scaled x0.125
__device__ float g_Vsg[HH*33];     // pre-scaled x0.125
__device__ int   g_tmin[LL];

__device__ __align__(16) __nv_bfloat16 g_xhi [BB*LL*DMM];
__device__ __align__(16) __nv_bfloat16 g_xlo [BB*LL*DMM];
__device__ __align__(16) __nv_bfloat16 g_whi [3*HD*DMM];
__device__ __align__(16) __nv_bfloat16 g_wlo [3*HD*DMM];
__device__ __align__(16) __nv_bfloat16 g_wohi[DMM*HD];
__device__ __align__(16) __nv_bfloat16 g_wolo[DMM*HD];
__device__ __align__(16) __nv_bfloat16 g_aohi[BB*LL*HD];
__device__ __align__(16) __nv_bfloat16 g_aolo[BB*LL*HD];
__device__ __align__(16) __nv_bfloat16 g_qh[BB*LL*HD];   // q x0.125 split
__device__ __align__(16) __nv_bfloat16 g_ql[BB*LL*HD];
__device__ __align__(16) __nv_bfloat16 g_kh[BB*LL*HD];
__device__ __align__(16) __nv_bfloat16 g_kl[BB*LL*HD];
__device__ __align__(16) __nv_bfloat16 g_vh[BB*LL*HD];
__device__ __align__(16) __nv_bfloat16 g_vl[BB*LL*HD];
__device__ __align__(16) __nv_bfloat16 g_wth[HH*64*64];  // w_pos^T [h][n][d] split
__device__ __align__(16) __nv_bfloat16 g_wtl[HH*64*64];
__device__ __align__(16) __nv_bfloat16 g_vth[BB*HH*64*LL]; // V^T [b][h][dv][j]
__device__ __align__(16) __nv_bfloat16 g_vtl[BB*HH*64*LL];

// ---------------- fused f32 -> bf16 hi/lo split for x + 4 weights ----------
__global__ __launch_bounds__(256)
void conv_all_kernel(const float* __restrict__ x,  const float* __restrict__ Wq,
                     const float* __restrict__ Wk, const float* __restrict__ Wv,
                     const float* __restrict__ Wo) {
    int bi = blockIdx.x;
    const float* src;
    __nv_bfloat16 *hi, *lo;
    int lb;
    if (bi < 1536)      { src = x;  hi = g_xhi;            lo = g_xlo;            lb = bi; }
    else if (bi < 1920) { src = Wq; hi = g_whi;            lo = g_wlo;            lb = bi - 1536; }
    else if (bi < 2304) { src = Wk; hi = g_whi + HD*DMM;   lo = g_wlo + HD*DMM;   lb = bi - 1920; }
    else if (bi < 2688) { src = Wv; hi = g_whi + 2*HD*DMM; lo = g_wlo + 2*HD*DMM; lb = bi - 2304; }
    else                { src = Wo; hi = g_wohi;           lo = g_wolo;           lb = bi - 2688; }
    int i = lb * 256 + threadIdx.x;
    float4 v = ((const float4*)src)[i];
    uint32_t h0, l0, h1, l1;
    split2(v.x, v.y, h0, l0);
    split2(v.z, v.w, h1, l1);
    ((uint32_t*)hi)[2*i]     = h0;
    ((uint32_t*)hi)[2*i + 1] = h1;
    ((uint32_t*)lo)[2*i]     = l0;
    ((uint32_t*)lo)[2*i + 1] = l1;
}

// ------- pipelined mma.sync bf16-split GEMM: 128x64 tile, 2 blocks/SM ------
// Warps 4(M) x 2(N); warp tile 32x32. cp.async double-buffer, K-chunk 64.
// Stage = AH 16K | AL 16K | BH 8K | BL 8K = 48KB; 2 stages = 96KB.
#define G_STAGE 49152
#define GEMM_SMEM 98304

__device__ __forceinline__ void gemm_issue(
    const __nv_bfloat16* __restrict__ Ahi, const __nv_bfloat16* __restrict__ Alo,
    const __nv_bfloat16* __restrict__ Bhi, const __nv_bfloat16* __restrict__ Blo,
    int Kt, int k0, uint32_t sbase, int tid)
{
    #pragma unroll
    for (int u = 0; u < 12; u++) {
        int e = tid + u * 256;
        if (e < 2048) {
            int t = e >> 10, rem = e & 1023;
            int row = rem >> 3, seg = rem & 7;
            const __nv_bfloat16* s = (t ? Alo : Ahi) + (size_t)row * Kt + k0 + seg * 8;
            cp16(sbase + t * 16384 + row * 128 + ((seg ^ (row & 7)) << 4), s);
        } else {
            int e2 = e - 2048;
            int t = e2 >> 9, rem = e2 & 511;
            int row = rem >> 3, seg = rem & 7;
            const __nv_bfloat16* s = (t ? Blo : Bhi) + (size_t)row * Kt + k0 + seg * 8;
            cp16(sbase + 32768 + t * 8192 + row * 128 + ((seg ^ (row & 7)) << 4), s);
        }
    }
    CP_COMMIT();
}

__device__ __forceinline__ void gemm_mma_body(
    const __nv_bfloat16* __restrict__ Ahi, const __nv_bfloat16* __restrict__ Alo,
    const __nv_bfloat16* __restrict__ Bhi, const __nv_bfloat16* __restrict__ Blo,
    int Kt, float* __restrict__ Cout, __nv_bfloat16* __restrict__ Chi,
    __nv_bfloat16* __restrict__ Clo, float sc, int Cstride,
    const float* __restrict__ bias)
{
    extern __shared__ char gsm[];
    const uint32_t sb = smem_u32(gsm);
    const int tid = threadIdx.x;
    const int wid = tid >> 5, lane = tid & 31;
    const int wm = wid >> 1, wn = wid & 1;          // 4 x 2 warp grid

    float acc[2][4][4];
    #pragma unroll
    for (int mt = 0; mt < 2; mt++)
        #pragma unroll
        for (int nt = 0; nt < 4; nt++)
            #pragma unroll
            for (int r = 0; r < 4; r++) acc[mt][nt][r] = 0.f;

    const int lr  = lane & 15;
    const int lk8 = lane >> 4;
    const int NCH = Kt >> 6;

    gemm_issue(Ahi, Alo, Bhi, Blo, Kt, 0, sb, tid);

    for (int ch = 0; ch < NCH; ch++) {
        if (ch + 1 < NCH) {
            gemm_issue(Ahi, Alo, Bhi, Blo, Kt, (ch + 1) << 6,
                       sb + ((ch + 1) & 1) * G_STAGE, tid);
            CP_WAIT1();
        } else {
            CP_WAIT0();
        }
        __syncthreads();
        const uint32_t st = sb + (ch & 1) * G_STAGE;

        #pragma unroll
        for (int ks = 0; ks < 4; ks++) {
            const int kseg = (ks << 1) + lk8;
            uint32_t ah[2][4], al[2][4];
            #pragma unroll
            for (int mt = 0; mt < 2; mt++) {
                int row = wm * 32 + mt * 16 + lr;
                uint32_t off = row * 128 + (((kseg ^ (row & 7))) << 4);
                ldsm_x4(ah[mt][0], ah[mt][1], ah[mt][2], ah[mt][3], st + off);
                ldsm_x4(al[mt][0], al[mt][1], al[mt][2], al[mt][3], st + 16384 + off);
            }
            uint32_t bh[2][4], bl[2][4];
            #pragma unroll
            for (int bt = 0; bt < 2; bt++) {
                int row = wn * 32 + bt * 16 + lr;
                uint32_t off = row * 128 + (((kseg ^ (row & 7))) << 4);
                ldsm_x4(bh[bt][0], bh[bt][1], bh[bt][2], bh[bt][3], st + 32768 + off);
                ldsm_x4(bl[bt][0], bl[bt][1], bl[bt][2], bl[bt][3], st + 40960 + off);
            }
            #pragma unroll
            for (int mt = 0; mt < 2; mt++) {
                #pragma unroll
                for (int nt = 0; nt < 4; nt++) {
                    int bt = nt >> 1, hi = nt & 1;
                    mma_bf16(acc[mt][nt], ah[mt], bh[bt][hi], bh[bt][hi + 2]);
                    mma_bf16(acc[mt][nt], ah[mt], bl[bt][hi], bl[bt][hi + 2]);
                    mma_bf16(acc[mt][nt], al[mt], bh[bt][hi], bh[bt][hi + 2]);
                }
            }
        }
        __syncthreads();
    }

    const int er = lane >> 2, ec = (lane & 3) << 1;
    #pragma unroll
    for (int mt = 0; mt < 2; mt++) {
        #pragma unroll
        for (int nt = 0; nt < 4; nt++) {
            int m = wm * 32 + mt * 16 + er;
            int n = wn * 32 + nt * 8 + ec;
            float b0 = 0.f, b1 = 0.f;
            if (bias) { b0 = bias[n]; b1 = bias[n + 1]; }
            float v0 = acc[mt][nt][0] + b0, v1 = acc[mt][nt][1] + b1;
            float v2 = acc[mt][nt][2] + b0, v3 = acc[mt][nt][3] + b1;
            if (Cout) {
                *(float2*)(Cout + (size_t)m * Cstride + n)       = make_float2(v0, v1);
                *(float2*)(Cout + (size_t)(m + 8) * Cstride + n) = make_float2(v2, v3);
            }
            if (Chi) {
                uint32_t h0, l0, h1, l1;
                split2(v0 * sc, v1 * sc, h0, l0);
                split2(v2 * sc, v3 * sc, h1, l1);
                *(uint32_t*)(Chi + (size_t)m * Cstride + n)       = h0;
                *(uint32_t*)(Clo + (size_t)m * Cstride + n)       = l0;
                *(uint32_t*)(Chi + (size_t)(m + 8) * Cstride + n) = h1;
                *(uint32_t*)(Clo + (size_t)(m + 8) * Cstride + n) = l1;
            }
        }
    }
}

// QKV: grid (16 M-tiles, 24 N-tiles of 64 over concatenated 1536)
__global__ __launch_bounds__(256, 2)
void qkv_mma_kernel() {
    int m0 = blockIdx.x * 128;
    int nglob = blockIdx.y * 64;
    int sel = nglob >> 9, ncol = nglob & 511;
    size_t co = (size_t)m0 * HD + ncol;
    __nv_bfloat16* hb = (sel == 0 ? g_qh : (sel == 1 ? g_kh : g_vh)) + co;
    __nv_bfloat16* lb = (sel == 0 ? g_ql : (sel == 1 ? g_kl : g_vl)) + co;
    float sc = sel == 0 ? 0.125f : 1.f;
    gemm_mma_body(g_xhi + (size_t)m0 * DMM, g_xlo + (size_t)m0 * DMM,
                  g_whi + (size_t)nglob * DMM, g_wlo + (size_t)nglob * DMM,
                  DMM, nullptr, hb, lb, sc, HD, nullptr);
}

// out: grid (16 M-tiles, 12 N-tiles of 64 over 768)
__global__ __launch_bounds__(256, 2)
void out_mma_kernel(const float* __restrict__ bo, float* __restrict__ out) {
    int m0 = blockIdx.x * 128;
    int n0 = blockIdx.y * 64;
    gemm_mma_body(g_aohi + (size_t)m0 * HD, g_aolo + (size_t)m0 * HD,
                  g_wohi + (size_t)n0 * HD, g_wolo + (size_t)n0 * HD,
                  HD, out + (size_t)m0 * DMM + n0, nullptr, nullptr, 1.f,
                  DMM, bo + n0);
}

// ---------------- prep: tmin LUT + per-head Vu/Vsg (x0.125) ----------------
__global__ void prep_kernel(const float* __restrict__ v_bias,
                            const float* __restrict__ w_pos) {
    __shared__ double cw[32];
    __shared__ float  vws[512];
    int tid = threadIdx.x;
    if (tid < 32)
        cw[tid] = exp((double)(tid + 1) * log((double)(LL + 1) / 2.0) / 32.0);
    __syncthreads();
    for (int a = tid; a < LL; a += 256) {
        int t = 32;
        for (int j = 31; j >= 0; j--) if ((double)a <= cw[j]) t = j;
        g_tmin[a] = t;
    }
    for (int o = tid; o < 512; o += 256) {
        int h = o >> 6, n = o & 63;
        float s = 0.f;
        for (int d = 0; d < 64; d++)
            s += v_bias[h*64 + d] * w_pos[h*4096 + d*64 + n];
        vws[o] = s;
    }
    __syncthreads();
    if (tid < 16) {
        int h = tid >> 1, sg = tid & 1;
        float run = 0.f;
        float* dst = (sg ? g_Vsg : g_Vu) + h*33;
        dst[32] = 0.f;
        for (int t = 31; t >= 0; t--) {
            run += vws[h*64 + sg*32 + t];
            dst[t] = run * 0.125f;
        }
    }
}

// w_pos^T bf16 split: [h][d][n] -> [h][n][d]
__global__ __launch_bounds__(256)
void wtrans_kernel(const float* __restrict__ w_pos) {
    int idx = blockIdx.x * 256 + threadIdx.x;       // 32768
    int h = idx >> 12, rem = idx & 4095;
    int n = rem >> 6, d = rem & 63;
    float v = w_pos[h*4096 + d*64 + n];
    __nv_bfloat16 hi = __float2bfloat16(v);
    __nv_bfloat16 lo = __float2bfloat16(v - __bfloat162float(hi));
    g_wth[idx] = hi;
    g_wtl[idx] = lo;
}

// uk[b,h,j] = u . (kh+kl)
__global__ __launch_bounds__(256)
void uk_kernel(const float* __restrict__ u_bias) {
    int idx = blockIdx.x * 256 + threadIdx.x;       // 16384
    int b = idx >> 13, rem = idx & 8191;
    int h = rem >> 10, j = rem & 1023;
    const __nv_bfloat16* kh = g_kh + (size_t)(b*LL + j) * HD + h*64;
    const __nv_bfloat16* kl = g_kl + (size_t)(b*LL + j) * HD + h*64;
    const float* u = u_bias + h*64;
    float s = 0.f;
    #pragma unroll
    for (int d = 0; d < 64; d++)
        s += (__bfloat162float(kh[d]) + __bfloat162float(kl[d])) * u[d];
    g_uk[idx] = s;
}

// V^T: [b][j][h][dv] -> [b][h][dv][j] (hi & lo)
__global__ __launch_bounds__(256)
void vtrans_kernel() {
    __shared__ unsigned short sh[128*72], sl[128*72];
    const int b = blockIdx.z, h = blockIdx.y;
    const int j0 = blockIdx.x * 128;
    const int tid = threadIdx.x;
    for (int x = tid; x < 1024; x += 256) {
        int j = x >> 3, seg = x & 7;
        size_t src = (size_t)(b*LL + j0 + j) * HD + h*64 + seg*8;
        *(uint4*)(sh + j*72 + seg*8) = *(const uint4*)(g_vh + src);
        *(uint4*)(sl + j*72 + seg*8) = *(const uint4*)(g_vl + src);
    }
    __syncthreads();
    for (int x = tid; x < 1024; x += 256) {
        int dv = x >> 4, jw = x & 15;
        unsigned short oh[8], ol[8];
        #pragma unroll
        for (int e = 0; e < 8; e++) {
            oh[e] = sh[(jw*8 + e)*72 + dv];
            ol[e] = sl[(jw*8 + e)*72 + dv];
        }
        size_t dst = ((size_t)(b*HH + h)*64 + dv)*LL + j0 + jw*8;
        *(uint4*)(g_vth + dst) = *(uint4*)oh;
        *(uint4*)(g_vtl + dst) = *(uint4*)ol;
    }
}

// -------- qw via mma + suffix sums: one block per (b, h, 128 i-rows) -------
#define QW_QH 0
#define QW_QL 16384
#define QW_WH 32768
#define QW_WL 40960
#define QW_QW 49152          // fp32 [128][65]
#define QW_SMEM (49152 + 128*65*4)

__global__ __launch_bounds__(256)
void qw_suffix_kernel() {
    extern __shared__ char qsm[];
    const uint32_t sb = smem_u32(qsm);
    float* qws = (float*)(qsm + QW_QW);
    const int b = blockIdx.z, h = blockIdx.y;
    const int i0 = blockIdx.x * 128;
    const int tid = threadIdx.x;
    const int wid = tid >> 5, lane = tid & 31;
    const int lr = lane & 15, lk8 = lane >> 4;

    {
        const __nv_bfloat16* qh = g_qh + (size_t)(b*LL + i0) * HD + h*64;
        const __nv_bfloat16* ql = g_ql + (size_t)(b*LL + i0) * HD + h*64;
        for (int x = tid; x < 1024; x += 256) {
            int row = x >> 3, seg = x & 7;
            uint32_t off = row * 128 + ((seg ^ (row & 7)) << 4);
            *(uint4*)(qsm + QW_QH + off) = *(const uint4*)(qh + (size_t)row*HD + seg*8);
            *(uint4*)(qsm + QW_QL + off) = *(const uint4*)(ql + (size_t)row*HD + seg*8);
        }
        const __nv_bfloat16* wth = g_wth + h*4096;
        const __nv_bfloat16* wtl = g_wtl + h*4096;
        for (int x = tid; x < 512; x += 256) {
            int row = x >> 3, seg = x & 7;
            uint32_t off = row * 128 + ((seg ^ (row & 7)) << 4);
            *(uint4*)(qsm + QW_WH + off) = *(const uint4*)(wth + row*64 + seg*8);
            *(uint4*)(qsm + QW_WL + off) = *(const uint4*)(wtl + row*64 + seg*8);
        }
    }
    __syncthreads();

    float sacc[8][4];
    #pragma unroll
    for (int p = 0; p < 8; p++)
        #pragma unroll
        for (int r = 0; r < 4; r++) sacc[p][r] = 0.f;

    #pragma unroll
    for (int ks = 0; ks < 4; ks++) {
        const int kseg = (ks << 1) + lk8;
        int arow = wid*16 + lr;
        uint32_t aoff = arow * 128 + ((kseg ^ (arow & 7)) << 4);
        uint32_t aH[4], aL[4];
        ldsm_x4(aH[0], aH[1], aH[2], aH[3], sb + QW_QH + aoff);
        ldsm_x4(aL[0], aL[1], aL[2], aL[3], sb + QW_QL + aoff);
        #pragma unroll
        for (int bt = 0; bt < 4; bt++) {
            int brow = bt*16 + lr;
            uint32_t boff = brow * 128 + ((kseg ^ (brow & 7)) << 4);
            uint32_t bH[4], bL[4];
            ldsm_x4(bH[0], bH[1], bH[2], bH[3], sb + QW_WH + boff);
            ldsm_x4(bL[0], bL[1], bL[2], bL[3], sb + QW_WL + boff);
            #pragma unroll
            for (int hi = 0; hi < 2; hi++) {
                mma_bf16(sacc[bt*2 + hi], aH, bH[hi], bH[hi + 2]);
                mma_bf16(sacc[bt*2 + hi], aH, bL[hi], bL[hi + 2]);
                mma_bf16(sacc[bt*2 + hi], aL, bH[hi], bH[hi + 2]);
            }
        }
    }

    const int er = lane >> 2, ec = (lane & 3) << 1;
    #pragma unroll
    for (int p = 0; p < 8; p++) {
        int r0 = wid*16 + er, n = p*8 + ec;
        qws[r0*65 + n]       = sacc[p][0];
        qws[r0*65 + n + 1]   = sacc[p][1];
        qws[(r0+8)*65 + n]     = sacc[p][2];
        qws[(r0+8)*65 + n + 1] = sacc[p][3];
    }
    __syncthreads();

    {
        int r = tid >> 1, sg = tid & 1;
        float* dst = (sg ? g_Ss : g_Su) + (size_t)((b*HH + h)*LL + i0 + r) * 33;
        float run = 0.f;
        dst[32] = 0.f;
        const float* src = qws + r*65 + sg*32;
        #pragma unroll
        for (int t = 31; t >= 0; t--) { run += src[t]; dst[t] = run; }
    }
}

// ---------------- flash attention via mma.sync, pipelined K/V ---------------
#define A_QH   0
#define A_QL   16384
#define A_STG0 32768             // stage: KH(16K) KL(16K) VTH(16K) VTL(16K)
#define A_STG1 98304
#define A_SUS  163840            // 128*33 f32
#define A_SSS  180736
#define A_UKS  197632            // 1024 f32 (full row, pre-scaled)
#define A_TMS  201728            // 1024 int
#define ATTN_SMEM 205824

__device__ __forceinline__ void attn_issue_chunk(
    const __nv_bfloat16* kh, const __nv_bfloat16* kl,
    const __nv_bfloat16* vth, const __nv_bfloat16* vtl,
    int j0, uint32_t sbase, int tid)
{
    #pragma unroll
    for (int u = 0; u < 16; u++) {
        int e = tid + u * 256;
        int t = e >> 10, rem = e & 1023;
        if (t < 2) {
            int row = rem >> 3, seg = rem & 7;
            const __nv_bfloat16* s = (t == 0 ? kh : kl) + (size_t)(j0 + row) * HD + seg * 8;
            cp16(sbase + t * 16384 + row * 128 + ((seg ^ (row & 7)) << 4), s);
        } else {
            int row = rem >> 4, seg = rem & 15;
            const __nv_bfloat16* s = (t == 2 ? vth : vtl) + (size_t)row * LL + j0 + seg * 8;
            cp16(sbase + t * 16384 + row * 256 + ((seg ^ (row & 15)) << 4), s);
        }
    }
    CP_COMMIT();
}

__global__ __launch_bounds__(256, 1)
void attn_kernel() {
    extern __shared__ char smc[];
    const uint32_t sb = smem_u32(smc);
    float* Sus = (float*)(smc + A_SUS);
    float* Sss = (float*)(smc + A_SSS);
    float* uks = (float*)(smc + A_UKS);
    int*   tms = (int*)  (smc + A_TMS);

    const int b = blockIdx.z, h = blockIdx.y;
    const int i0 = blockIdx.x * 128;
    const int tid = threadIdx.x;
    const int wid = tid >> 5, lane = tid & 31;
    const int lr = lane & 15, lk8 = lane >> 4;

    const __nv_bfloat16* kh_g  = g_kh + (size_t)(b*LL) * HD + h*64;
    const __nv_bfloat16* kl_g  = g_kl + (size_t)(b*LL) * HD + h*64;
    const __nv_bfloat16* vth_g = g_vth + ((size_t)(b*HH + h)*64)*LL;
    const __nv_bfloat16* vtl_g = g_vtl + ((size_t)(b*HH + h)*64)*LL;

    attn_issue_chunk(kh_g, kl_g, vth_g, vtl_g, 0, sb + A_STG0, tid);

    {
        const __nv_bfloat16* qh = g_qh + (size_t)(b*LL + i0) * HD + h*64;
        const __nv_bfloat16* ql = g_ql + (size_t)(b*LL + i0) * HD + h*64;
        for (int x = tid; x < 1024; x += 256) {
            int row = x >> 3, seg = x & 7;
            uint32_t off = row * 128 + ((seg ^ (row & 7)) << 4);
            *(uint4*)(smc + A_QH + off) = *(const uint4*)(qh + (size_t)row*HD + seg*8);
            *(uint4*)(smc + A_QL + off) = *(const uint4*)(ql + (size_t)row*HD + seg*8);
        }
        const float* sub = g_Su + (size_t)((b*HH + h)*LL + i0) * 33;
        const float* ssb = g_Ss + (size_t)((b*HH + h)*LL + i0) * 33;
        const float* vu  = g_Vu  + h*33;
        const float* vsg = g_Vsg + h*33;
        for (int x = tid; x < 128*33; x += 256) {
            int t = x % 33;
            Sus[x] = sub[x] + vu[t];
            Sss[x] = ssb[x] + vsg[t];
        }
        const float* ukg = g_uk + (size_t)(b*HH + h)*LL;
        for (int x = tid; x < LL; x += 256) {
            tms[x] = g_tmin[x];
            uks[x] = ukg[x] * 0.125f;
        }
    }

    float m0 = -INFINITY, m1 = -INFINITY, l0 = 0.f, l1 = 0.f;
    float oacc[8][4];
    #pragma unroll
    for (int ot = 0; ot < 8; ot++)
        #pragma unroll
        for (int r = 0; r < 4; r++) oacc[ot][r] = 0.f;

    const int r0 = wid*16 + (lane >> 2);
    const int ig0 = i0 + r0, ig1 = ig0 + 8;
    const float* suR0 = Sus + r0*33;
    const float* ssR0 = Sss + r0*33;
    const float* suR1 = suR0 + 8*33;
    const float* ssR1 = ssR0 + 8*33;

    for (int jt = 0; jt < 8; jt++) {
        const int j0 = jt * 128;
        if (jt + 1 < 8) {
            attn_issue_chunk(kh_g, kl_g, vth_g, vtl_g, j0 + 128,
                             sb + (((jt + 1) & 1) ? A_STG1 : A_STG0), tid);
            CP_WAIT1();
        } else {
            CP_WAIT0();
        }
        __syncthreads();
        const uint32_t st = sb + ((jt & 1) ? A_STG1 : A_STG0);

        float sacc[16][4];
        #pragma unroll
        for (int nt = 0; nt < 16; nt++)
            #pragma unroll
            for (int r = 0; r < 4; r++) sacc[nt][r] = 0.f;

        #pragma unroll
        for (int ks = 0; ks < 4; ks++) {
            const int kseg = (ks << 1) + lk8;
            int arow = wid*16 + lr;
            uint32_t aoff = arow * 128 + ((kseg ^ (arow & 7)) << 4);
            uint32_t aH[4], aL[4];
            ldsm_x4(aH[0], aH[1], aH[2], aH[3], sb + A_QH + aoff);
            ldsm_x4(aL[0], aL[1], aL[2], aL[3], sb + A_QL + aoff);
            #pragma unroll
            for (int bt = 0; bt < 8; bt++) {
                int brow = bt*16 + lr;
                uint32_t boff = brow * 128 + ((kseg ^ (brow & 7)) << 4);
                uint32_t bH[4], bL[4];
                ldsm_x4(bH[0], bH[1], bH[2], bH[3], st + boff);
                ldsm_x4(bL[0], bL[1], bL[2], bL[3], st + 16384 + boff);
                #pragma unroll
                for (int hi = 0; hi < 2; hi++) {
                    mma_bf16(sacc[bt*2 + hi], aH, bH[hi], bH[hi + 2]);
                    mma_bf16(sacc[bt*2 + hi], aH, bL[hi], bL[hi + 2]);
                    mma_bf16(sacc[bt*2 + hi], aL, bH[hi], bH[hi + 2]);
                }
            }
        }

        float mx0 = -INFINITY, mx1 = -INFINITY;
        #pragma unroll
        for (int nt = 0; nt < 16; nt++) {
            int cb = nt*8 + (lane & 3)*2;
            #pragma unroll
            for (int e = 0; e < 2; e++) {
                int j = j0 + cb + e;
                float ukv = uks[j];
                {
                    int d = j - ig0;
                    int a = d < 0 ? -d : d;
                    int t = tms[a];
                    float sg = (float)((d > 0) - (d < 0));
                    sacc[nt][e] += suR0[t] + sg * ssR0[t] + ukv;
                    mx0 = fmaxf(mx0, sacc[nt][e]);
                }
                {
                    int d = j - ig1;
                    int a = d < 0 ? -d : d;
                    int t = tms[a];
                    float sg = (float)((d > 0) - (d < 0));
                    sacc[nt][2 + e] += suR1[t] + sg * ssR1[t] + ukv;
                    mx1 = fmaxf(mx1, sacc[nt][2 + e]);
                }
            }
        }
        mx0 = fmaxf(mx0, __shfl_xor_sync(0xffffffffu, mx0, 1));
        mx0 = fmaxf(mx0, __shfl_xor_sync(0xffffffffu, mx0, 2));
        mx1 = fmaxf(mx1, __shfl_xor_sync(0xffffffffu, mx1, 1));
        mx1 = fmaxf(mx1, __shfl_xor_sync(0xffffffffu, mx1, 2));
        float mn0 = fmaxf(m0, mx0), mn1 = fmaxf(m1, mx1);
        float al0 = __expf(m0 - mn0), al1 = __expf(m1 - mn1);
        m0 = mn0; m1 = mn1;
        float sum0 = 0.f, sum1 = 0.f;
        #pragma unroll
        for (int nt = 0; nt < 16; nt++) {
            #pragma unroll
            for (int e = 0; e < 2; e++) {
                sacc[nt][e]     = __expf(sacc[nt][e]     - mn0); sum0 += sacc[nt][e];
                sacc[nt][2 + e] = __expf(sacc[nt][2 + e] - mn1); sum1 += sacc[nt][2 + e];
            }
        }
        sum0 += __shfl_xor_sync(0xffffffffu, sum0, 1);
        sum0 += __shfl_xor_sync(0xffffffffu, sum0, 2);
        sum1 += __shfl_xor_sync(0xffffffffu, sum1, 1);
        sum1 += __shfl_xor_sync(0xffffffffu, sum1, 2);
        l0 = l0 * al0 + sum0;
        l1 = l1 * al1 + sum1;
        #pragma unroll
        for (int ot = 0; ot < 8; ot++) {
            oacc[ot][0] *= al0; oacc[ot][1] *= al0;
            oacc[ot][2] *= al1; oacc[ot][3] *= al1;
        }

        #pragma unroll
        for (int kt = 0; kt < 8; kt++) {
            uint32_t pH[4], pL[4];
            split2(sacc[2*kt][0],     sacc[2*kt][1],     pH[0], pL[0]);
            split2(sacc[2*kt][2],     sacc[2*kt][3],     pH[1], pL[1]);
            split2(sacc[2*kt + 1][0], sacc[2*kt + 1][1], pH[2], pL[2]);
            split2(sacc[2*kt + 1][2], sacc[2*kt + 1][3], pH[3], pL[3]);
            #pragma unroll
            for (int bt = 0; bt < 4; bt++) {
                int vrow = bt*16 + lr;
                uint32_t voff = vrow * 256 + (((kt*2 + lk8) ^ (vrow & 15)) << 4);
                uint32_t vH[4], vL[4];
                ldsm_x4(vH[0], vH[1], vH[2], vH[3], st + 32768 + voff);
                ldsm_x4(vL[0], vL[1], vL[2], vL[3], st + 49152 + voff);
                #pragma unroll
                for (int hi = 0; hi < 2; hi++) {
                    mma_bf16(oacc[bt*2 + hi], pH, vH[hi], vH[hi + 2]);
                    mma_bf16(oacc[bt*2 + hi], pH, vL[hi], vL[hi + 2]);
                    mma_bf16(oacc[bt*2 + hi], pL, vH[hi], vH[hi + 2]);
                }
            }
        }
        __syncthreads();
    }

    float inv0 = 1.f / l0, inv1 = 1.f / l1;
    #pragma unroll
    for (int ot = 0; ot < 8; ot++) {
        int col = ot*8 + (lane & 3)*2;
        size_t p0 = (size_t)(b*LL + ig0) * HD + h*64 + col;
        size_t p1 = (size_t)(b*LL + ig1) * HD + h*64 + col;
        uint32_t h0, lo0, h1, lo1;
        split2(oacc[ot][0]*inv0, oacc[ot][1]*inv0, h0, lo0);
        split2(oacc[ot][2]*inv1, oacc[ot][3]*inv1, h1, lo1);
        *(uint32_t*)(g_aohi + p0) = h0;
        *(uint32_t*)(g_aolo + p0) = lo0;
        *(uint32_t*)(g_aohi + p1) = h1;
        *(uint32_t*)(g_aolo + p1) = lo1;
    }
}

// ---------------------------------------------------------------------------
extern "C" void kernel_launch(void* const* d_in, const int* in_sizes, int n_in,
                              void* d_out, int out_size) {
    const float* x  = (const float*)d_in[0];
    const float* Wq = (const float*)d_in[1];
    const float* Wk = (const float*)d_in[2];
    const float* Wv = (const float*)d_in[3];
    const float* Wo = (const float*)d_in[4];
    const float* bo = (const float*)d_in[5];
    const float* ub = (const float*)d_in[6];
    const float* vb = (const float*)d_in[7];
    const float* wp = (const float*)d_in[8];
    float* out = (float*)d_out;

    prep_kernel<<<1, 256>>>(vb, wp);
    wtrans_kernel<<<128, 256>>>(wp);
    conv_all_kernel<<<3072, 256>>>(x, Wq, Wk, Wv, Wo);

    cudaFuncSetAttribute(qkv_mma_kernel, cudaFuncAttributeMaxDynamicSharedMemorySize, GEMM_SMEM);
    cudaFuncSetAttribute(out_mma_kernel, cudaFuncAttributeMaxDynamicSharedMemorySize, GEMM_SMEM);

    qkv_mma_kernel<<<dim3(16, 24), 256, GEMM_SMEM>>>();

    vtrans_kernel<<<dim3(8, HH, BB), 256>>>();
    uk_kernel<<<64, 256>>>(ub);

    cudaFuncSetAttribute(qw_suffix_kernel, cudaFuncAttributeMaxDynamicSharedMemorySize, QW_SMEM);
    qw_suffix_kernel<<<dim3(8, HH, BB), 256, QW_SMEM>>>();

    cudaFuncSetAttribute(attn_kernel, cudaFuncAttributeMaxDynamicSharedMemorySize, ATTN_SMEM);
    attn_kernel<<<dim3(LL/128, HH, BB), 256, ATTN_SMEM>>>();

    out_mma_kernel<<<dim3(16, 12), 256, GEMM_SMEM>>>(bo, out);
}